// round 7
// baseline (speedup 1.0000x reference)
#include <cuda_runtime.h>
#include <math.h>
#include <stdint.h>

#define D_MODEL 1024
#define NHEAD   16
#define HDIM    64
#define DFF_    4096
#define NLAYER  6
#define BATCH   4
#define SEQ     2048
#define NTOK    (BATCH*SEQ)      /* 8192 */
#define KSEL    1024
#define NSEL    (BATCH*KSEL)     /* 4096 */

// ---------------- scratch (device globals; no allocations allowed) ----------
__device__ __align__(256) float g_x   [NTOK*D_MODEL];
__device__ __align__(256) float g_xsel[NSEL*D_MODEL];
__device__ __align__(256) float g_qkv [NTOK*3*D_MODEL];
__device__ __align__(256) float g_attn[NTOK*D_MODEL];
__device__ __align__(256) float g_t1  [NTOK*D_MODEL];
__device__ __align__(256) float g_t2  [NTOK*D_MODEL];
__device__ __align__(256) float g_ff  [NTOK*DFF_];
__device__ __align__(256) float g_rs  [BATCH*SEQ];
__device__ __align__(256) int   g_sel [BATCH*KSEL];
__device__ __align__(256) float g_w   [BATCH*KSEL];

// ---------------- packed fp32x2 helpers (sm_100+ PTX) ------------------------
__device__ __forceinline__ uint64_t pack2(float lo, float hi) {
    uint64_t r;
    asm("mov.b64 %0, {%1, %2};" : "=l"(r) : "f"(lo), "f"(hi));
    return r;
}
__device__ __forceinline__ uint64_t dup2(float a) {
    uint64_t r;
    asm("mov.b64 %0, {%1, %1};" : "=l"(r) : "f"(a));
    return r;
}
__device__ __forceinline__ void unpack2(uint64_t v, float& lo, float& hi) {
    asm("mov.b64 {%0, %1}, %2;" : "=f"(lo), "=f"(hi) : "l"(v));
}
__device__ __forceinline__ void fma2(uint64_t& d, uint64_t a, uint64_t b) {
    asm("fma.rn.f32x2 %0, %1, %2, %3;" : "=l"(d) : "l"(a), "l"(b), "l"(d));
}
__device__ __forceinline__ void mul2(uint64_t& d, uint64_t a, uint64_t b) {
    asm("mul.rn.f32x2 %0, %1, %2;" : "=l"(d) : "l"(a), "l"(b));
}

// ---------------- simple float4 copy ---------------------------------------
__global__ void copy_f4(const float4* __restrict__ src, float4* __restrict__ dst, int n4) {
    int i = blockIdx.x * blockDim.x + threadIdx.x;
    if (i < n4) dst[i] = src[i];
}

// ---------------- SGEMM: C[N,M] = A[N,K] @ W[M,K]^T + bias (opt relu) ------
// 128x128 tile, K-step 8, 256 threads, 8x8 micro-tile, packed f32x2 FMA.
// Per-lane arithmetic identical to scalar fp32 (fma.rn each lane, same k order).
template<int RELU>
__global__ __launch_bounds__(256, 2)
void sgemm128(const float* __restrict__ A, const float* __restrict__ W,
              const float* __restrict__ bias, float* __restrict__ C,
              int N, int M, int K) {
    __shared__ float As[8][128];
    __shared__ float Ws[8][128];
    const int t  = threadIdx.x;
    const int tx = t & 15;          // col group
    const int ty = t >> 4;          // row group
    const int cm = blockIdx.x * 128;
    const int rn = blockIdx.y * 128;
    const int lr = t >> 1;          // load row 0..127
    const int lk = (t & 1) * 4;     // load k offset 0 or 4

    const float* Aptr = A + (size_t)(rn + lr) * K + lk;
    const float* Wptr = W + (size_t)(cm + lr) * K + lk;

    // acc2[i][jp] = packed (C[i][2jp], C[i][2jp+1]); +0.0f bits are 0
    uint64_t acc2[8][4];
    #pragma unroll
    for (int i = 0; i < 8; i++)
        #pragma unroll
        for (int j = 0; j < 4; j++) acc2[i][j] = 0ull;

    for (int kt = 0; kt < K; kt += 8) {
        float4 av = *(const float4*)(Aptr + kt);
        float4 wv = *(const float4*)(Wptr + kt);
        As[lk+0][lr] = av.x; As[lk+1][lr] = av.y; As[lk+2][lr] = av.z; As[lk+3][lr] = av.w;
        Ws[lk+0][lr] = wv.x; Ws[lk+1][lr] = wv.y; Ws[lk+2][lr] = wv.z; Ws[lk+3][lr] = wv.w;
        __syncthreads();
        #pragma unroll
        for (int k = 0; k < 8; k++) {
            float a[8];
            *(float4*)&a[0] = *(const float4*)&As[k][ty*8];
            *(float4*)&a[4] = *(const float4*)&As[k][ty*8 + 4];
            float4 w0 = *(const float4*)&Ws[k][tx*8];
            float4 w1 = *(const float4*)&Ws[k][tx*8 + 4];
            uint64_t b2[4];
            b2[0] = pack2(w0.x, w0.y);
            b2[1] = pack2(w0.z, w0.w);
            b2[2] = pack2(w1.x, w1.y);
            b2[3] = pack2(w1.z, w1.w);
            #pragma unroll
            for (int i = 0; i < 8; i++) {
                uint64_t ad = dup2(a[i]);
                #pragma unroll
                for (int jp = 0; jp < 4; jp++)
                    fma2(acc2[i][jp], ad, b2[jp]);
            }
        }
        __syncthreads();
    }

    #pragma unroll
    for (int i = 0; i < 8; i++) {
        int row = rn + ty*8 + i;
        float* Crow = C + (size_t)row * M + cm + tx*8;
        float v[8];
        unpack2(acc2[i][0], v[0], v[1]);
        unpack2(acc2[i][1], v[2], v[3]);
        unpack2(acc2[i][2], v[4], v[5]);
        unpack2(acc2[i][3], v[6], v[7]);
        #pragma unroll
        for (int j = 0; j < 8; j++) {
            float o = v[j] + bias[cm + tx*8 + j];
            if (RELU) o = fmaxf(o, 0.f);
            v[j] = o;
        }
        *(float4*)(Crow)     = *(float4*)&v[0];
        *(float4*)(Crow + 4) = *(float4*)&v[4];
    }
}

// ---------------- flash attention (fp32 numerics, f32x2 FMA, HD=64) ---------
#define PS_STRIDE 65
#define ATTN_SMEM ((3*64*64 + 64*PS_STRIDE + 3*64) * 4)

__global__ __launch_bounds__(256)
void attn_kernel(const float* __restrict__ qkv, float* __restrict__ out,
                 int T) {
    extern __shared__ float sm[];
    float* Qs   = sm;                 // [d][q]  64x64
    float* Ks   = Qs + 64*64;         // [d][k]  64x64
    float* Vs   = Ks + 64*64;         // [k][d]  64x64
    float* Ps   = Vs + 64*64;         // [q][k]  64x65 (padded)
    float* mrow = Ps + 64*PS_STRIDE;
    float* lrow = mrow + 64;
    float* arow = lrow + 64;

    const int t  = threadIdx.x;
    const int tx = t & 15;
    const int ty = t >> 4;
    const int qt = blockIdx.x, h = blockIdx.y, b = blockIdx.z;
    const int stride = 3 * D_MODEL;

    const float* qbase = qkv + (size_t)(b*T + qt*64) * stride + h*HDIM;
    for (int it = t; it < 64*16; it += 256) {
        int q = it >> 4; int dg = (it & 15) * 4;
        float4 v = *(const float4*)(qbase + (size_t)q*stride + dg);
        Qs[(dg+0)*64 + q] = v.x; Qs[(dg+1)*64 + q] = v.y;
        Qs[(dg+2)*64 + q] = v.z; Qs[(dg+3)*64 + q] = v.w;
    }
    if (t < 64) { mrow[t] = -1e30f; lrow[t] = 0.f; }

    // oacc2[i][jp] = packed (O[i][2jp], O[i][2jp+1]) over d = tx*4..
    uint64_t oacc2[4][2];
    #pragma unroll
    for (int i = 0; i < 4; i++) { oacc2[i][0] = 0ull; oacc2[i][1] = 0ull; }

    const float* kbase0 = qkv + (size_t)(b*T) * stride +     D_MODEL + h*HDIM;
    const float* vbase0 = qkv + (size_t)(b*T) * stride + 2 * D_MODEL + h*HDIM;
    const int nkt = T / 64;

    for (int kt2 = 0; kt2 < nkt; kt2++) {
        __syncthreads();   // protect Ks/Vs/Ps reuse from previous iteration
        const float* kb = kbase0 + (size_t)kt2 * 64 * stride;
        const float* vb = vbase0 + (size_t)kt2 * 64 * stride;
        for (int it = t; it < 64*16; it += 256) {
            int kk = it >> 4; int dg = (it & 15) * 4;
            float4 kv = *(const float4*)(kb + (size_t)kk*stride + dg);
            Ks[(dg+0)*64 + kk] = kv.x; Ks[(dg+1)*64 + kk] = kv.y;
            Ks[(dg+2)*64 + kk] = kv.z; Ks[(dg+3)*64 + kk] = kv.w;
            float4 vv = *(const float4*)(vb + (size_t)kk*stride + dg);
            *(float4*)&Vs[kk*64 + dg] = vv;
        }
        __syncthreads();

        // S tile: s2[i][jp] packed pair over k-columns (tx*4+2jp, +1)
        uint64_t s2[4][2];
        #pragma unroll
        for (int i = 0; i < 4; i++) { s2[i][0] = 0ull; s2[i][1] = 0ull; }
        #pragma unroll 8
        for (int d = 0; d < 64; d++) {
            float4 a  = *(const float4*)&Qs[d*64 + ty*4];
            float4 bb = *(const float4*)&Ks[d*64 + tx*4];
            uint64_t b0 = pack2(bb.x, bb.y);
            uint64_t b1 = pack2(bb.z, bb.w);
            uint64_t a0 = dup2(a.x), a1 = dup2(a.y), a2 = dup2(a.z), a3 = dup2(a.w);
            fma2(s2[0][0], a0, b0); fma2(s2[0][1], a0, b1);
            fma2(s2[1][0], a1, b0); fma2(s2[1][1], a1, b1);
            fma2(s2[2][0], a2, b0); fma2(s2[2][1], a2, b1);
            fma2(s2[3][0], a3, b0); fma2(s2[3][1], a3, b1);
        }
        #pragma unroll
        for (int i = 0; i < 4; i++) {
            float s0, s1, s2v, s3;
            unpack2(s2[i][0], s0, s1);
            unpack2(s2[i][1], s2v, s3);
            float* pr = &Ps[(ty*4 + i)*PS_STRIDE + tx*4];
            pr[0] = s0 * 0.125f; pr[1] = s1 * 0.125f;
            pr[2] = s2v * 0.125f; pr[3] = s3 * 0.125f;
        }
        __syncthreads();

        // online softmax update, one thread per row
        if (t < 64) {
            float mo = mrow[t];
            float mt = -1e30f;
            #pragma unroll 8
            for (int k2 = 0; k2 < 64; k2++) mt = fmaxf(mt, Ps[t*PS_STRIDE + k2]);
            float mn = fmaxf(mo, mt);
            float al = __expf(mo - mn);
            float sum = 0.f;
            #pragma unroll 8
            for (int k2 = 0; k2 < 64; k2++) {
                float p = __expf(Ps[t*PS_STRIDE + k2] - mn);
                Ps[t*PS_STRIDE + k2] = p;
                sum += p;
            }
            mrow[t] = mn;
            lrow[t] = lrow[t]*al + sum;
            arow[t] = al;
        }
        __syncthreads();

        // O accumulation (packed over d pairs)
        {
            uint64_t al0 = dup2(arow[ty*4+0]);
            uint64_t al1 = dup2(arow[ty*4+1]);
            uint64_t al2 = dup2(arow[ty*4+2]);
            uint64_t al3 = dup2(arow[ty*4+3]);
            mul2(oacc2[0][0], oacc2[0][0], al0); mul2(oacc2[0][1], oacc2[0][1], al0);
            mul2(oacc2[1][0], oacc2[1][0], al1); mul2(oacc2[1][1], oacc2[1][1], al1);
            mul2(oacc2[2][0], oacc2[2][0], al2); mul2(oacc2[2][1], oacc2[2][1], al2);
            mul2(oacc2[3][0], oacc2[3][0], al3); mul2(oacc2[3][1], oacc2[3][1], al3);
        }
        #pragma unroll 8
        for (int k2 = 0; k2 < 64; k2++) {
            float4 v = *(const float4*)&Vs[k2*64 + tx*4];
            uint64_t v0 = pack2(v.x, v.y);
            uint64_t v1 = pack2(v.z, v.w);
            uint64_t p0 = dup2(Ps[(ty*4+0)*PS_STRIDE + k2]);
            uint64_t p1 = dup2(Ps[(ty*4+1)*PS_STRIDE + k2]);
            uint64_t p2 = dup2(Ps[(ty*4+2)*PS_STRIDE + k2]);
            uint64_t p3 = dup2(Ps[(ty*4+3)*PS_STRIDE + k2]);
            fma2(oacc2[0][0], p0, v0); fma2(oacc2[0][1], p0, v1);
            fma2(oacc2[1][0], p1, v0); fma2(oacc2[1][1], p1, v1);
            fma2(oacc2[2][0], p2, v0); fma2(oacc2[2][1], p2, v1);
            fma2(oacc2[3][0], p3, v0); fma2(oacc2[3][1], p3, v1);
        }
    }

    const int n0 = b*T + qt*64;
    #pragma unroll
    for (int i = 0; i < 4; i++) {
        int q = ty*4 + i;
        float inv = 1.f / lrow[q];
        float o0, o1, o2, o3;
        unpack2(oacc2[i][0], o0, o1);
        unpack2(oacc2[i][1], o2, o3);
        float4 o = make_float4(o0*inv, o1*inv, o2*inv, o3*inv);
        *(float4*)(out + (size_t)(n0 + q)*D_MODEL + h*HDIM + tx*4) = o;
    }
}

// ---------------- residual add + LayerNorm ----------------------------------
__global__ __launch_bounds__(256)
void addln_kernel(const float* __restrict__ a, const float* __restrict__ r,
                  const float* __restrict__ g, const float* __restrict__ be,
                  float* __restrict__ out) {
    __shared__ float rsum[256], rsq[256];
    const int n = blockIdx.x, t = threadIdx.x;
    float4 av = *(const float4*)(a + (size_t)n*D_MODEL + t*4);
    float4 rv = *(const float4*)(r + (size_t)n*D_MODEL + t*4);
    float x0 = av.x + rv.x, x1 = av.y + rv.y, x2 = av.z + rv.z, x3 = av.w + rv.w;
    rsum[t] = x0 + x1 + x2 + x3;
    rsq [t] = x0*x0 + x1*x1 + x2*x2 + x3*x3;
    __syncthreads();
    for (int off = 128; off > 0; off >>= 1) {
        if (t < off) { rsum[t] += rsum[t+off]; rsq[t] += rsq[t+off]; }
        __syncthreads();
    }
    float mu  = rsum[0] * (1.f/1024.f);
    float var = rsq[0]  * (1.f/1024.f) - mu*mu;
    float rstd = rsqrtf(var + 1e-5f);
    float4 gv = *(const float4*)(g  + t*4);
    float4 bv = *(const float4*)(be + t*4);
    float4 o;
    o.x = (x0 - mu)*rstd*gv.x + bv.x;
    o.y = (x1 - mu)*rstd*gv.y + bv.y;
    o.z = (x2 - mu)*rstd*gv.z + bv.z;
    o.w = (x3 - mu)*rstd*gv.w + bv.w;
    *(float4*)(out + (size_t)n*D_MODEL + t*4) = o;
}

// ---------------- router score ----------------------------------------------
__global__ __launch_bounds__(256)
void router_kernel(const float* __restrict__ x, const float* __restrict__ rw,
                   float* __restrict__ out) {
    __shared__ float red[256];
    const int n = blockIdx.x, t = threadIdx.x;
    float4 xv = *(const float4*)(x + (size_t)n*D_MODEL + t*4);
    float4 wv = *(const float4*)(rw + t*4);
    red[t] = xv.x*wv.x + xv.y*wv.y + xv.z*wv.z + xv.w*wv.w;
    __syncthreads();
    for (int off = 128; off > 0; off >>= 1) {
        if (t < off) red[t] += red[t+off];
        __syncthreads();
    }
    if (t == 0) out[n] = red[0];
}

// ---------------- top-k via bitonic sort (desc value, asc index) ------------
__global__ __launch_bounds__(1024)
void topk_kernel(const float* __restrict__ scores, int* __restrict__ sel,
                 float* __restrict__ wout) {
    __shared__ float v[2048];
    __shared__ int  id[2048];
    const int b = blockIdx.x, t = threadIdx.x;
    v[t]        = scores[b*SEQ + t];        id[t]        = t;
    v[t + 1024] = scores[b*SEQ + t + 1024]; id[t + 1024] = t + 1024;
    __syncthreads();
    for (int k = 2; k <= 2048; k <<= 1) {
        for (int j = k >> 1; j > 0; j >>= 1) {
            #pragma unroll
            for (int s = 0; s < 2; s++) {
                int i = t + s*1024;
                int ixj = i ^ j;
                if (ixj > i) {
                    float vi = v[i], vj = v[ixj];
                    int   ii = id[i], ij = id[ixj];
                    bool before = (vi > vj) || (vi == vj && ii < ij);
                    bool up = ((i & k) == 0);
                    bool dosw = up ? (!before) : before;
                    if (dosw) { v[i] = vj; v[ixj] = vi; id[i] = ij; id[ixj] = ii; }
                }
            }
            __syncthreads();
        }
    }
    // first KSEL entries are the top-k
    sel [b*KSEL + t] = id[t];
    wout[b*KSEL + t] = 1.f / (1.f + expf(-v[t]));
}

// ---------------- gather / scatter ------------------------------------------
__global__ __launch_bounds__(256)
void gather_kernel(const float* __restrict__ x, const int* __restrict__ sel,
                   float* __restrict__ xs) {
    const int row = blockIdx.x;
    const int b = row >> 10;
    const int src = b*SEQ + sel[row];
    const int t = threadIdx.x;
    float4 v = *(const float4*)(x + (size_t)src*D_MODEL + t*4);
    *(float4*)(xs + (size_t)row*D_MODEL + t*4) = v;
}

__global__ __launch_bounds__(256)
void scatter_kernel(float* __restrict__ x, const int* __restrict__ sel,
                    const float* __restrict__ w, const float* __restrict__ xs,
                    const float* __restrict__ proc) {
    const int row = blockIdx.x;
    const int b = row >> 10;
    const int dst = b*SEQ + sel[row];
    const float wv = w[row];
    const int t = threadIdx.x;
    float4 p  = *(const float4*)(proc + (size_t)row*D_MODEL + t*4);
    float4 s  = *(const float4*)(xs   + (size_t)row*D_MODEL + t*4);
    float4 xv = *(float4*)(x + (size_t)dst*D_MODEL + t*4);
    xv.x += (p.x - s.x)*wv;
    xv.y += (p.y - s.y)*wv;
    xv.z += (p.z - s.z)*wv;
    xv.w += (p.w - s.w)*wv;
    *(float4*)(x + (size_t)dst*D_MODEL + t*4) = xv;
}

// ---------------- host-side encoder layer ------------------------------------
static void run_encoder(const float* Xin, float* Xout, int Ncur, int Tcur, int Bcur,
                        const float* Wq, const float* bq, const float* Wo, const float* bo,
                        const float* W1, const float* b1, const float* W2, const float* b2,
                        const float* g1, const float* be1, const float* g2, const float* be2,
                        float* qkv, float* attnb, float* t1, float* t2, float* ff) {
    sgemm128<0><<<dim3(3*D_MODEL/128, Ncur/128), 256>>>(Xin, Wq, bq, qkv, Ncur, 3*D_MODEL, D_MODEL);
    attn_kernel<<<dim3(Tcur/64, NHEAD, Bcur), 256, ATTN_SMEM>>>(qkv, attnb, Tcur);
    sgemm128<0><<<dim3(D_MODEL/128, Ncur/128), 256>>>(attnb, Wo, bo, t2, Ncur, D_MODEL, D_MODEL);
    addln_kernel<<<Ncur, 256>>>(Xin, t2, g1, be1, t1);
    sgemm128<1><<<dim3(DFF_/128, Ncur/128), 256>>>(t1, W1, b1, ff, Ncur, DFF_, D_MODEL);
    sgemm128<0><<<dim3(D_MODEL/128, Ncur/128), 256>>>(ff, W2, b2, t2, Ncur, D_MODEL, DFF_);
    addln_kernel<<<Ncur, 256>>>(t1, t2, g2, be2, Xout);
}

extern "C" void kernel_launch(void* const* d_in, const int* in_sizes, int n_in,
                              void* d_out, int out_size) {
    (void)in_sizes; (void)n_in; (void)out_size;
    const float* x    = (const float*)d_in[0];
    const float* Wqkv = (const float*)d_in[1];
    const float* bqkv = (const float*)d_in[2];
    const float* Wo   = (const float*)d_in[3];
    const float* bo   = (const float*)d_in[4];
    const float* W1   = (const float*)d_in[5];
    const float* b1   = (const float*)d_in[6];
    const float* W2   = (const float*)d_in[7];
    const float* b2   = (const float*)d_in[8];
    const float* g1   = (const float*)d_in[9];
    const float* be1  = (const float*)d_in[10];
    const float* g2   = (const float*)d_in[11];
    const float* be2  = (const float*)d_in[12];
    const float* rw   = (const float*)d_in[13];

    float *gx, *gxsel, *gqkv, *gattn, *gt1, *gt2, *gff, *grs, *gw; int* gsel;
    cudaGetSymbolAddress((void**)&gx,    g_x);
    cudaGetSymbolAddress((void**)&gxsel, g_xsel);
    cudaGetSymbolAddress((void**)&gqkv,  g_qkv);
    cudaGetSymbolAddress((void**)&gattn, g_attn);
    cudaGetSymbolAddress((void**)&gt1,   g_t1);
    cudaGetSymbolAddress((void**)&gt2,   g_t2);
    cudaGetSymbolAddress((void**)&gff,   g_ff);
    cudaGetSymbolAddress((void**)&grs,   g_rs);
    cudaGetSymbolAddress((void**)&gsel,  g_sel);
    cudaGetSymbolAddress((void**)&gw,    g_w);

    cudaFuncSetAttribute(attn_kernel, cudaFuncAttributeMaxDynamicSharedMemorySize, ATTN_SMEM);

    const int n4 = NTOK*D_MODEL/4;
    copy_f4<<<(n4 + 255)/256, 256>>>((const float4*)x, (float4*)gx, n4);

    for (int L = 0; L < NLAYER; L++) {
        const float* Wq_l  = Wqkv + (size_t)L*3*D_MODEL*D_MODEL;
        const float* bq_l  = bqkv + (size_t)L*3*D_MODEL;
        const float* Wo_l  = Wo   + (size_t)L*D_MODEL*D_MODEL;
        const float* bo_l  = bo   + (size_t)L*D_MODEL;
        const float* W1_l  = W1   + (size_t)L*DFF_*D_MODEL;
        const float* b1_l  = b1   + (size_t)L*DFF_;
        const float* W2_l  = W2   + (size_t)L*D_MODEL*DFF_;
        const float* b2_l  = b2   + (size_t)L*D_MODEL;
        const float* g1_l  = g1   + (size_t)L*D_MODEL;
        const float* be1_l = be1  + (size_t)L*D_MODEL;
        const float* g2_l  = g2   + (size_t)L*D_MODEL;
        const float* be2_l = be2  + (size_t)L*D_MODEL;

        if (L & 1) {
            router_kernel<<<NTOK, 256>>>(gx, rw + (size_t)L*D_MODEL, grs);
            topk_kernel<<<BATCH, 1024>>>(grs, gsel, gw);
            gather_kernel<<<NSEL, 256>>>(gx, gsel, gxsel);
            run_encoder(gxsel, gattn, NSEL, KSEL, BATCH,
                        Wq_l, bq_l, Wo_l, bo_l, W1_l, b1_l, W2_l, b2_l,
                        g1_l, be1_l, g2_l, be2_l,
                        gqkv, gattn, gt1, gt2, gff);
            scatter_kernel<<<NSEL, 256>>>(gx, gsel, gw, gxsel, gattn);
        } else {
            run_encoder(gx, gx, NTOK, SEQ, BATCH,
                        Wq_l, bq_l, Wo_l, bo_l, W1_l, b1_l, W2_l, b2_l,
                        g1_l, be1_l, g2_l, be2_l,
                        gqkv, gattn, gt1, gt2, gff);
        }
    }

    copy_f4<<<(n4 + 255)/256, 256>>>((const float4*)gx, (float4*)d_out, n4);
}

// round 9
// speedup vs baseline: 1.3448x; 1.3448x over previous
#include <cuda_runtime.h>
#include <cuda_fp16.h>
#include <math.h>
#include <stdint.h>

#define D_MODEL 1024
#define NHEAD   16
#define HDIM    64
#define DFF_    4096
#define NLAYER  6
#define BATCH   4
#define SEQ     2048
#define NTOK    (BATCH*SEQ)      /* 8192 */
#define KSEL    1024
#define NSEL    (BATCH*KSEL)     /* 4096 */

#define WQKV_SZ (NLAYER*3*D_MODEL*D_MODEL)
#define WO_SZ   (NLAYER*D_MODEL*D_MODEL)
#define W1_SZ   (NLAYER*DFF_*D_MODEL)
#define W2_SZ   (NLAYER*D_MODEL*DFF_)
#define ACT_SZ  (NTOK*DFF_)

#define LOW_SCALE   2048.0f
#define LOW_UNSCALE (1.0f/2048.0f)

// ---------------- scratch (device globals; no allocations allowed) ----------
__device__ __align__(256) float g_x   [NTOK*D_MODEL];
__device__ __align__(256) float g_xsel[NSEL*D_MODEL];
__device__ __align__(256) float g_qkv [NTOK*3*D_MODEL];
__device__ __align__(256) float g_attn[NTOK*D_MODEL];
__device__ __align__(256) float g_t1  [NTOK*D_MODEL];
__device__ __align__(256) float g_t2  [NTOK*D_MODEL];
__device__ __align__(256) float g_ff  [NTOK*DFF_];
__device__ __align__(256) float g_rs  [BATCH*SEQ];
__device__ __align__(256) int   g_sel [BATCH*KSEL];
__device__ __align__(256) float g_w   [BATCH*KSEL];

// fp16 split-plane buffers (h, l*2048)
__device__ __align__(256) __half g_wqkv2[2][WQKV_SZ];
__device__ __align__(256) __half g_wo2  [2][WO_SZ];
__device__ __align__(256) __half g_w12  [2][W1_SZ];
__device__ __align__(256) __half g_w22  [2][W2_SZ];
__device__ __align__(256) __half g_act2 [2][ACT_SZ];

// ---------------- simple float4 copy ---------------------------------------
__global__ void copy_f4(const float4* __restrict__ src, float4* __restrict__ dst, int n4) {
    int i = blockIdx.x * blockDim.x + threadIdx.x;
    if (i < n4) dst[i] = src[i];
}

// ---------------- 2-way fp16 split (low plane scaled by 2048) ----------------
__global__ __launch_bounds__(256)
void split2_kernel(const float* __restrict__ in,
                   __half* __restrict__ ph, __half* __restrict__ pl, int n8) {
    int i = blockIdx.x * blockDim.x + threadIdx.x;
    if (i >= n8) return;
    const float4* p = (const float4*)in + (size_t)i * 2;
    float4 x0 = p[0], x1 = p[1];
    float v[8] = {x0.x, x0.y, x0.z, x0.w, x1.x, x1.y, x1.z, x1.w};
    __align__(16) __half hh[8], ll[8];
    #pragma unroll
    for (int k = 0; k < 8; k++) {
        __half h = __float2half_rn(v[k]);
        hh[k] = h;
        float r = (v[k] - __half2float(h)) * LOW_SCALE;   // exact power-of-2 scale
        ll[k] = __float2half_rn(r);
    }
    *(uint4*)(ph + (size_t)i * 8) = *(uint4*)hh;
    *(uint4*)(pl + (size_t)i * 8) = *(uint4*)ll;
}

static inline void split2(const float* in, __half* h, __half* l, size_t n) {
    int n8 = (int)(n / 8);
    split2_kernel<<<(n8 + 255) / 256, 256>>>(in, h, l, n8);
}

#define MMA_F16(d, a, b) \
    asm volatile("mma.sync.aligned.m16n8k16.row.col.f32.f16.f16.f32 " \
        "{%0,%1,%2,%3}, {%4,%5,%6,%7}, {%8,%9}, {%0,%1,%2,%3};" \
        : "+f"((d)[0]), "+f"((d)[1]), "+f"((d)[2]), "+f"((d)[3]) \
        : "r"((a)[0]), "r"((a)[1]), "r"((a)[2]), "r"((a)[3]), "r"((b)[0]), "r"((b)[1]))

// ---------------- fp16 2-plane split GEMM, separate accumulators -------------
// C[N,M] = A[N,K] @ W[M,K]^T + bias, optional relu.
// A = ah + al/2048, W = wh + wl/2048  (al, wl stored pre-scaled by 2048)
// acc1 = sum ah*wh ;  acc2 = sum (ah*wl + al*wh)   [same-magnitude terms only]
// C = acc1 + acc2/2048        (dropped al*wl/2048^2 ~ 2^-22 relative)
// Block 128x128, BK=16, 256 threads (8 warps: 2m x 4n), warp tile 64x32.
// Fragments via direct LDS, documented PTX lane mapping (hi-plane verified R6).
#define SROW 24

template<int RELU>
__global__ __launch_bounds__(256)
void gemm_fp16x2(const __half* __restrict__ Ah, const __half* __restrict__ Al,
                 const __half* __restrict__ Wh, const __half* __restrict__ Wl,
                 const float* __restrict__ bias, float* __restrict__ C,
                 int N, int M, int K) {
    __shared__ __align__(16) __half sA[2][128][SROW];
    __shared__ __align__(16) __half sW[2][128][SROW];

    const int t    = threadIdx.x;
    const int lane = t & 31;
    const int warp = t >> 5;
    const int wm   = warp >> 2;      // 0..1
    const int wn   = warp & 3;       // 0..3
    const int rn   = blockIdx.y * 128;
    const int cm   = blockIdx.x * 128;
    const int g    = lane >> 2;      // 0..7
    const int tg   = lane & 3;       // 0..3

    const int lrow = t >> 1;
    const int lk   = (t & 1) * 8;

    const __half* Ap[2] = { Ah + (size_t)(rn + lrow) * K + lk,
                            Al + (size_t)(rn + lrow) * K + lk };
    const __half* Wp[2] = { Wh + (size_t)(cm + lrow) * K + lk,
                            Wl + (size_t)(cm + lrow) * K + lk };

    float acc1[4][4][4], acc2[4][4][4];
    #pragma unroll
    for (int i = 0; i < 4; i++)
        #pragma unroll
        for (int j = 0; j < 4; j++)
            #pragma unroll
            for (int r = 0; r < 4; r++) { acc1[i][j][r] = 0.f; acc2[i][j][r] = 0.f; }

    const int KT = K >> 4;
    for (int kt = 0; kt < KT; kt++) {
        #pragma unroll
        for (int p = 0; p < 2; p++) {
            *(uint4*)&sA[p][lrow][lk] = *(const uint4*)(Ap[p] + (size_t)kt * 16);
            *(uint4*)&sW[p][lrow][lk] = *(const uint4*)(Wp[p] + (size_t)kt * 16);
        }
        __syncthreads();

        uint32_t fb[2][4][2];
        #pragma unroll
        for (int jn = 0; jn < 4; jn++) {
            const int c0 = wn * 32 + jn * 8 + g;
            #pragma unroll
            for (int p = 0; p < 2; p++) {
                fb[p][jn][0] = *(const uint32_t*)&sW[p][c0][tg * 2];
                fb[p][jn][1] = *(const uint32_t*)&sW[p][c0][tg * 2 + 8];
            }
        }

        #pragma unroll
        for (int im = 0; im < 4; im++) {
            const int r0 = wm * 64 + im * 16;
            uint32_t fa[2][4];
            #pragma unroll
            for (int p = 0; p < 2; p++) {
                fa[p][0] = *(const uint32_t*)&sA[p][r0 + g][tg * 2];
                fa[p][1] = *(const uint32_t*)&sA[p][r0 + g + 8][tg * 2];
                fa[p][2] = *(const uint32_t*)&sA[p][r0 + g][tg * 2 + 8];
                fa[p][3] = *(const uint32_t*)&sA[p][r0 + g + 8][tg * 2 + 8];
            }
            #pragma unroll
            for (int jn = 0; jn < 4; jn++) {
                MMA_F16(acc1[im][jn], fa[0], fb[0][jn]);  // hh -> acc1
                MMA_F16(acc2[im][jn], fa[0], fb[1][jn]);  // h*l -> acc2
                MMA_F16(acc2[im][jn], fa[1], fb[0][jn]);  // l*h -> acc2
            }
        }
        __syncthreads();
    }

    // epilogue: combine planes in fp32, bias (+relu), direct stores
    #pragma unroll
    for (int im = 0; im < 4; im++) {
        #pragma unroll
        for (int jn = 0; jn < 4; jn++) {
            const int row = rn + wm * 64 + im * 16 + g;
            const int col = cm + wn * 32 + jn * 8 + tg * 2;
            float b0 = bias[col], b1 = bias[col + 1];
            float v0 = acc1[im][jn][0] + acc2[im][jn][0] * LOW_UNSCALE + b0;
            float v1 = acc1[im][jn][1] + acc2[im][jn][1] * LOW_UNSCALE + b1;
            float v2 = acc1[im][jn][2] + acc2[im][jn][2] * LOW_UNSCALE + b0;
            float v3 = acc1[im][jn][3] + acc2[im][jn][3] * LOW_UNSCALE + b1;
            if (RELU) {
                v0 = fmaxf(v0, 0.f); v1 = fmaxf(v1, 0.f);
                v2 = fmaxf(v2, 0.f); v3 = fmaxf(v3, 0.f);
            }
            *(float2*)&C[(size_t)row * M + col]       = make_float2(v0, v1);
            *(float2*)&C[(size_t)(row + 8) * M + col] = make_float2(v2, v3);
        }
    }
}

// ---------------- flash attention (fp32, HD=64) -----------------------------
#define PS_STRIDE 65
#define ATTN_SMEM ((3*64*64 + 64*PS_STRIDE + 3*64) * 4)

__global__ __launch_bounds__(256)
void attn_kernel(const float* __restrict__ qkv, float* __restrict__ out,
                 int T) {
    extern __shared__ float sm[];
    float* Qs   = sm;
    float* Ks   = Qs + 64*64;
    float* Vs   = Ks + 64*64;
    float* Ps   = Vs + 64*64;
    float* mrow = Ps + 64*PS_STRIDE;
    float* lrow = mrow + 64;
    float* arow = lrow + 64;

    const int t  = threadIdx.x;
    const int tx = t & 15;
    const int ty = t >> 4;
    const int qt = blockIdx.x, h = blockIdx.y, b = blockIdx.z;
    const int stride = 3 * D_MODEL;

    const float* qbase = qkv + (size_t)(b*T + qt*64) * stride + h*HDIM;
    for (int it = t; it < 64*16; it += 256) {
        int q = it >> 4; int dg = (it & 15) * 4;
        float4 v = *(const float4*)(qbase + (size_t)q*stride + dg);
        Qs[(dg+0)*64 + q] = v.x; Qs[(dg+1)*64 + q] = v.y;
        Qs[(dg+2)*64 + q] = v.z; Qs[(dg+3)*64 + q] = v.w;
    }
    if (t < 64) { mrow[t] = -1e30f; lrow[t] = 0.f; }

    float oacc[4][4];
    #pragma unroll
    for (int i = 0; i < 4; i++)
        #pragma unroll
        for (int j = 0; j < 4; j++) oacc[i][j] = 0.f;

    const float* kbase0 = qkv + (size_t)(b*T) * stride +     D_MODEL + h*HDIM;
    const float* vbase0 = qkv + (size_t)(b*T) * stride + 2 * D_MODEL + h*HDIM;
    const int nkt = T / 64;

    for (int kt2 = 0; kt2 < nkt; kt2++) {
        __syncthreads();
        const float* kb = kbase0 + (size_t)kt2 * 64 * stride;
        const float* vb = vbase0 + (size_t)kt2 * 64 * stride;
        for (int it = t; it < 64*16; it += 256) {
            int kk = it >> 4; int dg = (it & 15) * 4;
            float4 kv = *(const float4*)(kb + (size_t)kk*stride + dg);
            Ks[(dg+0)*64 + kk] = kv.x; Ks[(dg+1)*64 + kk] = kv.y;
            Ks[(dg+2)*64 + kk] = kv.z; Ks[(dg+3)*64 + kk] = kv.w;
            float4 vv = *(const float4*)(vb + (size_t)kk*stride + dg);
            *(float4*)&Vs[kk*64 + dg] = vv;
        }
        __syncthreads();

        float s[4][4];
        #pragma unroll
        for (int i = 0; i < 4; i++)
            #pragma unroll
            for (int j = 0; j < 4; j++) s[i][j] = 0.f;
        #pragma unroll 16
        for (int d = 0; d < 64; d++) {
            float4 a  = *(const float4*)&Qs[d*64 + ty*4];
            float4 bb = *(const float4*)&Ks[d*64 + tx*4];
            s[0][0] += a.x*bb.x; s[0][1] += a.x*bb.y; s[0][2] += a.x*bb.z; s[0][3] += a.x*bb.w;
            s[1][0] += a.y*bb.x; s[1][1] += a.y*bb.y; s[1][2] += a.y*bb.z; s[1][3] += a.y*bb.w;
            s[2][0] += a.z*bb.x; s[2][1] += a.z*bb.y; s[2][2] += a.z*bb.z; s[2][3] += a.z*bb.w;
            s[3][0] += a.w*bb.x; s[3][1] += a.w*bb.y; s[3][2] += a.w*bb.z; s[3][3] += a.w*bb.w;
        }
        #pragma unroll
        for (int i = 0; i < 4; i++)
            #pragma unroll
            for (int j = 0; j < 4; j++)
                Ps[(ty*4 + i)*PS_STRIDE + tx*4 + j] = s[i][j] * 0.125f;
        __syncthreads();

        if (t < 64) {
            float mo = mrow[t];
            float mt = -1e30f;
            #pragma unroll 8
            for (int k2 = 0; k2 < 64; k2++) mt = fmaxf(mt, Ps[t*PS_STRIDE + k2]);
            float mn = fmaxf(mo, mt);
            float al = __expf(mo - mn);
            float sum = 0.f;
            #pragma unroll 8
            for (int k2 = 0; k2 < 64; k2++) {
                float p = __expf(Ps[t*PS_STRIDE + k2] - mn);
                Ps[t*PS_STRIDE + k2] = p;
                sum += p;
            }
            mrow[t] = mn;
            lrow[t] = lrow[t]*al + sum;
            arow[t] = al;
        }
        __syncthreads();

        float al0 = arow[ty*4+0], al1 = arow[ty*4+1], al2 = arow[ty*4+2], al3 = arow[ty*4+3];
        #pragma unroll
        for (int j = 0; j < 4; j++) {
            oacc[0][j] *= al0; oacc[1][j] *= al1; oacc[2][j] *= al2; oacc[3][j] *= al3;
        }
        #pragma unroll 8
        for (int k2 = 0; k2 < 64; k2++) {
            float4 v = *(const float4*)&Vs[k2*64 + tx*4];
            float p0 = Ps[(ty*4+0)*PS_STRIDE + k2];
            float p1 = Ps[(ty*4+1)*PS_STRIDE + k2];
            float p2 = Ps[(ty*4+2)*PS_STRIDE + k2];
            float p3 = Ps[(ty*4+3)*PS_STRIDE + k2];
            oacc[0][0] += p0*v.x; oacc[0][1] += p0*v.y; oacc[0][2] += p0*v.z; oacc[0][3] += p0*v.w;
            oacc[1][0] += p1*v.x; oacc[1][1] += p1*v.y; oacc[1][2] += p1*v.z; oacc[1][3] += p1*v.w;
            oacc[2][0] += p2*v.x; oacc[2][1] += p2*v.y; oacc[2][2] += p2*v.z; oacc[2][3] += p2*v.w;
            oacc[3][0] += p3*v.x; oacc[3][1] += p3*v.y; oacc[3][2] += p3*v.z; oacc[3][3] += p3*v.w;
        }
    }

    const int n0 = b*T + qt*64;
    #pragma unroll
    for (int i = 0; i < 4; i++) {
        int q = ty*4 + i;
        float inv = 1.f / lrow[q];
        float4 o = make_float4(oacc[i][0]*inv, oacc[i][1]*inv, oacc[i][2]*inv, oacc[i][3]*inv);
        *(float4*)(out + (size_t)(n0 + q)*D_MODEL + h*HDIM + tx*4) = o;
    }
}

// ---------------- residual add + LayerNorm ----------------------------------
__global__ __launch_bounds__(256)
void addln_kernel(const float* __restrict__ a, const float* __restrict__ r,
                  const float* __restrict__ g, const float* __restrict__ be,
                  float* __restrict__ out) {
    __shared__ float rsum[256], rsq[256];
    const int n = blockIdx.x, t = threadIdx.x;
    float4 av = *(const float4*)(a + (size_t)n*D_MODEL + t*4);
    float4 rv = *(const float4*)(r + (size_t)n*D_MODEL + t*4);
    float x0 = av.x + rv.x, x1 = av.y + rv.y, x2 = av.z + rv.z, x3 = av.w + rv.w;
    rsum[t] = x0 + x1 + x2 + x3;
    rsq [t] = x0*x0 + x1*x1 + x2*x2 + x3*x3;
    __syncthreads();
    for (int off = 128; off > 0; off >>= 1) {
        if (t < off) { rsum[t] += rsum[t+off]; rsq[t] += rsq[t+off]; }
        __syncthreads();
    }
    float mu  = rsum[0] * (1.f/1024.f);
    float var = rsq[0]  * (1.f/1024.f) - mu*mu;
    float rstd = rsqrtf(var + 1e-5f);
    float4 gv = *(const float4*)(g  + t*4);
    float4 bv = *(const float4*)(be + t*4);
    float4 o;
    o.x = (x0 - mu)*rstd*gv.x + bv.x;
    o.y = (x1 - mu)*rstd*gv.y + bv.y;
    o.z = (x2 - mu)*rstd*gv.z + bv.z;
    o.w = (x3 - mu)*rstd*gv.w + bv.w;
    *(float4*)(out + (size_t)n*D_MODEL + t*4) = o;
}

// ---------------- router score ----------------------------------------------
__global__ __launch_bounds__(256)
void router_kernel(const float* __restrict__ x, const float* __restrict__ rw,
                   float* __restrict__ out) {
    __shared__ float red[256];
    const int n = blockIdx.x, t = threadIdx.x;
    float4 xv = *(const float4*)(x + (size_t)n*D_MODEL + t*4);
    float4 wv = *(const float4*)(rw + t*4);
    red[t] = xv.x*wv.x + xv.y*wv.y + xv.z*wv.z + xv.w*wv.w;
    __syncthreads();
    for (int off = 128; off > 0; off >>= 1) {
        if (t < off) red[t] += red[t+off];
        __syncthreads();
    }
    if (t == 0) out[n] = red[0];
}

// ---------------- top-k via bitonic sort (desc value, asc index) ------------
__global__ __launch_bounds__(1024)
void topk_kernel(const float* __restrict__ scores, int* __restrict__ sel,
                 float* __restrict__ wout) {
    __shared__ float v[2048];
    __shared__ int  id[2048];
    const int b = blockIdx.x, t = threadIdx.x;
    v[t]        = scores[b*SEQ + t];        id[t]        = t;
    v[t + 1024] = scores[b*SEQ + t + 1024]; id[t + 1024] = t + 1024;
    __syncthreads();
    for (int k = 2; k <= 2048; k <<= 1) {
        for (int j = k >> 1; j > 0; j >>= 1) {
            #pragma unroll
            for (int s = 0; s < 2; s++) {
                int i = t + s*1024;
                int ixj = i ^ j;
                if (ixj > i) {
                    float vi = v[i], vj = v[ixj];
                    int   ii = id[i], ij = id[ixj];
                    bool before = (vi > vj) || (vi == vj && ii < ij);
                    bool up = ((i & k) == 0);
                    bool dosw = up ? (!before) : before;
                    if (dosw) { v[i] = vj; v[ixj] = vi; id[i] = ij; id[ixj] = ii; }
                }
            }
            __syncthreads();
        }
    }
    sel [b*KSEL + t] = id[t];
    wout[b*KSEL + t] = 1.f / (1.f + expf(-v[t]));
}

// ---------------- gather / scatter ------------------------------------------
__global__ __launch_bounds__(256)
void gather_kernel(const float* __restrict__ x, const int* __restrict__ sel,
                   float* __restrict__ xs) {
    const int row = blockIdx.x;
    const int b = row >> 10;
    const int src = b*SEQ + sel[row];
    const int t = threadIdx.x;
    float4 v = *(const float4*)(x + (size_t)src*D_MODEL + t*4);
    *(float4*)(xs + (size_t)row*D_MODEL + t*4) = v;
}

__global__ __launch_bounds__(256)
void scatter_kernel(float* __restrict__ x, const int* __restrict__ sel,
                    const float* __restrict__ w, const float* __restrict__ xs,
                    const float* __restrict__ proc) {
    const int row = blockIdx.x;
    const int b = row >> 10;
    const int dst = b*SEQ + sel[row];
    const float wv = w[row];
    const int t = threadIdx.x;
    float4 p  = *(const float4*)(proc + (size_t)row*D_MODEL + t*4);
    float4 s  = *(const float4*)(xs   + (size_t)row*D_MODEL + t*4);
    float4 xv = *(float4*)(x + (size_t)dst*D_MODEL + t*4);
    xv.x += (p.x - s.x)*wv;
    xv.y += (p.y - s.y)*wv;
    xv.z += (p.z - s.z)*wv;
    xv.w += (p.w - s.w)*wv;
    *(float4*)(x + (size_t)dst*D_MODEL + t*4) = xv;
}

// ---------------- host-side helpers ------------------------------------------
struct WP2 { __half *h, *l; };

static void run_encoder(const float* Xin, float* Xout, int Ncur, int Tcur, int Bcur,
                        WP2 wq, const float* bq, WP2 wo, const float* bo,
                        WP2 w1, const float* b1, WP2 w2, const float* b2,
                        const float* g1, const float* be1, const float* g2, const float* be2,
                        float* qkv, float* attnb, float* t1, float* t2, float* ff,
                        __half* ah, __half* al) {
    split2(Xin, ah, al, (size_t)Ncur * D_MODEL);
    gemm_fp16x2<0><<<dim3(3*D_MODEL/128, Ncur/128), 256>>>(ah, al, wq.h, wq.l,
                                                           bq, qkv, Ncur, 3*D_MODEL, D_MODEL);
    attn_kernel<<<dim3(Tcur/64, NHEAD, Bcur), 256, ATTN_SMEM>>>(qkv, attnb, Tcur);
    split2(attnb, ah, al, (size_t)Ncur * D_MODEL);
    gemm_fp16x2<0><<<dim3(D_MODEL/128, Ncur/128), 256>>>(ah, al, wo.h, wo.l,
                                                         bo, t2, Ncur, D_MODEL, D_MODEL);
    addln_kernel<<<Ncur, 256>>>(Xin, t2, g1, be1, t1);
    split2(t1, ah, al, (size_t)Ncur * D_MODEL);
    gemm_fp16x2<1><<<dim3(DFF_/128, Ncur/128), 256>>>(ah, al, w1.h, w1.l,
                                                      b1, ff, Ncur, DFF_, D_MODEL);
    split2(ff, ah, al, (size_t)Ncur * DFF_);
    gemm_fp16x2<0><<<dim3(D_MODEL/128, Ncur/128), 256>>>(ah, al, w2.h, w2.l,
                                                         b2, t2, Ncur, D_MODEL, DFF_);
    addln_kernel<<<Ncur, 256>>>(t1, t2, g2, be2, Xout);
}

extern "C" void kernel_launch(void* const* d_in, const int* in_sizes, int n_in,
                              void* d_out, int out_size) {
    (void)in_sizes; (void)n_in; (void)out_size;
    const float* x    = (const float*)d_in[0];
    const float* Wqkv = (const float*)d_in[1];
    const float* bqkv = (const float*)d_in[2];
    const float* Wo   = (const float*)d_in[3];
    const float* bo   = (const float*)d_in[4];
    const float* W1   = (const float*)d_in[5];
    const float* b1   = (const float*)d_in[6];
    const float* W2   = (const float*)d_in[7];
    const float* b2   = (const float*)d_in[8];
    const float* g1   = (const float*)d_in[9];
    const float* be1  = (const float*)d_in[10];
    const float* g2   = (const float*)d_in[11];
    const float* be2  = (const float*)d_in[12];
    const float* rw   = (const float*)d_in[13];

    float *gx, *gxsel, *gqkv, *gattn, *gt1, *gt2, *gff, *grs, *gw; int* gsel;
    cudaGetSymbolAddress((void**)&gx,    g_x);
    cudaGetSymbolAddress((void**)&gxsel, g_xsel);
    cudaGetSymbolAddress((void**)&gqkv,  g_qkv);
    cudaGetSymbolAddress((void**)&gattn, g_attn);
    cudaGetSymbolAddress((void**)&gt1,   g_t1);
    cudaGetSymbolAddress((void**)&gt2,   g_t2);
    cudaGetSymbolAddress((void**)&gff,   g_ff);
    cudaGetSymbolAddress((void**)&grs,   g_rs);
    cudaGetSymbolAddress((void**)&gsel,  g_sel);
    cudaGetSymbolAddress((void**)&gw,    g_w);

    __half *wqkv2, *wo2, *w12, *w22, *act2;
    cudaGetSymbolAddress((void**)&wqkv2, g_wqkv2);
    cudaGetSymbolAddress((void**)&wo2,   g_wo2);
    cudaGetSymbolAddress((void**)&w12,   g_w12);
    cudaGetSymbolAddress((void**)&w22,   g_w22);
    cudaGetSymbolAddress((void**)&act2,  g_act2);

    cudaFuncSetAttribute(attn_kernel, cudaFuncAttributeMaxDynamicSharedMemorySize, ATTN_SMEM);

    // split all weights into fp16 hi + scaled-lo planes (once per launch)
    split2(Wqkv, wqkv2, wqkv2 + WQKV_SZ, WQKV_SZ);
    split2(Wo,   wo2,   wo2   + WO_SZ,   WO_SZ);
    split2(W1,   w12,   w12   + W1_SZ,   W1_SZ);
    split2(W2,   w22,   w22   + W2_SZ,   W2_SZ);

    __half* ah = act2;
    __half* al = act2 + (size_t)ACT_SZ;

    const int n4 = NTOK*D_MODEL/4;
    copy_f4<<<(n4 + 255)/256, 256>>>((const float4*)x, (float4*)gx, n4);

    for (int L = 0; L < NLAYER; L++) {
        WP2 wq_l = { wqkv2 + (size_t)L*3*D_MODEL*D_MODEL,
                     wqkv2 + WQKV_SZ + (size_t)L*3*D_MODEL*D_MODEL };
        WP2 wo_l = { wo2 + (size_t)L*D_MODEL*D_MODEL,
                     wo2 + WO_SZ + (size_t)L*D_MODEL*D_MODEL };
        WP2 w1_l = { w12 + (size_t)L*DFF_*D_MODEL,
                     w12 + W1_SZ + (size_t)L*DFF_*D_MODEL };
        WP2 w2_l = { w22 + (size_t)L*D_MODEL*DFF_,
                     w22 + W2_SZ + (size_t)L*D_MODEL*DFF_ };
        const float* bq_l  = bqkv + (size_t)L*3*D_MODEL;
        const float* bo_l  = bo   + (size_t)L*D_MODEL;
        const float* b1_l  = b1   + (size_t)L*DFF_;
        const float* b2_l  = b2   + (size_t)L*D_MODEL;
        const float* g1_l  = g1   + (size_t)L*D_MODEL;
        const float* be1_l = be1  + (size_t)L*D_MODEL;
        const float* g2_l  = g2   + (size_t)L*D_MODEL;
        const float* be2_l = be2  + (size_t)L*D_MODEL;

        if (L & 1) {
            router_kernel<<<NTOK, 256>>>(gx, rw + (size_t)L*D_MODEL, grs);
            topk_kernel<<<BATCH, 1024>>>(grs, gsel, gw);
            gather_kernel<<<NSEL, 256>>>(gx, gsel, gxsel);
            run_encoder(gxsel, gattn, NSEL, KSEL, BATCH,
                        wq_l, bq_l, wo_l, bo_l, w1_l, b1_l, w2_l, b2_l,
                        g1_l, be1_l, g2_l, be2_l,
                        gqkv, gattn, gt1, gt2, gff, ah, al);
            scatter_kernel<<<NSEL, 256>>>(gx, gsel, gw, gxsel, gattn);
        } else {
            run_encoder(gx, gx, NTOK, SEQ, BATCH,
                        wq_l, bq_l, wo_l, bo_l, w1_l, b1_l, w2_l, b2_l,
                        g1_l, be1_l, g2_l, be2_l,
                        gqkv, gattn, gt1, gt2, gff, ah, al);
        }
    }

    copy_f4<<<(n4 + 255)/256, 256>>>((const float4*)gx, (float4*)d_out, n4);
}

// round 10
// speedup vs baseline: 1.7145x; 1.2748x over previous
#include <cuda_runtime.h>
#include <cuda_fp16.h>
#include <math.h>
#include <stdint.h>

#define D_MODEL 1024
#define NHEAD   16
#define HDIM    64
#define DFF_    4096
#define NLAYER  6
#define BATCH   4
#define SEQ     2048
#define NTOK    (BATCH*SEQ)      /* 8192 */
#define KSEL    1024
#define NSEL    (BATCH*KSEL)     /* 4096 */

#define WQKV_SZ (NLAYER*3*D_MODEL*D_MODEL)
#define WO_SZ   (NLAYER*D_MODEL*D_MODEL)
#define W1_SZ   (NLAYER*DFF_*D_MODEL)
#define W2_SZ   (NLAYER*D_MODEL*DFF_)
#define ACT_SZ  (NTOK*DFF_)

#define LOW_SCALE   2048.0f
#define LOW_UNSCALE (1.0f/2048.0f)

// ---------------- scratch (device globals; no allocations allowed) ----------
__device__ __align__(256) float g_x   [NTOK*D_MODEL];
__device__ __align__(256) float g_xsel[NSEL*D_MODEL];
__device__ __align__(256) float g_qkv [NTOK*3*D_MODEL];
__device__ __align__(256) float g_attn[NTOK*D_MODEL];
__device__ __align__(256) float g_t1  [NTOK*D_MODEL];
__device__ __align__(256) float g_t2  [NTOK*D_MODEL];
__device__ __align__(256) float g_ff  [NTOK*DFF_];
__device__ __align__(256) float g_rs  [BATCH*SEQ];
__device__ __align__(256) int   g_sel [BATCH*KSEL];
__device__ __align__(256) float g_w   [BATCH*KSEL];

// fp16 split-plane buffers (h, l*2048)
__device__ __align__(256) __half g_wqkv2[2][WQKV_SZ];
__device__ __align__(256) __half g_wo2  [2][WO_SZ];
__device__ __align__(256) __half g_w12  [2][W1_SZ];
__device__ __align__(256) __half g_w22  [2][W2_SZ];
__device__ __align__(256) __half g_act2 [2][ACT_SZ];

// ---------------- simple float4 copy ---------------------------------------
__global__ void copy_f4(const float4* __restrict__ src, float4* __restrict__ dst, int n4) {
    int i = blockIdx.x * blockDim.x + threadIdx.x;
    if (i < n4) dst[i] = src[i];
}

// ---------------- 2-way fp16 split (low plane scaled by 2048) ----------------
__global__ __launch_bounds__(256)
void split2_kernel(const float* __restrict__ in,
                   __half* __restrict__ ph, __half* __restrict__ pl, int n8) {
    int i = blockIdx.x * blockDim.x + threadIdx.x;
    if (i >= n8) return;
    const float4* p = (const float4*)in + (size_t)i * 2;
    float4 x0 = p[0], x1 = p[1];
    float v[8] = {x0.x, x0.y, x0.z, x0.w, x1.x, x1.y, x1.z, x1.w};
    __align__(16) __half hh[8], ll[8];
    #pragma unroll
    for (int k = 0; k < 8; k++) {
        __half h = __float2half_rn(v[k]);
        hh[k] = h;
        float r = (v[k] - __half2float(h)) * LOW_SCALE;
        ll[k] = __float2half_rn(r);
    }
    *(uint4*)(ph + (size_t)i * 8) = *(uint4*)hh;
    *(uint4*)(pl + (size_t)i * 8) = *(uint4*)ll;
}

static inline void split2(const float* in, __half* h, __half* l, size_t n) {
    int n8 = (int)(n / 8);
    split2_kernel<<<(n8 + 255) / 256, 256>>>(in, h, l, n8);
}

#define MMA_F16(d, a, b) \
    asm volatile("mma.sync.aligned.m16n8k16.row.col.f32.f16.f16.f32 " \
        "{%0,%1,%2,%3}, {%4,%5,%6,%7}, {%8,%9}, {%0,%1,%2,%3};" \
        : "+f"((d)[0]), "+f"((d)[1]), "+f"((d)[2]), "+f"((d)[3]) \
        : "r"((a)[0]), "r"((a)[1]), "r"((a)[2]), "r"((a)[3]), "r"((b)[0]), "r"((b)[1]))

__device__ __forceinline__ void cp_async16(uint32_t smem_addr, const void* gptr) {
    asm volatile("cp.async.ca.shared.global [%0], [%1], 16;" :: "r"(smem_addr), "l"(gptr));
}
#define CP_COMMIT() asm volatile("cp.async.commit_group;" ::: "memory")
#define CP_WAIT_1() asm volatile("cp.async.wait_group 1;" ::: "memory")
#define CP_WAIT_0() asm volatile("cp.async.wait_group 0;" ::: "memory")

// ---------------- fp16 2-plane split GEMM, double-buffered cp.async ----------
// C[N,M] = A[N,K] @ W[M,K]^T + bias, optional relu.
// A = ah + al/2048, W = wh + wl/2048 (lo planes pre-scaled by 2048)
// acc1 = sum ah*wh ; acc2 = sum (ah*wl + al*wh) ; C = acc1 + acc2/2048
// Block 128x128, BK=32, 256 threads (8 warps: 2m x 4n), warp tile 64x32.
// Dynamic smem: 2 bufs x [A,W] x 2 planes x 128x40 halves = 80KB.
#define BK2 32
#define SROW2 40                       /* 32 + 8 pad halves; 80B row stride */
#define PLANE_HALVES (128*SROW2)       /* 5120 */
#define GEMM_SMEM_BYTES (2*2*2*PLANE_HALVES*2)

template<int RELU>
__global__ __launch_bounds__(256)
void gemm_fp16x2(const __half* __restrict__ Ah, const __half* __restrict__ Al,
                 const __half* __restrict__ Wh, const __half* __restrict__ Wl,
                 const float* __restrict__ bias, float* __restrict__ C,
                 int N, int M, int K) {
    extern __shared__ __half smh[];
    // layout: [buf][tensor(0=A,1=W)][plane] each PLANE_HALVES
    const int t    = threadIdx.x;
    const int lane = t & 31;
    const int warp = t >> 5;
    const int wm   = warp >> 2;      // 0..1
    const int wn   = warp & 3;       // 0..3
    const int rn   = blockIdx.y * 128;
    const int cm   = blockIdx.x * 128;
    const int g    = lane >> 2;      // 0..7
    const int tg   = lane & 3;       // 0..3

    const __half* Ap[2] = { Ah, Al };
    const __half* Wp[2] = { Wh, Wl };

    const uint32_t smem_u32 = (uint32_t)__cvta_generic_to_shared(smh);
    // this thread's two staging chunks: chunk c -> row c>>2, k-offset (c&3)*8 halves
    const int c0r = t >> 2,        c0k = (t & 3) * 8;
    const int c1r = (t + 256) >> 2, c1k = ((t + 256) & 3) * 8;

    float acc1[4][4][4], acc2[4][4][4];
    #pragma unroll
    for (int i = 0; i < 4; i++)
        #pragma unroll
        for (int j = 0; j < 4; j++)
            #pragma unroll
            for (int r = 0; r < 4; r++) { acc1[i][j][r] = 0.f; acc2[i][j][r] = 0.f; }

    const int KT = K / BK2;

    // issue one stage of cp.async loads (8 x 16B per thread), then commit
    auto issue_stage = [&](int buf, int k0) {
        #pragma unroll
        for (int p = 0; p < 2; p++) {
            uint32_t baseA = smem_u32 + (uint32_t)(((buf*2 + 0)*2 + p) * PLANE_HALVES) * 2;
            uint32_t baseW = smem_u32 + (uint32_t)(((buf*2 + 1)*2 + p) * PLANE_HALVES) * 2;
            cp_async16(baseA + (uint32_t)(c0r*SROW2 + c0k)*2, Ap[p] + (size_t)(rn + c0r)*K + k0 + c0k);
            cp_async16(baseA + (uint32_t)(c1r*SROW2 + c1k)*2, Ap[p] + (size_t)(rn + c1r)*K + k0 + c1k);
            cp_async16(baseW + (uint32_t)(c0r*SROW2 + c0k)*2, Wp[p] + (size_t)(cm + c0r)*K + k0 + c0k);
            cp_async16(baseW + (uint32_t)(c1r*SROW2 + c1k)*2, Wp[p] + (size_t)(cm + c1r)*K + k0 + c1k);
        }
        CP_COMMIT();
    };

    issue_stage(0, 0);

    for (int kt = 0; kt < KT; kt++) {
        const int cur = kt & 1;
        const bool more = (kt + 1) < KT;
        if (more) issue_stage(cur ^ 1, (kt + 1) * BK2);
        if (more) CP_WAIT_1(); else CP_WAIT_0();
        __syncthreads();

        const __half* sA0 = smh + ((cur*2 + 0)*2 + 0) * PLANE_HALVES;
        const __half* sA1 = smh + ((cur*2 + 0)*2 + 1) * PLANE_HALVES;
        const __half* sW0 = smh + ((cur*2 + 1)*2 + 0) * PLANE_HALVES;
        const __half* sW1 = smh + ((cur*2 + 1)*2 + 1) * PLANE_HALVES;

        #pragma unroll
        for (int ks0 = 0; ks0 < BK2; ks0 += 16) {
            uint32_t fb[2][4][2];
            #pragma unroll
            for (int jn = 0; jn < 4; jn++) {
                const int c0 = wn * 32 + jn * 8 + g;
                fb[0][jn][0] = *(const uint32_t*)&sW0[c0*SROW2 + ks0 + tg*2];
                fb[0][jn][1] = *(const uint32_t*)&sW0[c0*SROW2 + ks0 + tg*2 + 8];
                fb[1][jn][0] = *(const uint32_t*)&sW1[c0*SROW2 + ks0 + tg*2];
                fb[1][jn][1] = *(const uint32_t*)&sW1[c0*SROW2 + ks0 + tg*2 + 8];
            }
            #pragma unroll
            for (int im = 0; im < 4; im++) {
                const int r0 = wm * 64 + im * 16;
                uint32_t fa[2][4];
                fa[0][0] = *(const uint32_t*)&sA0[(r0 + g    )*SROW2 + ks0 + tg*2];
                fa[0][1] = *(const uint32_t*)&sA0[(r0 + g + 8)*SROW2 + ks0 + tg*2];
                fa[0][2] = *(const uint32_t*)&sA0[(r0 + g    )*SROW2 + ks0 + tg*2 + 8];
                fa[0][3] = *(const uint32_t*)&sA0[(r0 + g + 8)*SROW2 + ks0 + tg*2 + 8];
                fa[1][0] = *(const uint32_t*)&sA1[(r0 + g    )*SROW2 + ks0 + tg*2];
                fa[1][1] = *(const uint32_t*)&sA1[(r0 + g + 8)*SROW2 + ks0 + tg*2];
                fa[1][2] = *(const uint32_t*)&sA1[(r0 + g    )*SROW2 + ks0 + tg*2 + 8];
                fa[1][3] = *(const uint32_t*)&sA1[(r0 + g + 8)*SROW2 + ks0 + tg*2 + 8];
                #pragma unroll
                for (int jn = 0; jn < 4; jn++) {
                    MMA_F16(acc1[im][jn], fa[0], fb[0][jn]);  // hh -> acc1
                    MMA_F16(acc2[im][jn], fa[0], fb[1][jn]);  // h*l -> acc2
                    MMA_F16(acc2[im][jn], fa[1], fb[0][jn]);  // l*h -> acc2
                }
            }
        }
        __syncthreads();
    }

    // epilogue: combine planes in fp32, bias (+relu), direct stores
    #pragma unroll
    for (int im = 0; im < 4; im++) {
        #pragma unroll
        for (int jn = 0; jn < 4; jn++) {
            const int row = rn + wm * 64 + im * 16 + g;
            const int col = cm + wn * 32 + jn * 8 + tg * 2;
            float b0 = bias[col], b1 = bias[col + 1];
            float v0 = acc1[im][jn][0] + acc2[im][jn][0] * LOW_UNSCALE + b0;
            float v1 = acc1[im][jn][1] + acc2[im][jn][1] * LOW_UNSCALE + b1;
            float v2 = acc1[im][jn][2] + acc2[im][jn][2] * LOW_UNSCALE + b0;
            float v3 = acc1[im][jn][3] + acc2[im][jn][3] * LOW_UNSCALE + b1;
            if (RELU) {
                v0 = fmaxf(v0, 0.f); v1 = fmaxf(v1, 0.f);
                v2 = fmaxf(v2, 0.f); v3 = fmaxf(v3, 0.f);
            }
            *(float2*)&C[(size_t)row * M + col]       = make_float2(v0, v1);
            *(float2*)&C[(size_t)(row + 8) * M + col] = make_float2(v2, v3);
        }
    }
}

// ---------------- flash attention (fp32, HD=64) -----------------------------
#define PS_STRIDE 65
#define ATTN_SMEM ((3*64*64 + 64*PS_STRIDE + 3*64) * 4)

__global__ __launch_bounds__(256)
void attn_kernel(const float* __restrict__ qkv, float* __restrict__ out,
                 int T) {
    extern __shared__ float sm[];
    float* Qs   = sm;
    float* Ks   = Qs + 64*64;
    float* Vs   = Ks + 64*64;
    float* Ps   = Vs + 64*64;
    float* mrow = Ps + 64*PS_STRIDE;
    float* lrow = mrow + 64;
    float* arow = lrow + 64;

    const int t  = threadIdx.x;
    const int tx = t & 15;
    const int ty = t >> 4;
    const int qt = blockIdx.x, h = blockIdx.y, b = blockIdx.z;
    const int stride = 3 * D_MODEL;

    const float* qbase = qkv + (size_t)(b*T + qt*64) * stride + h*HDIM;
    for (int it = t; it < 64*16; it += 256) {
        int q = it >> 4; int dg = (it & 15) * 4;
        float4 v = *(const float4*)(qbase + (size_t)q*stride + dg);
        Qs[(dg+0)*64 + q] = v.x; Qs[(dg+1)*64 + q] = v.y;
        Qs[(dg+2)*64 + q] = v.z; Qs[(dg+3)*64 + q] = v.w;
    }
    if (t < 64) { mrow[t] = -1e30f; lrow[t] = 0.f; }

    float oacc[4][4];
    #pragma unroll
    for (int i = 0; i < 4; i++)
        #pragma unroll
        for (int j = 0; j < 4; j++) oacc[i][j] = 0.f;

    const float* kbase0 = qkv + (size_t)(b*T) * stride +     D_MODEL + h*HDIM;
    const float* vbase0 = qkv + (size_t)(b*T) * stride + 2 * D_MODEL + h*HDIM;
    const int nkt = T / 64;

    for (int kt2 = 0; kt2 < nkt; kt2++) {
        __syncthreads();
        const float* kb = kbase0 + (size_t)kt2 * 64 * stride;
        const float* vb = vbase0 + (size_t)kt2 * 64 * stride;
        for (int it = t; it < 64*16; it += 256) {
            int kk = it >> 4; int dg = (it & 15) * 4;
            float4 kv = *(const float4*)(kb + (size_t)kk*stride + dg);
            Ks[(dg+0)*64 + kk] = kv.x; Ks[(dg+1)*64 + kk] = kv.y;
            Ks[(dg+2)*64 + kk] = kv.z; Ks[(dg+3)*64 + kk] = kv.w;
            float4 vv = *(const float4*)(vb + (size_t)kk*stride + dg);
            *(float4*)&Vs[kk*64 + dg] = vv;
        }
        __syncthreads();

        float s[4][4];
        #pragma unroll
        for (int i = 0; i < 4; i++)
            #pragma unroll
            for (int j = 0; j < 4; j++) s[i][j] = 0.f;
        #pragma unroll 16
        for (int d = 0; d < 64; d++) {
            float4 a  = *(const float4*)&Qs[d*64 + ty*4];
            float4 bb = *(const float4*)&Ks[d*64 + tx*4];
            s[0][0] += a.x*bb.x; s[0][1] += a.x*bb.y; s[0][2] += a.x*bb.z; s[0][3] += a.x*bb.w;
            s[1][0] += a.y*bb.x; s[1][1] += a.y*bb.y; s[1][2] += a.y*bb.z; s[1][3] += a.y*bb.w;
            s[2][0] += a.z*bb.x; s[2][1] += a.z*bb.y; s[2][2] += a.z*bb.z; s[2][3] += a.z*bb.w;
            s[3][0] += a.w*bb.x; s[3][1] += a.w*bb.y; s[3][2] += a.w*bb.z; s[3][3] += a.w*bb.w;
        }
        #pragma unroll
        for (int i = 0; i < 4; i++)
            #pragma unroll
            for (int j = 0; j < 4; j++)
                Ps[(ty*4 + i)*PS_STRIDE + tx*4 + j] = s[i][j] * 0.125f;
        __syncthreads();

        if (t < 64) {
            float mo = mrow[t];
            float mt = -1e30f;
            #pragma unroll 8
            for (int k2 = 0; k2 < 64; k2++) mt = fmaxf(mt, Ps[t*PS_STRIDE + k2]);
            float mn = fmaxf(mo, mt);
            float al = __expf(mo - mn);
            float sum = 0.f;
            #pragma unroll 8
            for (int k2 = 0; k2 < 64; k2++) {
                float p = __expf(Ps[t*PS_STRIDE + k2] - mn);
                Ps[t*PS_STRIDE + k2] = p;
                sum += p;
            }
            mrow[t] = mn;
            lrow[t] = lrow[t]*al + sum;
            arow[t] = al;
        }
        __syncthreads();

        float al0 = arow[ty*4+0], al1 = arow[ty*4+1], al2 = arow[ty*4+2], al3 = arow[ty*4+3];
        #pragma unroll
        for (int j = 0; j < 4; j++) {
            oacc[0][j] *= al0; oacc[1][j] *= al1; oacc[2][j] *= al2; oacc[3][j] *= al3;
        }
        #pragma unroll 8
        for (int k2 = 0; k2 < 64; k2++) {
            float4 v = *(const float4*)&Vs[k2*64 + tx*4];
            float p0 = Ps[(ty*4+0)*PS_STRIDE + k2];
            float p1 = Ps[(ty*4+1)*PS_STRIDE + k2];
            float p2 = Ps[(ty*4+2)*PS_STRIDE + k2];
            float p3 = Ps[(ty*4+3)*PS_STRIDE + k2];
            oacc[0][0] += p0*v.x; oacc[0][1] += p0*v.y; oacc[0][2] += p0*v.z; oacc[0][3] += p0*v.w;
            oacc[1][0] += p1*v.x; oacc[1][1] += p1*v.y; oacc[1][2] += p1*v.z; oacc[1][3] += p1*v.w;
            oacc[2][0] += p2*v.x; oacc[2][1] += p2*v.y; oacc[2][2] += p2*v.z; oacc[2][3] += p2*v.w;
            oacc[3][0] += p3*v.x; oacc[3][1] += p3*v.y; oacc[3][2] += p3*v.z; oacc[3][3] += p3*v.w;
        }
    }

    const int n0 = b*T + qt*64;
    #pragma unroll
    for (int i = 0; i < 4; i++) {
        int q = ty*4 + i;
        float inv = 1.f / lrow[q];
        float4 o = make_float4(oacc[i][0]*inv, oacc[i][1]*inv, oacc[i][2]*inv, oacc[i][3]*inv);
        *(float4*)(out + (size_t)(n0 + q)*D_MODEL + h*HDIM + tx*4) = o;
    }
}

// ---------------- residual add + LayerNorm ----------------------------------
__global__ __launch_bounds__(256)
void addln_kernel(const float* __restrict__ a, const float* __restrict__ r,
                  const float* __restrict__ g, const float* __restrict__ be,
                  float* __restrict__ out) {
    __shared__ float rsum[256], rsq[256];
    const int n = blockIdx.x, t = threadIdx.x;
    float4 av = *(const float4*)(a + (size_t)n*D_MODEL + t*4);
    float4 rv = *(const float4*)(r + (size_t)n*D_MODEL + t*4);
    float x0 = av.x + rv.x, x1 = av.y + rv.y, x2 = av.z + rv.z, x3 = av.w + rv.w;
    rsum[t] = x0 + x1 + x2 + x3;
    rsq [t] = x0*x0 + x1*x1 + x2*x2 + x3*x3;
    __syncthreads();
    for (int off = 128; off > 0; off >>= 1) {
        if (t < off) { rsum[t] += rsum[t+off]; rsq[t] += rsq[t+off]; }
        __syncthreads();
    }
    float mu  = rsum[0] * (1.f/1024.f);
    float var = rsq[0]  * (1.f/1024.f) - mu*mu;
    float rstd = rsqrtf(var + 1e-5f);
    float4 gv = *(const float4*)(g  + t*4);
    float4 bv = *(const float4*)(be + t*4);
    float4 o;
    o.x = (x0 - mu)*rstd*gv.x + bv.x;
    o.y = (x1 - mu)*rstd*gv.y + bv.y;
    o.z = (x2 - mu)*rstd*gv.z + bv.z;
    o.w = (x3 - mu)*rstd*gv.w + bv.w;
    *(float4*)(out + (size_t)n*D_MODEL + t*4) = o;
}

// ---------------- router score ----------------------------------------------
__global__ __launch_bounds__(256)
void router_kernel(const float* __restrict__ x, const float* __restrict__ rw,
                   float* __restrict__ out) {
    __shared__ float red[256];
    const int n = blockIdx.x, t = threadIdx.x;
    float4 xv = *(const float4*)(x + (size_t)n*D_MODEL + t*4);
    float4 wv = *(const float4*)(rw + t*4);
    red[t] = xv.x*wv.x + xv.y*wv.y + xv.z*wv.z + xv.w*wv.w;
    __syncthreads();
    for (int off = 128; off > 0; off >>= 1) {
        if (t < off) red[t] += red[t+off];
        __syncthreads();
    }
    if (t == 0) out[n] = red[0];
}

// ---------------- top-k via bitonic sort (desc value, asc index) ------------
__global__ __launch_bounds__(1024)
void topk_kernel(const float* __restrict__ scores, int* __restrict__ sel,
                 float* __restrict__ wout) {
    __shared__ float v[2048];
    __shared__ int  id[2048];
    const int b = blockIdx.x, t = threadIdx.x;
    v[t]        = scores[b*SEQ + t];        id[t]        = t;
    v[t + 1024] = scores[b*SEQ + t + 1024]; id[t + 1024] = t + 1024;
    __syncthreads();
    for (int k = 2; k <= 2048; k <<= 1) {
        for (int j = k >> 1; j > 0; j >>= 1) {
            #pragma unroll
            for (int s = 0; s < 2; s++) {
                int i = t + s*1024;
                int ixj = i ^ j;
                if (ixj > i) {
                    float vi = v[i], vj = v[ixj];
                    int   ii = id[i], ij = id[ixj];
                    bool before = (vi > vj) || (vi == vj && ii < ij);
                    bool up = ((i & k) == 0);
                    bool dosw = up ? (!before) : before;
                    if (dosw) { v[i] = vj; v[ixj] = vi; id[i] = ij; id[ixj] = ii; }
                }
            }
            __syncthreads();
        }
    }
    sel [b*KSEL + t] = id[t];
    wout[b*KSEL + t] = 1.f / (1.f + expf(-v[t]));
}

// ---------------- gather / scatter ------------------------------------------
__global__ __launch_bounds__(256)
void gather_kernel(const float* __restrict__ x, const int* __restrict__ sel,
                   float* __restrict__ xs) {
    const int row = blockIdx.x;
    const int b = row >> 10;
    const int src = b*SEQ + sel[row];
    const int t = threadIdx.x;
    float4 v = *(const float4*)(x + (size_t)src*D_MODEL + t*4);
    *(float4*)(xs + (size_t)row*D_MODEL + t*4) = v;
}

__global__ __launch_bounds__(256)
void scatter_kernel(float* __restrict__ x, const int* __restrict__ sel,
                    const float* __restrict__ w, const float* __restrict__ xs,
                    const float* __restrict__ proc) {
    const int row = blockIdx.x;
    const int b = row >> 10;
    const int dst = b*SEQ + sel[row];
    const float wv = w[row];
    const int t = threadIdx.x;
    float4 p  = *(const float4*)(proc + (size_t)row*D_MODEL + t*4);
    float4 s  = *(const float4*)(xs   + (size_t)row*D_MODEL + t*4);
    float4 xv = *(float4*)(x + (size_t)dst*D_MODEL + t*4);
    xv.x += (p.x - s.x)*wv;
    xv.y += (p.y - s.y)*wv;
    xv.z += (p.z - s.z)*wv;
    xv.w += (p.w - s.w)*wv;
    *(float4*)(x + (size_t)dst*D_MODEL + t*4) = xv;
}

// ---------------- host-side helpers ------------------------------------------
struct WP2 { __half *h, *l; };

static void run_encoder(const float* Xin, float* Xout, int Ncur, int Tcur, int Bcur,
                        WP2 wq, const float* bq, WP2 wo, const float* bo,
                        WP2 w1, const float* b1, WP2 w2, const float* b2,
                        const float* g1, const float* be1, const float* g2, const float* be2,
                        float* qkv, float* attnb, float* t1, float* t2, float* ff,
                        __half* ah, __half* al) {
    split2(Xin, ah, al, (size_t)Ncur * D_MODEL);
    gemm_fp16x2<0><<<dim3(3*D_MODEL/128, Ncur/128), 256, GEMM_SMEM_BYTES>>>(
        ah, al, wq.h, wq.l, bq, qkv, Ncur, 3*D_MODEL, D_MODEL);
    attn_kernel<<<dim3(Tcur/64, NHEAD, Bcur), 256, ATTN_SMEM>>>(qkv, attnb, Tcur);
    split2(attnb, ah, al, (size_t)Ncur * D_MODEL);
    gemm_fp16x2<0><<<dim3(D_MODEL/128, Ncur/128), 256, GEMM_SMEM_BYTES>>>(
        ah, al, wo.h, wo.l, bo, t2, Ncur, D_MODEL, D_MODEL);
    addln_kernel<<<Ncur, 256>>>(Xin, t2, g1, be1, t1);
    split2(t1, ah, al, (size_t)Ncur * D_MODEL);
    gemm_fp16x2<1><<<dim3(DFF_/128, Ncur/128), 256, GEMM_SMEM_BYTES>>>(
        ah, al, w1.h, w1.l, b1, ff, Ncur, DFF_, D_MODEL);
    split2(ff, ah, al, (size_t)Ncur * DFF_);
    gemm_fp16x2<0><<<dim3(D_MODEL/128, Ncur/128), 256, GEMM_SMEM_BYTES>>>(
        ah, al, w2.h, w2.l, b2, t2, Ncur, D_MODEL, DFF_);
    addln_kernel<<<Ncur, 256>>>(t1, t2, g2, be2, Xout);
}

extern "C" void kernel_launch(void* const* d_in, const int* in_sizes, int n_in,
                              void* d_out, int out_size) {
    (void)in_sizes; (void)n_in; (void)out_size;
    const float* x    = (const float*)d_in[0];
    const float* Wqkv = (const float*)d_in[1];
    const float* bqkv = (const float*)d_in[2];
    const float* Wo   = (const float*)d_in[3];
    const float* bo   = (const float*)d_in[4];
    const float* W1   = (const float*)d_in[5];
    const float* b1   = (const float*)d_in[6];
    const float* W2   = (const float*)d_in[7];
    const float* b2   = (const float*)d_in[8];
    const float* g1   = (const float*)d_in[9];
    const float* be1  = (const float*)d_in[10];
    const float* g2   = (const float*)d_in[11];
    const float* be2  = (const float*)d_in[12];
    const float* rw   = (const float*)d_in[13];

    float *gx, *gxsel, *gqkv, *gattn, *gt1, *gt2, *gff, *grs, *gw; int* gsel;
    cudaGetSymbolAddress((void**)&gx,    g_x);
    cudaGetSymbolAddress((void**)&gxsel, g_xsel);
    cudaGetSymbolAddress((void**)&gqkv,  g_qkv);
    cudaGetSymbolAddress((void**)&gattn, g_attn);
    cudaGetSymbolAddress((void**)&gt1,   g_t1);
    cudaGetSymbolAddress((void**)&gt2,   g_t2);
    cudaGetSymbolAddress((void**)&gff,   g_ff);
    cudaGetSymbolAddress((void**)&grs,   g_rs);
    cudaGetSymbolAddress((void**)&gsel,  g_sel);
    cudaGetSymbolAddress((void**)&gw,    g_w);

    __half *wqkv2, *wo2, *w12, *w22, *act2;
    cudaGetSymbolAddress((void**)&wqkv2, g_wqkv2);
    cudaGetSymbolAddress((void**)&wo2,   g_wo2);
    cudaGetSymbolAddress((void**)&w12,   g_w12);
    cudaGetSymbolAddress((void**)&w22,   g_w22);
    cudaGetSymbolAddress((void**)&act2,  g_act2);

    cudaFuncSetAttribute(attn_kernel, cudaFuncAttributeMaxDynamicSharedMemorySize, ATTN_SMEM);
    cudaFuncSetAttribute(gemm_fp16x2<0>, cudaFuncAttributeMaxDynamicSharedMemorySize, GEMM_SMEM_BYTES);
    cudaFuncSetAttribute(gemm_fp16x2<1>, cudaFuncAttributeMaxDynamicSharedMemorySize, GEMM_SMEM_BYTES);

    // split all weights into fp16 hi + scaled-lo planes (once per launch)
    split2(Wqkv, wqkv2, wqkv2 + WQKV_SZ, WQKV_SZ);
    split2(Wo,   wo2,   wo2   + WO_SZ,   WO_SZ);
    split2(W1,   w12,   w12   + W1_SZ,   W1_SZ);
    split2(W2,   w22,   w22   + W2_SZ,   W2_SZ);

    __half* ah = act2;
    __half* al = act2 + (size_t)ACT_SZ;

    const int n4 = NTOK*D_MODEL/4;
    copy_f4<<<(n4 + 255)/256, 256>>>((const float4*)x, (float4*)gx, n4);

    for (int L = 0; L < NLAYER; L++) {
        WP2 wq_l = { wqkv2 + (size_t)L*3*D_MODEL*D_MODEL,
                     wqkv2 + WQKV_SZ + (size_t)L*3*D_MODEL*D_MODEL };
        WP2 wo_l = { wo2 + (size_t)L*D_MODEL*D_MODEL,
                     wo2 + WO_SZ + (size_t)L*D_MODEL*D_MODEL };
        WP2 w1_l = { w12 + (size_t)L*DFF_*D_MODEL,
                     w12 + W1_SZ + (size_t)L*DFF_*D_MODEL };
        WP2 w2_l = { w22 + (size_t)L*D_MODEL*DFF_,
                     w22 + W2_SZ + (size_t)L*D_MODEL*DFF_ };
        const float* bq_l  = bqkv + (size_t)L*3*D_MODEL;
        const float* bo_l  = bo   + (size_t)L*D_MODEL;
        const float* b1_l  = b1   + (size_t)L*DFF_;
        const float* b2_l  = b2   + (size_t)L*D_MODEL;
        const float* g1_l  = g1   + (size_t)L*D_MODEL;
        const float* be1_l = be1  + (size_t)L*D_MODEL;
        const float* g2_l  = g2   + (size_t)L*D_MODEL;
        const float* be2_l = be2  + (size_t)L*D_MODEL;

        if (L & 1) {
            router_kernel<<<NTOK, 256>>>(gx, rw + (size_t)L*D_MODEL, grs);
            topk_kernel<<<BATCH, 1024>>>(grs, gsel, gw);
            gather_kernel<<<NSEL, 256>>>(gx, gsel, gxsel);
            run_encoder(gxsel, gattn, NSEL, KSEL, BATCH,
                        wq_l, bq_l, wo_l, bo_l, w1_l, b1_l, w2_l, b2_l,
                        g1_l, be1_l, g2_l, be2_l,
                        gqkv, gattn, gt1, gt2, gff, ah, al);
            scatter_kernel<<<NSEL, 256>>>(gx, gsel, gw, gxsel, gattn);
        } else {
            run_encoder(gx, gx, NTOK, SEQ, BATCH,
                        wq_l, bq_l, wo_l, bo_l, w1_l, b1_l, w2_l, b2_l,
                        g1_l, be1_l, g2_l, be2_l,
                        gqkv, gattn, gt1, gt2, gff, ah, al);
        }
    }

    copy_f4<<<(n4 + 255)/256, 256>>>((const float4*)gx, (float4*)d_out, n4);
}

// round 11
// speedup vs baseline: 2.1478x; 1.2527x over previous
#include <cuda_runtime.h>
#include <cuda_fp16.h>
#include <math.h>
#include <stdint.h>

#define D_MODEL 1024
#define NHEAD   16
#define HDIM    64
#define DFF_    4096
#define NLAYER  6
#define BATCH   4
#define SEQ     2048
#define NTOK    (BATCH*SEQ)      /* 8192 */
#define KSEL    1024
#define NSEL    (BATCH*KSEL)     /* 4096 */

#define WQKV_SZ (NLAYER*3*D_MODEL*D_MODEL)
#define WO_SZ   (NLAYER*D_MODEL*D_MODEL)
#define W1_SZ   (NLAYER*DFF_*D_MODEL)
#define W2_SZ   (NLAYER*D_MODEL*DFF_)
#define ACT_SZ  (NTOK*DFF_)

#define LOW_SCALE   2048.0f
#define LOW_UNSCALE (1.0f/2048.0f)

// ---------------- scratch (device globals; no allocations allowed) ----------
__device__ __align__(256) float g_x   [NTOK*D_MODEL];
__device__ __align__(256) float g_xsel[NSEL*D_MODEL];
__device__ __align__(256) float g_qkv [NTOK*3*D_MODEL];
__device__ __align__(256) float g_attn[NTOK*D_MODEL];
__device__ __align__(256) float g_t1  [NTOK*D_MODEL];
__device__ __align__(256) float g_t2  [NTOK*D_MODEL];
__device__ __align__(256) float g_ff  [NTOK*DFF_];
__device__ __align__(256) float g_rs  [BATCH*SEQ];
__device__ __align__(256) int   g_sel [BATCH*KSEL];
__device__ __align__(256) float g_w   [BATCH*KSEL];

// fp16 split-plane buffers (h, l*2048)
__device__ __align__(256) __half g_wqkv2[2][WQKV_SZ];
__device__ __align__(256) __half g_wo2  [2][WO_SZ];
__device__ __align__(256) __half g_w12  [2][W1_SZ];
__device__ __align__(256) __half g_w22  [2][W2_SZ];
__device__ __align__(256) __half g_act2 [2][ACT_SZ];

// ---------------- simple float4 copy ---------------------------------------
__global__ void copy_f4(const float4* __restrict__ src, float4* __restrict__ dst, int n4) {
    int i = blockIdx.x * blockDim.x + threadIdx.x;
    if (i < n4) dst[i] = src[i];
}

// ---------------- 2-way fp16 split (low plane scaled by 2048) ----------------
__global__ __launch_bounds__(256)
void split2_kernel(const float* __restrict__ in,
                   __half* __restrict__ ph, __half* __restrict__ pl, int n8) {
    int i = blockIdx.x * blockDim.x + threadIdx.x;
    if (i >= n8) return;
    const float4* p = (const float4*)in + (size_t)i * 2;
    float4 x0 = p[0], x1 = p[1];
    float v[8] = {x0.x, x0.y, x0.z, x0.w, x1.x, x1.y, x1.z, x1.w};
    __align__(16) __half hh[8], ll[8];
    #pragma unroll
    for (int k = 0; k < 8; k++) {
        __half h = __float2half_rn(v[k]);
        hh[k] = h;
        float r = (v[k] - __half2float(h)) * LOW_SCALE;
        ll[k] = __float2half_rn(r);
    }
    *(uint4*)(ph + (size_t)i * 8) = *(uint4*)hh;
    *(uint4*)(pl + (size_t)i * 8) = *(uint4*)ll;
}

static inline void split2(const float* in, __half* h, __half* l, size_t n) {
    int n8 = (int)(n / 8);
    split2_kernel<<<(n8 + 255) / 256, 256>>>(in, h, l, n8);
}

#define MMA_F16(d, a, b) \
    asm volatile("mma.sync.aligned.m16n8k16.row.col.f32.f16.f16.f32 " \
        "{%0,%1,%2,%3}, {%4,%5,%6,%7}, {%8,%9}, {%0,%1,%2,%3};" \
        : "+f"((d)[0]), "+f"((d)[1]), "+f"((d)[2]), "+f"((d)[3]) \
        : "r"((a)[0]), "r"((a)[1]), "r"((a)[2]), "r"((a)[3]), "r"((b)[0]), "r"((b)[1]))

__device__ __forceinline__ void cp_async16(uint32_t smem_addr, const void* gptr) {
    asm volatile("cp.async.ca.shared.global [%0], [%1], 16;" :: "r"(smem_addr), "l"(gptr));
}
#define CP_COMMIT() asm volatile("cp.async.commit_group;" ::: "memory")
#define CP_WAIT_1() asm volatile("cp.async.wait_group 1;" ::: "memory")
#define CP_WAIT_0() asm volatile("cp.async.wait_group 0;" ::: "memory")

// ---------------- fast exp on FMA pipe (no MUFU), rel err ~1.5e-6 ------------
__device__ __forceinline__ float fexp(float x) {
    x = fmaxf(x, -80.0f);
    float t  = x * 1.4426950408889634f;
    float fl = floorf(t);
    float f  = t - fl;
    float p  = 1.5252734e-5f;
    p = fmaf(p, f, 1.5403530e-4f);
    p = fmaf(p, f, 1.3333558e-3f);
    p = fmaf(p, f, 9.6181291e-3f);
    p = fmaf(p, f, 5.5504109e-2f);
    p = fmaf(p, f, 2.4022651e-1f);
    p = fmaf(p, f, 6.9314718e-1f);
    p = fmaf(p, f, 1.0f);
    int i = (int)fl;
    float sc = __int_as_float((i + 127) << 23);
    return p * sc;
}

// ---------------- fp16 2-plane split GEMM, double-buffered cp.async ----------
#define BK2 32
#define SROW2 40
#define PLANE_HALVES (128*SROW2)
#define GEMM_SMEM_BYTES (2*2*2*PLANE_HALVES*2)

template<int RELU>
__global__ __launch_bounds__(256)
void gemm_fp16x2(const __half* __restrict__ Ah, const __half* __restrict__ Al,
                 const __half* __restrict__ Wh, const __half* __restrict__ Wl,
                 const float* __restrict__ bias, float* __restrict__ C,
                 int N, int M, int K) {
    extern __shared__ __half smh[];
    const int t    = threadIdx.x;
    const int lane = t & 31;
    const int warp = t >> 5;
    const int wm   = warp >> 2;
    const int wn   = warp & 3;
    const int rn   = blockIdx.y * 128;
    const int cm   = blockIdx.x * 128;
    const int g    = lane >> 2;
    const int tg   = lane & 3;

    const __half* Ap[2] = { Ah, Al };
    const __half* Wp[2] = { Wh, Wl };

    const uint32_t smem_u32 = (uint32_t)__cvta_generic_to_shared(smh);
    const int c0r = t >> 2,        c0k = (t & 3) * 8;
    const int c1r = (t + 256) >> 2, c1k = ((t + 256) & 3) * 8;

    float acc1[4][4][4], acc2[4][4][4];
    #pragma unroll
    for (int i = 0; i < 4; i++)
        #pragma unroll
        for (int j = 0; j < 4; j++)
            #pragma unroll
            for (int r = 0; r < 4; r++) { acc1[i][j][r] = 0.f; acc2[i][j][r] = 0.f; }

    const int KT = K / BK2;

    auto issue_stage = [&](int buf, int k0) {
        #pragma unroll
        for (int p = 0; p < 2; p++) {
            uint32_t baseA = smem_u32 + (uint32_t)(((buf*2 + 0)*2 + p) * PLANE_HALVES) * 2;
            uint32_t baseW = smem_u32 + (uint32_t)(((buf*2 + 1)*2 + p) * PLANE_HALVES) * 2;
            cp_async16(baseA + (uint32_t)(c0r*SROW2 + c0k)*2, Ap[p] + (size_t)(rn + c0r)*K + k0 + c0k);
            cp_async16(baseA + (uint32_t)(c1r*SROW2 + c1k)*2, Ap[p] + (size_t)(rn + c1r)*K + k0 + c1k);
            cp_async16(baseW + (uint32_t)(c0r*SROW2 + c0k)*2, Wp[p] + (size_t)(cm + c0r)*K + k0 + c0k);
            cp_async16(baseW + (uint32_t)(c1r*SROW2 + c1k)*2, Wp[p] + (size_t)(cm + c1r)*K + k0 + c1k);
        }
        CP_COMMIT();
    };

    issue_stage(0, 0);

    for (int kt = 0; kt < KT; kt++) {
        const int cur = kt & 1;
        const bool more = (kt + 1) < KT;
        if (more) issue_stage(cur ^ 1, (kt + 1) * BK2);
        if (more) CP_WAIT_1(); else CP_WAIT_0();
        __syncthreads();

        const __half* sA0 = smh + ((cur*2 + 0)*2 + 0) * PLANE_HALVES;
        const __half* sA1 = smh + ((cur*2 + 0)*2 + 1) * PLANE_HALVES;
        const __half* sW0 = smh + ((cur*2 + 1)*2 + 0) * PLANE_HALVES;
        const __half* sW1 = smh + ((cur*2 + 1)*2 + 1) * PLANE_HALVES;

        #pragma unroll
        for (int ks0 = 0; ks0 < BK2; ks0 += 16) {
            uint32_t fb[2][4][2];
            #pragma unroll
            for (int jn = 0; jn < 4; jn++) {
                const int c0 = wn * 32 + jn * 8 + g;
                fb[0][jn][0] = *(const uint32_t*)&sW0[c0*SROW2 + ks0 + tg*2];
                fb[0][jn][1] = *(const uint32_t*)&sW0[c0*SROW2 + ks0 + tg*2 + 8];
                fb[1][jn][0] = *(const uint32_t*)&sW1[c0*SROW2 + ks0 + tg*2];
                fb[1][jn][1] = *(const uint32_t*)&sW1[c0*SROW2 + ks0 + tg*2 + 8];
            }
            #pragma unroll
            for (int im = 0; im < 4; im++) {
                const int r0 = wm * 64 + im * 16;
                uint32_t fa[2][4];
                fa[0][0] = *(const uint32_t*)&sA0[(r0 + g    )*SROW2 + ks0 + tg*2];
                fa[0][1] = *(const uint32_t*)&sA0[(r0 + g + 8)*SROW2 + ks0 + tg*2];
                fa[0][2] = *(const uint32_t*)&sA0[(r0 + g    )*SROW2 + ks0 + tg*2 + 8];
                fa[0][3] = *(const uint32_t*)&sA0[(r0 + g + 8)*SROW2 + ks0 + tg*2 + 8];
                fa[1][0] = *(const uint32_t*)&sA1[(r0 + g    )*SROW2 + ks0 + tg*2];
                fa[1][1] = *(const uint32_t*)&sA1[(r0 + g + 8)*SROW2 + ks0 + tg*2];
                fa[1][2] = *(const uint32_t*)&sA1[(r0 + g    )*SROW2 + ks0 + tg*2 + 8];
                fa[1][3] = *(const uint32_t*)&sA1[(r0 + g + 8)*SROW2 + ks0 + tg*2 + 8];
                #pragma unroll
                for (int jn = 0; jn < 4; jn++) {
                    MMA_F16(acc1[im][jn], fa[0], fb[0][jn]);
                    MMA_F16(acc2[im][jn], fa[0], fb[1][jn]);
                    MMA_F16(acc2[im][jn], fa[1], fb[0][jn]);
                }
            }
        }
        __syncthreads();
    }

    #pragma unroll
    for (int im = 0; im < 4; im++) {
        #pragma unroll
        for (int jn = 0; jn < 4; jn++) {
            const int row = rn + wm * 64 + im * 16 + g;
            const int col = cm + wn * 32 + jn * 8 + tg * 2;
            float b0 = bias[col], b1 = bias[col + 1];
            float v0 = acc1[im][jn][0] + acc2[im][jn][0] * LOW_UNSCALE + b0;
            float v1 = acc1[im][jn][1] + acc2[im][jn][1] * LOW_UNSCALE + b1;
            float v2 = acc1[im][jn][2] + acc2[im][jn][2] * LOW_UNSCALE + b0;
            float v3 = acc1[im][jn][3] + acc2[im][jn][3] * LOW_UNSCALE + b1;
            if (RELU) {
                v0 = fmaxf(v0, 0.f); v1 = fmaxf(v1, 0.f);
                v2 = fmaxf(v2, 0.f); v3 = fmaxf(v3, 0.f);
            }
            *(float2*)&C[(size_t)row * M + col]       = make_float2(v0, v1);
            *(float2*)&C[(size_t)(row + 8) * M + col] = make_float2(v2, v3);
        }
    }
}

// ---------------- MMA flash attention (fp16 split, poly exp) -----------------
// Block: 64 queries x (head, batch). 256 threads, 8 warps (2m x 4n).
// S = Q K^T (split, 3 mma terms, fp32-class), softmax with poly exp,
// P split into 2 planes, O += P V (split, 3 terms, separate accumulators).
#define QS 72   /* halves row stride for Q/K/Vt/P planes (conflict-free 4g+tg) */
#define SS 68   /* floats row stride for S tile */
#define ATTN_PLANE (64*QS)
#define ATTN_SMEM2 (8*ATTN_PLANE*2 + (64*SS + 3*64)*4)

__global__ __launch_bounds__(256)
void attn_mma(const float* __restrict__ qkv, float* __restrict__ out, int T) {
    extern __shared__ char sm_raw[];
    __half* Qh  = (__half*)sm_raw;
    __half* Ql  = Qh  + ATTN_PLANE;
    __half* Kh  = Ql  + ATTN_PLANE;
    __half* Kl  = Kh  + ATTN_PLANE;
    __half* Vth = Kl  + ATTN_PLANE;
    __half* Vtl = Vth + ATTN_PLANE;
    __half* Ph  = Vtl + ATTN_PLANE;
    __half* Pl  = Ph  + ATTN_PLANE;
    float*  Ssm = (float*)(Pl + ATTN_PLANE);
    float*  mrow = Ssm + 64*SS;
    float*  lrow = mrow + 64;
    float*  arow = lrow + 64;

    const int t    = threadIdx.x;
    const int lane = t & 31;
    const int warp = t >> 5;
    const int wm   = warp >> 2;      // 0..1
    const int wn   = warp & 3;       // 0..3
    const int g    = lane >> 2;      // 0..7
    const int tg   = lane & 3;       // 0..3
    const int qt = blockIdx.x, h = blockIdx.y, b = blockIdx.z;
    const int stride = 3 * D_MODEL;

    // ---- load Q tile (64x64), convert+split ----
    {
        const int row = t >> 2, dg = (t & 3) * 16;
        const float* src = qkv + (size_t)(b*T + qt*64 + row) * stride + h*HDIM + dg;
        __align__(16) __half hh[16], ll[16];
        #pragma unroll
        for (int j4 = 0; j4 < 4; j4++) {
            float4 v = *(const float4*)(src + j4*4);
            float vv[4] = {v.x, v.y, v.z, v.w};
            #pragma unroll
            for (int e = 0; e < 4; e++) {
                __half hv = __float2half_rn(vv[e]);
                hh[j4*4+e] = hv;
                ll[j4*4+e] = __float2half_rn((vv[e] - __half2float(hv)) * LOW_SCALE);
            }
        }
        *(uint4*)&Qh[row*QS + dg]     = *(uint4*)&hh[0];
        *(uint4*)&Qh[row*QS + dg + 8] = *(uint4*)&hh[8];
        *(uint4*)&Ql[row*QS + dg]     = *(uint4*)&ll[0];
        *(uint4*)&Ql[row*QS + dg + 8] = *(uint4*)&ll[8];
    }
    if (t < 64) { mrow[t] = -1e30f; lrow[t] = 0.f; }

    float o1[2][2][4], o2[2][2][4];
    #pragma unroll
    for (int i = 0; i < 2; i++)
        #pragma unroll
        for (int j = 0; j < 2; j++)
            #pragma unroll
            for (int r = 0; r < 4; r++) { o1[i][j][r] = 0.f; o2[i][j][r] = 0.f; }

    const int nkt = T / 64;
    for (int kt2 = 0; kt2 < nkt; kt2++) {
        __syncthreads();   // protect K/Vt/P smem reuse
        // ---- load K tile (64x64) and V tile (transposed), convert+split ----
        {
            const int row = t >> 2, dg = (t & 3) * 16;
            const float* ks = qkv + (size_t)(b*T + kt2*64 + row) * stride + D_MODEL + h*HDIM + dg;
            __align__(16) __half hh[16], ll[16];
            #pragma unroll
            for (int j4 = 0; j4 < 4; j4++) {
                float4 v = *(const float4*)(ks + j4*4);
                float vv[4] = {v.x, v.y, v.z, v.w};
                #pragma unroll
                for (int e = 0; e < 4; e++) {
                    __half hv = __float2half_rn(vv[e]);
                    hh[j4*4+e] = hv;
                    ll[j4*4+e] = __float2half_rn((vv[e] - __half2float(hv)) * LOW_SCALE);
                }
            }
            *(uint4*)&Kh[row*QS + dg]     = *(uint4*)&hh[0];
            *(uint4*)&Kh[row*QS + dg + 8] = *(uint4*)&hh[8];
            *(uint4*)&Kl[row*QS + dg]     = *(uint4*)&ll[0];
            *(uint4*)&Kl[row*QS + dg + 8] = *(uint4*)&ll[8];

            const float* vs = qkv + (size_t)(b*T + kt2*64 + row) * stride + 2*D_MODEL + h*HDIM + dg;
            #pragma unroll
            for (int j4 = 0; j4 < 4; j4++) {
                float4 v = *(const float4*)(vs + j4*4);
                float vv[4] = {v.x, v.y, v.z, v.w};
                #pragma unroll
                for (int e = 0; e < 4; e++) {
                    int d = dg + j4*4 + e;
                    __half hv = __float2half_rn(vv[e]);
                    Vth[d*QS + row] = hv;
                    Vtl[d*QS + row] = __float2half_rn((vv[e] - __half2float(hv)) * LOW_SCALE);
                }
            }
        }
        __syncthreads();

        // ---- S = Q K^T (split, 3 terms) ----
        float s1[2][2][4], s2[2][2][4];
        #pragma unroll
        for (int i = 0; i < 2; i++)
            #pragma unroll
            for (int j = 0; j < 2; j++)
                #pragma unroll
                for (int r = 0; r < 4; r++) { s1[i][j][r] = 0.f; s2[i][j][r] = 0.f; }

        #pragma unroll
        for (int ks0 = 0; ks0 < 64; ks0 += 16) {
            uint32_t fb[2][2][2];
            #pragma unroll
            for (int jn = 0; jn < 2; jn++) {
                const int c0 = wn * 16 + jn * 8 + g;
                fb[0][jn][0] = *(const uint32_t*)&Kh[c0*QS + ks0 + tg*2];
                fb[0][jn][1] = *(const uint32_t*)&Kh[c0*QS + ks0 + tg*2 + 8];
                fb[1][jn][0] = *(const uint32_t*)&Kl[c0*QS + ks0 + tg*2];
                fb[1][jn][1] = *(const uint32_t*)&Kl[c0*QS + ks0 + tg*2 + 8];
            }
            #pragma unroll
            for (int im = 0; im < 2; im++) {
                const int r0 = wm * 32 + im * 16;
                uint32_t fa[2][4];
                fa[0][0] = *(const uint32_t*)&Qh[(r0 + g    )*QS + ks0 + tg*2];
                fa[0][1] = *(const uint32_t*)&Qh[(r0 + g + 8)*QS + ks0 + tg*2];
                fa[0][2] = *(const uint32_t*)&Qh[(r0 + g    )*QS + ks0 + tg*2 + 8];
                fa[0][3] = *(const uint32_t*)&Qh[(r0 + g + 8)*QS + ks0 + tg*2 + 8];
                fa[1][0] = *(const uint32_t*)&Ql[(r0 + g    )*QS + ks0 + tg*2];
                fa[1][1] = *(const uint32_t*)&Ql[(r0 + g + 8)*QS + ks0 + tg*2];
                fa[1][2] = *(const uint32_t*)&Ql[(r0 + g    )*QS + ks0 + tg*2 + 8];
                fa[1][3] = *(const uint32_t*)&Ql[(r0 + g + 8)*QS + ks0 + tg*2 + 8];
                #pragma unroll
                for (int jn = 0; jn < 2; jn++) {
                    MMA_F16(s1[im][jn], fa[0], fb[0][jn]);
                    MMA_F16(s2[im][jn], fa[0], fb[1][jn]);
                    MMA_F16(s2[im][jn], fa[1], fb[0][jn]);
                }
            }
        }
        // write scaled S to smem
        #pragma unroll
        for (int im = 0; im < 2; im++) {
            #pragma unroll
            for (int jn = 0; jn < 2; jn++) {
                const int r = wm * 32 + im * 16 + g;
                const int c = wn * 16 + jn * 8 + tg * 2;
                float v0 = (s1[im][jn][0] + s2[im][jn][0]*LOW_UNSCALE) * 0.125f;
                float v1 = (s1[im][jn][1] + s2[im][jn][1]*LOW_UNSCALE) * 0.125f;
                float v2 = (s1[im][jn][2] + s2[im][jn][2]*LOW_UNSCALE) * 0.125f;
                float v3 = (s1[im][jn][3] + s2[im][jn][3]*LOW_UNSCALE) * 0.125f;
                *(float2*)&Ssm[r*SS + c]       = make_float2(v0, v1);
                *(float2*)&Ssm[(r + 8)*SS + c] = make_float2(v2, v3);
            }
        }
        __syncthreads();

        // ---- softmax: 4 threads per row, poly exp ----
        {
            const int row = t >> 2, q4 = (t & 3) * 16;
            float vals[16];
            float mloc = -1e30f;
            #pragma unroll
            for (int j = 0; j < 16; j++) {
                vals[j] = Ssm[row*SS + q4 + j];
                mloc = fmaxf(mloc, vals[j]);
            }
            mloc = fmaxf(mloc, __shfl_xor_sync(0xFFFFFFFF, mloc, 1));
            mloc = fmaxf(mloc, __shfl_xor_sync(0xFFFFFFFF, mloc, 2));
            float mo = mrow[row];
            float mn = fmaxf(mo, mloc);
            float sum = 0.f;
            #pragma unroll
            for (int j = 0; j < 16; j++) {
                float p = fexp(vals[j] - mn);
                sum += p;
                __half hv = __float2half_rn(p);
                Ph[row*QS + q4 + j] = hv;
                Pl[row*QS + q4 + j] = __float2half_rn((p - __half2float(hv)) * LOW_SCALE);
            }
            sum += __shfl_xor_sync(0xFFFFFFFF, sum, 1);
            sum += __shfl_xor_sync(0xFFFFFFFF, sum, 2);
            if ((t & 3) == 0) {
                float al = fexp(mo - mn);
                mrow[row] = mn;
                lrow[row] = lrow[row]*al + sum;
                arow[row] = al;
            }
        }
        __syncthreads();

        // ---- rescale O accumulators, then O += P V ----
        #pragma unroll
        for (int im = 0; im < 2; im++) {
            const int r0 = wm * 32 + im * 16;
            float a0 = arow[r0 + g], a1 = arow[r0 + g + 8];
            #pragma unroll
            for (int jn = 0; jn < 2; jn++) {
                o1[im][jn][0] *= a0; o1[im][jn][1] *= a0;
                o1[im][jn][2] *= a1; o1[im][jn][3] *= a1;
                o2[im][jn][0] *= a0; o2[im][jn][1] *= a0;
                o2[im][jn][2] *= a1; o2[im][jn][3] *= a1;
            }
        }
        #pragma unroll
        for (int ks0 = 0; ks0 < 64; ks0 += 16) {
            uint32_t fb[2][2][2];
            #pragma unroll
            for (int jn = 0; jn < 2; jn++) {
                const int c0 = wn * 16 + jn * 8 + g;   // d index
                fb[0][jn][0] = *(const uint32_t*)&Vth[c0*QS + ks0 + tg*2];
                fb[0][jn][1] = *(const uint32_t*)&Vth[c0*QS + ks0 + tg*2 + 8];
                fb[1][jn][0] = *(const uint32_t*)&Vtl[c0*QS + ks0 + tg*2];
                fb[1][jn][1] = *(const uint32_t*)&Vtl[c0*QS + ks0 + tg*2 + 8];
            }
            #pragma unroll
            for (int im = 0; im < 2; im++) {
                const int r0 = wm * 32 + im * 16;
                uint32_t fa[2][4];
                fa[0][0] = *(const uint32_t*)&Ph[(r0 + g    )*QS + ks0 + tg*2];
                fa[0][1] = *(const uint32_t*)&Ph[(r0 + g + 8)*QS + ks0 + tg*2];
                fa[0][2] = *(const uint32_t*)&Ph[(r0 + g    )*QS + ks0 + tg*2 + 8];
                fa[0][3] = *(const uint32_t*)&Ph[(r0 + g + 8)*QS + ks0 + tg*2 + 8];
                fa[1][0] = *(const uint32_t*)&Pl[(r0 + g    )*QS + ks0 + tg*2];
                fa[1][1] = *(const uint32_t*)&Pl[(r0 + g + 8)*QS + ks0 + tg*2];
                fa[1][2] = *(const uint32_t*)&Pl[(r0 + g    )*QS + ks0 + tg*2 + 8];
                fa[1][3] = *(const uint32_t*)&Pl[(r0 + g + 8)*QS + ks0 + tg*2 + 8];
                #pragma unroll
                for (int jn = 0; jn < 2; jn++) {
                    MMA_F16(o1[im][jn], fa[0], fb[0][jn]);
                    MMA_F16(o2[im][jn], fa[0], fb[1][jn]);
                    MMA_F16(o2[im][jn], fa[1], fb[0][jn]);
                }
            }
        }
    }
    __syncthreads();

    // ---- final: normalize and store ----
    const int n0 = b*T + qt*64;
    #pragma unroll
    for (int im = 0; im < 2; im++) {
        #pragma unroll
        for (int jn = 0; jn < 2; jn++) {
            const int r = wm * 32 + im * 16 + g;
            const int c = wn * 16 + jn * 8 + tg * 2;
            float inv0 = 1.f / lrow[r];
            float inv1 = 1.f / lrow[r + 8];
            float v0 = (o1[im][jn][0] + o2[im][jn][0]*LOW_UNSCALE) * inv0;
            float v1 = (o1[im][jn][1] + o2[im][jn][1]*LOW_UNSCALE) * inv0;
            float v2 = (o1[im][jn][2] + o2[im][jn][2]*LOW_UNSCALE) * inv1;
            float v3 = (o1[im][jn][3] + o2[im][jn][3]*LOW_UNSCALE) * inv1;
            *(float2*)&out[(size_t)(n0 + r)*D_MODEL + h*HDIM + c]     = make_float2(v0, v1);
            *(float2*)&out[(size_t)(n0 + r + 8)*D_MODEL + h*HDIM + c] = make_float2(v2, v3);
        }
    }
}

// ---------------- residual add + LayerNorm ----------------------------------
__global__ __launch_bounds__(256)
void addln_kernel(const float* __restrict__ a, const float* __restrict__ r,
                  const float* __restrict__ g, const float* __restrict__ be,
                  float* __restrict__ out) {
    __shared__ float rsum[256], rsq[256];
    const int n = blockIdx.x, t = threadIdx.x;
    float4 av = *(const float4*)(a + (size_t)n*D_MODEL + t*4);
    float4 rv = *(const float4*)(r + (size_t)n*D_MODEL + t*4);
    float x0 = av.x + rv.x, x1 = av.y + rv.y, x2 = av.z + rv.z, x3 = av.w + rv.w;
    rsum[t] = x0 + x1 + x2 + x3;
    rsq [t] = x0*x0 + x1*x1 + x2*x2 + x3*x3;
    __syncthreads();
    for (int off = 128; off > 0; off >>= 1) {
        if (t < off) { rsum[t] += rsum[t+off]; rsq[t] += rsq[t+off]; }
        __syncthreads();
    }
    float mu  = rsum[0] * (1.f/1024.f);
    float var = rsq[0]  * (1.f/1024.f) - mu*mu;
    float rstd = rsqrtf(var + 1e-5f);
    float4 gv = *(const float4*)(g  + t*4);
    float4 bv = *(const float4*)(be + t*4);
    float4 o;
    o.x = (x0 - mu)*rstd*gv.x + bv.x;
    o.y = (x1 - mu)*rstd*gv.y + bv.y;
    o.z = (x2 - mu)*rstd*gv.z + bv.z;
    o.w = (x3 - mu)*rstd*gv.w + bv.w;
    *(float4*)(out + (size_t)n*D_MODEL + t*4) = o;
}

// ---------------- router score ----------------------------------------------
__global__ __launch_bounds__(256)
void router_kernel(const float* __restrict__ x, const float* __restrict__ rw,
                   float* __restrict__ out) {
    __shared__ float red[256];
    const int n = blockIdx.x, t = threadIdx.x;
    float4 xv = *(const float4*)(x + (size_t)n*D_MODEL + t*4);
    float4 wv = *(const float4*)(rw + t*4);
    red[t] = xv.x*wv.x + xv.y*wv.y + xv.z*wv.z + xv.w*wv.w;
    __syncthreads();
    for (int off = 128; off > 0; off >>= 1) {
        if (t < off) red[t] += red[t+off];
        __syncthreads();
    }
    if (t == 0) out[n] = red[0];
}

// ---------------- top-k via bitonic sort (desc value, asc index) ------------
__global__ __launch_bounds__(1024)
void topk_kernel(const float* __restrict__ scores, int* __restrict__ sel,
                 float* __restrict__ wout) {
    __shared__ float v[2048];
    __shared__ int  id[2048];
    const int b = blockIdx.x, t = threadIdx.x;
    v[t]        = scores[b*SEQ + t];        id[t]        = t;
    v[t + 1024] = scores[b*SEQ + t + 1024]; id[t + 1024] = t + 1024;
    __syncthreads();
    for (int k = 2; k <= 2048; k <<= 1) {
        for (int j = k >> 1; j > 0; j >>= 1) {
            #pragma unroll
            for (int s = 0; s < 2; s++) {
                int i = t + s*1024;
                int ixj = i ^ j;
                if (ixj > i) {
                    float vi = v[i], vj = v[ixj];
                    int   ii = id[i], ij = id[ixj];
                    bool before = (vi > vj) || (vi == vj && ii < ij);
                    bool up = ((i & k) == 0);
                    bool dosw = up ? (!before) : before;
                    if (dosw) { v[i] = vj; v[ixj] = vi; id[i] = ij; id[ixj] = ii; }
                }
            }
            __syncthreads();
        }
    }
    sel [b*KSEL + t] = id[t];
    wout[b*KSEL + t] = 1.f / (1.f + expf(-v[t]));
}

// ---------------- gather / scatter ------------------------------------------
__global__ __launch_bounds__(256)
void gather_kernel(const float* __restrict__ x, const int* __restrict__ sel,
                   float* __restrict__ xs) {
    const int row = blockIdx.x;
    const int b = row >> 10;
    const int src = b*SEQ + sel[row];
    const int t = threadIdx.x;
    float4 v = *(const float4*)(x + (size_t)src*D_MODEL + t*4);
    *(float4*)(xs + (size_t)row*D_MODEL + t*4) = v;
}

__global__ __launch_bounds__(256)
void scatter_kernel(float* __restrict__ x, const int* __restrict__ sel,
                    const float* __restrict__ w, const float* __restrict__ xs,
                    const float* __restrict__ proc) {
    const int row = blockIdx.x;
    const int b = row >> 10;
    const int dst = b*SEQ + sel[row];
    const float wv = w[row];
    const int t = threadIdx.x;
    float4 p  = *(const float4*)(proc + (size_t)row*D_MODEL + t*4);
    float4 s  = *(const float4*)(xs   + (size_t)row*D_MODEL + t*4);
    float4 xv = *(float4*)(x + (size_t)dst*D_MODEL + t*4);
    xv.x += (p.x - s.x)*wv;
    xv.y += (p.y - s.y)*wv;
    xv.z += (p.z - s.z)*wv;
    xv.w += (p.w - s.w)*wv;
    *(float4*)(x + (size_t)dst*D_MODEL + t*4) = xv;
}

// ---------------- host-side helpers ------------------------------------------
struct WP2 { __half *h, *l; };

static void run_encoder(const float* Xin, float* Xout, int Ncur, int Tcur, int Bcur,
                        WP2 wq, const float* bq, WP2 wo, const float* bo,
                        WP2 w1, const float* b1, WP2 w2, const float* b2,
                        const float* g1, const float* be1, const float* g2, const float* be2,
                        float* qkv, float* attnb, float* t1, float* t2, float* ff,
                        __half* ah, __half* al) {
    split2(Xin, ah, al, (size_t)Ncur * D_MODEL);
    gemm_fp16x2<0><<<dim3(3*D_MODEL/128, Ncur/128), 256, GEMM_SMEM_BYTES>>>(
        ah, al, wq.h, wq.l, bq, qkv, Ncur, 3*D_MODEL, D_MODEL);
    attn_mma<<<dim3(Tcur/64, NHEAD, Bcur), 256, ATTN_SMEM2>>>(qkv, attnb, Tcur);
    split2(attnb, ah, al, (size_t)Ncur * D_MODEL);
    gemm_fp16x2<0><<<dim3(D_MODEL/128, Ncur/128), 256, GEMM_SMEM_BYTES>>>(
        ah, al, wo.h, wo.l, bo, t2, Ncur, D_MODEL, D_MODEL);
    addln_kernel<<<Ncur, 256>>>(Xin, t2, g1, be1, t1);
    split2(t1, ah, al, (size_t)Ncur * D_MODEL);
    gemm_fp16x2<1><<<dim3(DFF_/128, Ncur/128), 256, GEMM_SMEM_BYTES>>>(
        ah, al, w1.h, w1.l, b1, ff, Ncur, DFF_, D_MODEL);
    split2(ff, ah, al, (size_t)Ncur * DFF_);
    gemm_fp16x2<0><<<dim3(D_MODEL/128, Ncur/128), 256, GEMM_SMEM_BYTES>>>(
        ah, al, w2.h, w2.l, b2, t2, Ncur, D_MODEL, DFF_);
    addln_kernel<<<Ncur, 256>>>(t1, t2, g2, be2, Xout);
}

extern "C" void kernel_launch(void* const* d_in, const int* in_sizes, int n_in,
                              void* d_out, int out_size) {
    (void)in_sizes; (void)n_in; (void)out_size;
    const float* x    = (const float*)d_in[0];
    const float* Wqkv = (const float*)d_in[1];
    const float* bqkv = (const float*)d_in[2];
    const float* Wo   = (const float*)d_in[3];
    const float* bo   = (const float*)d_in[4];
    const float* W1   = (const float*)d_in[5];
    const float* b1   = (const float*)d_in[6];
    const float* W2   = (const float*)d_in[7];
    const float* b2   = (const float*)d_in[8];
    const float* g1   = (const float*)d_in[9];
    const float* be1  = (const float*)d_in[10];
    const float* g2   = (const float*)d_in[11];
    const float* be2  = (const float*)d_in[12];
    const float* rw   = (const float*)d_in[13];

    float *gx, *gxsel, *gqkv, *gattn, *gt1, *gt2, *gff, *grs, *gw; int* gsel;
    cudaGetSymbolAddress((void**)&gx,    g_x);
    cudaGetSymbolAddress((void**)&gxsel, g_xsel);
    cudaGetSymbolAddress((void**)&gqkv,  g_qkv);
    cudaGetSymbolAddress((void**)&gattn, g_attn);
    cudaGetSymbolAddress((void**)&gt1,   g_t1);
    cudaGetSymbolAddress((void**)&gt2,   g_t2);
    cudaGetSymbolAddress((void**)&gff,   g_ff);
    cudaGetSymbolAddress((void**)&grs,   g_rs);
    cudaGetSymbolAddress((void**)&gsel,  g_sel);
    cudaGetSymbolAddress((void**)&gw,    g_w);

    __half *wqkv2, *wo2, *w12, *w22, *act2;
    cudaGetSymbolAddress((void**)&wqkv2, g_wqkv2);
    cudaGetSymbolAddress((void**)&wo2,   g_wo2);
    cudaGetSymbolAddress((void**)&w12,   g_w12);
    cudaGetSymbolAddress((void**)&w22,   g_w22);
    cudaGetSymbolAddress((void**)&act2,  g_act2);

    cudaFuncSetAttribute(attn_mma, cudaFuncAttributeMaxDynamicSharedMemorySize, ATTN_SMEM2);
    cudaFuncSetAttribute(gemm_fp16x2<0>, cudaFuncAttributeMaxDynamicSharedMemorySize, GEMM_SMEM_BYTES);
    cudaFuncSetAttribute(gemm_fp16x2<1>, cudaFuncAttributeMaxDynamicSharedMemorySize, GEMM_SMEM_BYTES);

    split2(Wqkv, wqkv2, wqkv2 + WQKV_SZ, WQKV_SZ);
    split2(Wo,   wo2,   wo2   + WO_SZ,   WO_SZ);
    split2(W1,   w12,   w12   + W1_SZ,   W1_SZ);
    split2(W2,   w22,   w22   + W2_SZ,   W2_SZ);

    __half* ah = act2;
    __half* al = act2 + (size_t)ACT_SZ;

    const int n4 = NTOK*D_MODEL/4;
    copy_f4<<<(n4 + 255)/256, 256>>>((const float4*)x, (float4*)gx, n4);

    for (int L = 0; L < NLAYER; L++) {
        WP2 wq_l = { wqkv2 + (size_t)L*3*D_MODEL*D_MODEL,
                     wqkv2 + WQKV_SZ + (size_t)L*3*D_MODEL*D_MODEL };
        WP2 wo_l = { wo2 + (size_t)L*D_MODEL*D_MODEL,
                     wo2 + WO_SZ + (size_t)L*D_MODEL*D_MODEL };
        WP2 w1_l = { w12 + (size_t)L*DFF_*D_MODEL,
                     w12 + W1_SZ + (size_t)L*DFF_*D_MODEL };
        WP2 w2_l = { w22 + (size_t)L*D_MODEL*DFF_,
                     w22 + W2_SZ + (size_t)L*D_MODEL*DFF_ };
        const float* bq_l  = bqkv + (size_t)L*3*D_MODEL;
        const float* bo_l  = bo   + (size_t)L*D_MODEL;
        const float* b1_l  = b1   + (size_t)L*DFF_;
        const float* b2_l  = b2   + (size_t)L*D_MODEL;
        const float* g1_l  = g1   + (size_t)L*D_MODEL;
        const float* be1_l = be1  + (size_t)L*D_MODEL;
        const float* g2_l  = g2   + (size_t)L*D_MODEL;
        const float* be2_l = be2  + (size_t)L*D_MODEL;

        if (L & 1) {
            router_kernel<<<NTOK, 256>>>(gx, rw + (size_t)L*D_MODEL, grs);
            topk_kernel<<<BATCH, 1024>>>(grs, gsel, gw);
            gather_kernel<<<NSEL, 256>>>(gx, gsel, gxsel);
            run_encoder(gxsel, gattn, NSEL, KSEL, BATCH,
                        wq_l, bq_l, wo_l, bo_l, w1_l, b1_l, w2_l, b2_l,
                        g1_l, be1_l, g2_l, be2_l,
                        gqkv, gattn, gt1, gt2, gff, ah, al);
            scatter_kernel<<<NSEL, 256>>>(gx, gsel, gw, gxsel, gattn);
        } else {
            run_encoder(gx, gx, NTOK, SEQ, BATCH,
                        wq_l, bq_l, wo_l, bo_l, w1_l, b1_l, w2_l, b2_l,
                        g1_l, be1_l, g2_l, be2_l,
                        gqkv, gattn, gt1, gt2, gff, ah, al);
        }
    }

    copy_f4<<<(n4 + 255)/256, 256>>>((const float4*)gx, (float4*)d_out, n4);
}

// round 12
// speedup vs baseline: 2.3491x; 1.0937x over previous
#include <cuda_runtime.h>
#include <cuda_fp16.h>
#include <math.h>
#include <stdint.h>

#define D_MODEL 1024
#define NHEAD   16
#define HDIM    64
#define DFF_    4096
#define NLAYER  6
#define BATCH   4
#define SEQ     2048
#define NTOK    (BATCH*SEQ)      /* 8192 */
#define KSEL    1024
#define NSEL    (BATCH*KSEL)     /* 4096 */

#define WQKV_SZ (NLAYER*3*D_MODEL*D_MODEL)
#define WO_SZ   (NLAYER*D_MODEL*D_MODEL)
#define W1_SZ   (NLAYER*DFF_*D_MODEL)
#define W2_SZ   (NLAYER*D_MODEL*DFF_)
#define ACT_SZ  (NTOK*DFF_)

#define LOW_SCALE   2048.0f
#define LOW_UNSCALE (1.0f/2048.0f)

// ---------------- scratch (device globals; no allocations allowed) ----------
__device__ __align__(256) float g_x   [NTOK*D_MODEL];
__device__ __align__(256) float g_xsel[NSEL*D_MODEL];
__device__ __align__(256) float g_qkv [NTOK*3*D_MODEL];
__device__ __align__(256) float g_attn[NTOK*D_MODEL];
__device__ __align__(256) float g_t1  [NTOK*D_MODEL];
__device__ __align__(256) float g_t2  [NTOK*D_MODEL];
__device__ __align__(256) float g_ff  [NTOK*DFF_];
__device__ __align__(256) float g_rs  [BATCH*SEQ];
__device__ __align__(256) int   g_sel [BATCH*KSEL];
__device__ __align__(256) float g_w   [BATCH*KSEL];

// fp16 split-plane buffers (h, l*2048)
__device__ __align__(256) __half g_wqkv2[2][WQKV_SZ];
__device__ __align__(256) __half g_wo2  [2][WO_SZ];
__device__ __align__(256) __half g_w12  [2][W1_SZ];
__device__ __align__(256) __half g_w22  [2][W2_SZ];
__device__ __align__(256) __half g_act2 [2][ACT_SZ];

// ---------------- simple float4 copy ---------------------------------------
__global__ void copy_f4(const float4* __restrict__ src, float4* __restrict__ dst, int n4) {
    int i = blockIdx.x * blockDim.x + threadIdx.x;
    if (i < n4) dst[i] = src[i];
}

// ---------------- 2-way fp16 split (low plane scaled by 2048) ----------------
__global__ __launch_bounds__(256)
void split2_kernel(const float* __restrict__ in,
                   __half* __restrict__ ph, __half* __restrict__ pl, int n8) {
    int i = blockIdx.x * blockDim.x + threadIdx.x;
    if (i >= n8) return;
    const float4* p = (const float4*)in + (size_t)i * 2;
    float4 x0 = p[0], x1 = p[1];
    float v[8] = {x0.x, x0.y, x0.z, x0.w, x1.x, x1.y, x1.z, x1.w};
    __align__(16) __half hh[8], ll[8];
    #pragma unroll
    for (int k = 0; k < 8; k++) {
        __half h = __float2half_rn(v[k]);
        hh[k] = h;
        float r = (v[k] - __half2float(h)) * LOW_SCALE;
        ll[k] = __float2half_rn(r);
    }
    *(uint4*)(ph + (size_t)i * 8) = *(uint4*)hh;
    *(uint4*)(pl + (size_t)i * 8) = *(uint4*)ll;
}

static inline void split2(const float* in, __half* h, __half* l, size_t n) {
    int n8 = (int)(n / 8);
    split2_kernel<<<(n8 + 255) / 256, 256>>>(in, h, l, n8);
}

#define MMA_F16(d, a, b) \
    asm volatile("mma.sync.aligned.m16n8k16.row.col.f32.f16.f16.f32 " \
        "{%0,%1,%2,%3}, {%4,%5,%6,%7}, {%8,%9}, {%0,%1,%2,%3};" \
        : "+f"((d)[0]), "+f"((d)[1]), "+f"((d)[2]), "+f"((d)[3]) \
        : "r"((a)[0]), "r"((a)[1]), "r"((a)[2]), "r"((a)[3]), "r"((b)[0]), "r"((b)[1]))

#define LDSM4(r, addr) \
    asm volatile("ldmatrix.sync.aligned.m8n8.x4.shared.b16 {%0,%1,%2,%3}, [%4];" \
        : "=r"((r)[0]), "=r"((r)[1]), "=r"((r)[2]), "=r"((r)[3]) : "r"(addr))

__device__ __forceinline__ void cp_async16(uint32_t smem_addr, const void* gptr) {
    asm volatile("cp.async.ca.shared.global [%0], [%1], 16;" :: "r"(smem_addr), "l"(gptr));
}
#define CP_COMMIT() asm volatile("cp.async.commit_group;" ::: "memory")
#define CP_WAIT_1() asm volatile("cp.async.wait_group 1;" ::: "memory")
#define CP_WAIT_0() asm volatile("cp.async.wait_group 0;" ::: "memory")

// ---------------- fast exp on FMA pipe (no MUFU), rel err ~1.5e-6 ------------
__device__ __forceinline__ float fexp(float x) {
    x = fmaxf(x, -80.0f);
    float t  = x * 1.4426950408889634f;
    float fl = floorf(t);
    float f  = t - fl;
    float p  = 1.5252734e-5f;
    p = fmaf(p, f, 1.5403530e-4f);
    p = fmaf(p, f, 1.3333558e-3f);
    p = fmaf(p, f, 9.6181291e-3f);
    p = fmaf(p, f, 5.5504109e-2f);
    p = fmaf(p, f, 2.4022651e-1f);
    p = fmaf(p, f, 6.9314718e-1f);
    p = fmaf(p, f, 1.0f);
    int i = (int)fl;
    float sc = __int_as_float((i + 127) << 23);
    return p * sc;
}

// ---------------- fp16 2-plane split GEMM, cp.async + ldmatrix ---------------
#define BK2 32
#define SROW2 40
#define PLANE_HALVES (128*SROW2)
#define GEMM_SMEM_BYTES (2*2*2*PLANE_HALVES*2)

template<int RELU>
__global__ __launch_bounds__(256)
void gemm_fp16x2(const __half* __restrict__ Ah, const __half* __restrict__ Al,
                 const __half* __restrict__ Wh, const __half* __restrict__ Wl,
                 const float* __restrict__ bias, float* __restrict__ C,
                 int N, int M, int K) {
    extern __shared__ __half smh[];
    const int t    = threadIdx.x;
    const int lane = t & 31;
    const int warp = t >> 5;
    const int wm   = warp >> 2;
    const int wn   = warp & 3;
    const int rn   = blockIdx.y * 128;
    const int cm   = blockIdx.x * 128;
    const int g    = lane >> 2;
    const int tg   = lane & 3;

    // ldmatrix per-lane geometry
    const int la_row = (lane & 7) + ((lane >> 3) & 1) * 8;   // A: row in 16-row tile
    const int la_k   = (lane >> 4) * 8;                       // A: k-chunk
    const int lb_row = (lane & 7);                            // B: row in 8-row tile
    const int lb_jn  = (lane >> 4);                           // B: jn within pair
    const int lb_k   = ((lane >> 3) & 1) * 8;                 // B: k-chunk

    const __half* Ap[2] = { Ah, Al };
    const __half* Wp[2] = { Wh, Wl };

    const uint32_t smem_u32 = (uint32_t)__cvta_generic_to_shared(smh);
    const int c0r = t >> 2,        c0k = (t & 3) * 8;
    const int c1r = (t + 256) >> 2, c1k = ((t + 256) & 3) * 8;

    float acc1[4][4][4], acc2[4][4][4];
    #pragma unroll
    for (int i = 0; i < 4; i++)
        #pragma unroll
        for (int j = 0; j < 4; j++)
            #pragma unroll
            for (int r = 0; r < 4; r++) { acc1[i][j][r] = 0.f; acc2[i][j][r] = 0.f; }

    const int KT = K / BK2;

    auto issue_stage = [&](int buf, int k0) {
        #pragma unroll
        for (int p = 0; p < 2; p++) {
            uint32_t baseA = smem_u32 + (uint32_t)(((buf*2 + 0)*2 + p) * PLANE_HALVES) * 2;
            uint32_t baseW = smem_u32 + (uint32_t)(((buf*2 + 1)*2 + p) * PLANE_HALVES) * 2;
            cp_async16(baseA + (uint32_t)(c0r*SROW2 + c0k)*2, Ap[p] + (size_t)(rn + c0r)*K + k0 + c0k);
            cp_async16(baseA + (uint32_t)(c1r*SROW2 + c1k)*2, Ap[p] + (size_t)(rn + c1r)*K + k0 + c1k);
            cp_async16(baseW + (uint32_t)(c0r*SROW2 + c0k)*2, Wp[p] + (size_t)(cm + c0r)*K + k0 + c0k);
            cp_async16(baseW + (uint32_t)(c1r*SROW2 + c1k)*2, Wp[p] + (size_t)(cm + c1r)*K + k0 + c1k);
        }
        CP_COMMIT();
    };

    issue_stage(0, 0);

    for (int kt = 0; kt < KT; kt++) {
        const int cur = kt & 1;
        const bool more = (kt + 1) < KT;
        if (more) issue_stage(cur ^ 1, (kt + 1) * BK2);
        if (more) CP_WAIT_1(); else CP_WAIT_0();
        __syncthreads();

        const uint32_t uA0 = smem_u32 + (uint32_t)(((cur*2 + 0)*2 + 0) * PLANE_HALVES) * 2;
        const uint32_t uA1 = smem_u32 + (uint32_t)(((cur*2 + 0)*2 + 1) * PLANE_HALVES) * 2;
        const uint32_t uW0 = smem_u32 + (uint32_t)(((cur*2 + 1)*2 + 0) * PLANE_HALVES) * 2;
        const uint32_t uW1 = smem_u32 + (uint32_t)(((cur*2 + 1)*2 + 1) * PLANE_HALVES) * 2;

        #pragma unroll
        for (int ks0 = 0; ks0 < BK2; ks0 += 16) {
            // B fragments: 2 planes x 4 jn (loaded as 2 jn-pairs per ldmatrix.x4)
            uint32_t fbv[2][8];
            #pragma unroll
            for (int jp = 0; jp < 2; jp++) {
                uint32_t boff = (uint32_t)((wn*32 + jp*16 + lb_jn*8 + lb_row)*SROW2 + ks0 + lb_k) * 2;
                LDSM4(&fbv[0][jp*4], uW0 + boff);
                LDSM4(&fbv[1][jp*4], uW1 + boff);
            }
            #pragma unroll
            for (int im = 0; im < 4; im++) {
                const int r0 = wm * 64 + im * 16;
                uint32_t aoff = (uint32_t)((r0 + la_row)*SROW2 + ks0 + la_k) * 2;
                uint32_t fa[2][4];
                LDSM4(fa[0], uA0 + aoff);
                LDSM4(fa[1], uA1 + aoff);
                #pragma unroll
                for (int jn = 0; jn < 4; jn++) {
                    MMA_F16(acc1[im][jn], fa[0], &fbv[0][jn*2]);
                    MMA_F16(acc2[im][jn], fa[0], &fbv[1][jn*2]);
                    MMA_F16(acc2[im][jn], fa[1], &fbv[0][jn*2]);
                }
            }
        }
        __syncthreads();
    }

    #pragma unroll
    for (int im = 0; im < 4; im++) {
        #pragma unroll
        for (int jn = 0; jn < 4; jn++) {
            const int row = rn + wm * 64 + im * 16 + g;
            const int col = cm + wn * 32 + jn * 8 + tg * 2;
            float b0 = bias[col], b1 = bias[col + 1];
            float v0 = acc1[im][jn][0] + acc2[im][jn][0] * LOW_UNSCALE + b0;
            float v1 = acc1[im][jn][1] + acc2[im][jn][1] * LOW_UNSCALE + b1;
            float v2 = acc1[im][jn][2] + acc2[im][jn][2] * LOW_UNSCALE + b0;
            float v3 = acc1[im][jn][3] + acc2[im][jn][3] * LOW_UNSCALE + b1;
            if (RELU) {
                v0 = fmaxf(v0, 0.f); v1 = fmaxf(v1, 0.f);
                v2 = fmaxf(v2, 0.f); v3 = fmaxf(v3, 0.f);
            }
            *(float2*)&C[(size_t)row * M + col]       = make_float2(v0, v1);
            *(float2*)&C[(size_t)(row + 8) * M + col] = make_float2(v2, v3);
        }
    }
}

// ---------------- MMA flash attention (fp16 split, poly exp, ldmatrix) -------
#define QS 72
#define SS 68
#define ATTN_PLANE (64*QS)
#define ATTN_SMEM2 (8*ATTN_PLANE*2 + (64*SS + 3*64)*4)

__global__ __launch_bounds__(256)
void attn_mma(const float* __restrict__ qkv, float* __restrict__ out, int T) {
    extern __shared__ char sm_raw[];
    __half* Qh  = (__half*)sm_raw;
    __half* Ql  = Qh  + ATTN_PLANE;
    __half* Kh  = Ql  + ATTN_PLANE;
    __half* Kl  = Kh  + ATTN_PLANE;
    __half* Vth = Kl  + ATTN_PLANE;
    __half* Vtl = Vth + ATTN_PLANE;
    __half* Ph  = Vtl + ATTN_PLANE;
    __half* Pl  = Ph  + ATTN_PLANE;
    float*  Ssm = (float*)(Pl + ATTN_PLANE);
    float*  mrow = Ssm + 64*SS;
    float*  lrow = mrow + 64;
    float*  arow = lrow + 64;

    const int t    = threadIdx.x;
    const int lane = t & 31;
    const int warp = t >> 5;
    const int wm   = warp >> 2;
    const int wn   = warp & 3;
    const int g    = lane >> 2;
    const int tg   = lane & 3;
    const int qt = blockIdx.x, h = blockIdx.y, b = blockIdx.z;
    const int stride = 3 * D_MODEL;

    const int la_row = (lane & 7) + ((lane >> 3) & 1) * 8;
    const int la_k   = (lane >> 4) * 8;
    const int lb_row = (lane & 7);
    const int lb_jn  = (lane >> 4);
    const int lb_k   = ((lane >> 3) & 1) * 8;

    const uint32_t uQh = (uint32_t)__cvta_generic_to_shared(Qh);
    const uint32_t uQl = (uint32_t)__cvta_generic_to_shared(Ql);
    const uint32_t uKh = (uint32_t)__cvta_generic_to_shared(Kh);
    const uint32_t uKl = (uint32_t)__cvta_generic_to_shared(Kl);
    const uint32_t uVh = (uint32_t)__cvta_generic_to_shared(Vth);
    const uint32_t uVl = (uint32_t)__cvta_generic_to_shared(Vtl);
    const uint32_t uPh = (uint32_t)__cvta_generic_to_shared(Ph);
    const uint32_t uPl = (uint32_t)__cvta_generic_to_shared(Pl);

    // ---- load Q tile (64x64), convert+split ----
    {
        const int row = t >> 2, dg = (t & 3) * 16;
        const float* src = qkv + (size_t)(b*T + qt*64 + row) * stride + h*HDIM + dg;
        __align__(16) __half hh[16], ll[16];
        #pragma unroll
        for (int j4 = 0; j4 < 4; j4++) {
            float4 v = *(const float4*)(src + j4*4);
            float vv[4] = {v.x, v.y, v.z, v.w};
            #pragma unroll
            for (int e = 0; e < 4; e++) {
                __half hv = __float2half_rn(vv[e]);
                hh[j4*4+e] = hv;
                ll[j4*4+e] = __float2half_rn((vv[e] - __half2float(hv)) * LOW_SCALE);
            }
        }
        *(uint4*)&Qh[row*QS + dg]     = *(uint4*)&hh[0];
        *(uint4*)&Qh[row*QS + dg + 8] = *(uint4*)&hh[8];
        *(uint4*)&Ql[row*QS + dg]     = *(uint4*)&ll[0];
        *(uint4*)&Ql[row*QS + dg + 8] = *(uint4*)&ll[8];
    }
    if (t < 64) { mrow[t] = -1e30f; lrow[t] = 0.f; }

    float o1[2][2][4], o2[2][2][4];
    #pragma unroll
    for (int i = 0; i < 2; i++)
        #pragma unroll
        for (int j = 0; j < 2; j++)
            #pragma unroll
            for (int r = 0; r < 4; r++) { o1[i][j][r] = 0.f; o2[i][j][r] = 0.f; }

    const int nkt = T / 64;
    for (int kt2 = 0; kt2 < nkt; kt2++) {
        __syncthreads();
        // ---- load K tile and V tile (transposed), convert+split ----
        {
            const int row = t >> 2, dg = (t & 3) * 16;
            const float* ks = qkv + (size_t)(b*T + kt2*64 + row) * stride + D_MODEL + h*HDIM + dg;
            __align__(16) __half hh[16], ll[16];
            #pragma unroll
            for (int j4 = 0; j4 < 4; j4++) {
                float4 v = *(const float4*)(ks + j4*4);
                float vv[4] = {v.x, v.y, v.z, v.w};
                #pragma unroll
                for (int e = 0; e < 4; e++) {
                    __half hv = __float2half_rn(vv[e]);
                    hh[j4*4+e] = hv;
                    ll[j4*4+e] = __float2half_rn((vv[e] - __half2float(hv)) * LOW_SCALE);
                }
            }
            *(uint4*)&Kh[row*QS + dg]     = *(uint4*)&hh[0];
            *(uint4*)&Kh[row*QS + dg + 8] = *(uint4*)&hh[8];
            *(uint4*)&Kl[row*QS + dg]     = *(uint4*)&ll[0];
            *(uint4*)&Kl[row*QS + dg + 8] = *(uint4*)&ll[8];

            const float* vs = qkv + (size_t)(b*T + kt2*64 + row) * stride + 2*D_MODEL + h*HDIM + dg;
            #pragma unroll
            for (int j4 = 0; j4 < 4; j4++) {
                float4 v = *(const float4*)(vs + j4*4);
                float vv[4] = {v.x, v.y, v.z, v.w};
                #pragma unroll
                for (int e = 0; e < 4; e++) {
                    int d = dg + j4*4 + e;
                    __half hv = __float2half_rn(vv[e]);
                    Vth[d*QS + row] = hv;
                    Vtl[d*QS + row] = __float2half_rn((vv[e] - __half2float(hv)) * LOW_SCALE);
                }
            }
        }
        __syncthreads();

        // ---- S = Q K^T (split, 3 terms) ----
        float s1[2][2][4], s2[2][2][4];
        #pragma unroll
        for (int i = 0; i < 2; i++)
            #pragma unroll
            for (int j = 0; j < 2; j++)
                #pragma unroll
                for (int r = 0; r < 4; r++) { s1[i][j][r] = 0.f; s2[i][j][r] = 0.f; }

        #pragma unroll
        for (int ks0 = 0; ks0 < 64; ks0 += 16) {
            uint32_t fbv[2][4];
            {
                uint32_t boff = (uint32_t)((wn*16 + lb_jn*8 + lb_row)*QS + ks0 + lb_k) * 2;
                LDSM4(fbv[0], uKh + boff);
                LDSM4(fbv[1], uKl + boff);
            }
            #pragma unroll
            for (int im = 0; im < 2; im++) {
                const int r0 = wm * 32 + im * 16;
                uint32_t aoff = (uint32_t)((r0 + la_row)*QS + ks0 + la_k) * 2;
                uint32_t fa[2][4];
                LDSM4(fa[0], uQh + aoff);
                LDSM4(fa[1], uQl + aoff);
                #pragma unroll
                for (int jn = 0; jn < 2; jn++) {
                    MMA_F16(s1[im][jn], fa[0], &fbv[0][jn*2]);
                    MMA_F16(s2[im][jn], fa[0], &fbv[1][jn*2]);
                    MMA_F16(s2[im][jn], fa[1], &fbv[0][jn*2]);
                }
            }
        }
        #pragma unroll
        for (int im = 0; im < 2; im++) {
            #pragma unroll
            for (int jn = 0; jn < 2; jn++) {
                const int r = wm * 32 + im * 16 + g;
                const int c = wn * 16 + jn * 8 + tg * 2;
                float v0 = (s1[im][jn][0] + s2[im][jn][0]*LOW_UNSCALE) * 0.125f;
                float v1 = (s1[im][jn][1] + s2[im][jn][1]*LOW_UNSCALE) * 0.125f;
                float v2 = (s1[im][jn][2] + s2[im][jn][2]*LOW_UNSCALE) * 0.125f;
                float v3 = (s1[im][jn][3] + s2[im][jn][3]*LOW_UNSCALE) * 0.125f;
                *(float2*)&Ssm[r*SS + c]       = make_float2(v0, v1);
                *(float2*)&Ssm[(r + 8)*SS + c] = make_float2(v2, v3);
            }
        }
        __syncthreads();

        // ---- softmax: 4 threads per row, poly exp ----
        {
            const int row = t >> 2, q4 = (t & 3) * 16;
            float vals[16];
            float mloc = -1e30f;
            #pragma unroll
            for (int j = 0; j < 16; j++) {
                vals[j] = Ssm[row*SS + q4 + j];
                mloc = fmaxf(mloc, vals[j]);
            }
            mloc = fmaxf(mloc, __shfl_xor_sync(0xFFFFFFFF, mloc, 1));
            mloc = fmaxf(mloc, __shfl_xor_sync(0xFFFFFFFF, mloc, 2));
            float mo = mrow[row];
            float mn = fmaxf(mo, mloc);
            float sum = 0.f;
            #pragma unroll
            for (int j = 0; j < 16; j++) {
                float p = fexp(vals[j] - mn);
                sum += p;
                __half hv = __float2half_rn(p);
                Ph[row*QS + q4 + j] = hv;
                Pl[row*QS + q4 + j] = __float2half_rn((p - __half2float(hv)) * LOW_SCALE);
            }
            sum += __shfl_xor_sync(0xFFFFFFFF, sum, 1);
            sum += __shfl_xor_sync(0xFFFFFFFF, sum, 2);
            if ((t & 3) == 0) {
                float al = fexp(mo - mn);
                mrow[row] = mn;
                lrow[row] = lrow[row]*al + sum;
                arow[row] = al;
            }
        }
        __syncthreads();

        // ---- rescale O accumulators, then O += P V ----
        #pragma unroll
        for (int im = 0; im < 2; im++) {
            const int r0 = wm * 32 + im * 16;
            float a0 = arow[r0 + g], a1 = arow[r0 + g + 8];
            #pragma unroll
            for (int jn = 0; jn < 2; jn++) {
                o1[im][jn][0] *= a0; o1[im][jn][1] *= a0;
                o1[im][jn][2] *= a1; o1[im][jn][3] *= a1;
                o2[im][jn][0] *= a0; o2[im][jn][1] *= a0;
                o2[im][jn][2] *= a1; o2[im][jn][3] *= a1;
            }
        }
        #pragma unroll
        for (int ks0 = 0; ks0 < 64; ks0 += 16) {
            uint32_t fbv[2][4];
            {
                uint32_t boff = (uint32_t)((wn*16 + lb_jn*8 + lb_row)*QS + ks0 + lb_k) * 2;
                LDSM4(fbv[0], uVh + boff);
                LDSM4(fbv[1], uVl + boff);
            }
            #pragma unroll
            for (int im = 0; im < 2; im++) {
                const int r0 = wm * 32 + im * 16;
                uint32_t aoff = (uint32_t)((r0 + la_row)*QS + ks0 + la_k) * 2;
                uint32_t fa[2][4];
                LDSM4(fa[0], uPh + aoff);
                LDSM4(fa[1], uPl + aoff);
                #pragma unroll
                for (int jn = 0; jn < 2; jn++) {
                    MMA_F16(o1[im][jn], fa[0], &fbv[0][jn*2]);
                    MMA_F16(o2[im][jn], fa[0], &fbv[1][jn*2]);
                    MMA_F16(o2[im][jn], fa[1], &fbv[0][jn*2]);
                }
            }
        }
    }
    __syncthreads();

    // ---- final: normalize and store ----
    const int n0 = b*T + qt*64;
    #pragma unroll
    for (int im = 0; im < 2; im++) {
        #pragma unroll
        for (int jn = 0; jn < 2; jn++) {
            const int r = wm * 32 + im * 16 + g;
            const int c = wn * 16 + jn * 8 + tg * 2;
            float inv0 = 1.f / lrow[r];
            float inv1 = 1.f / lrow[r + 8];
            float v0 = (o1[im][jn][0] + o2[im][jn][0]*LOW_UNSCALE) * inv0;
            float v1 = (o1[im][jn][1] + o2[im][jn][1]*LOW_UNSCALE) * inv0;
            float v2 = (o1[im][jn][2] + o2[im][jn][2]*LOW_UNSCALE) * inv1;
            float v3 = (o1[im][jn][3] + o2[im][jn][3]*LOW_UNSCALE) * inv1;
            *(float2*)&out[(size_t)(n0 + r)*D_MODEL + h*HDIM + c]     = make_float2(v0, v1);
            *(float2*)&out[(size_t)(n0 + r + 8)*D_MODEL + h*HDIM + c] = make_float2(v2, v3);
        }
    }
}

// ---------------- residual add + LayerNorm ----------------------------------
__global__ __launch_bounds__(256)
void addln_kernel(const float* __restrict__ a, const float* __restrict__ r,
                  const float* __restrict__ g, const float* __restrict__ be,
                  float* __restrict__ out) {
    __shared__ float rsum[256], rsq[256];
    const int n = blockIdx.x, t = threadIdx.x;
    float4 av = *(const float4*)(a + (size_t)n*D_MODEL + t*4);
    float4 rv = *(const float4*)(r + (size_t)n*D_MODEL + t*4);
    float x0 = av.x + rv.x, x1 = av.y + rv.y, x2 = av.z + rv.z, x3 = av.w + rv.w;
    rsum[t] = x0 + x1 + x2 + x3;
    rsq [t] = x0*x0 + x1*x1 + x2*x2 + x3*x3;
    __syncthreads();
    for (int off = 128; off > 0; off >>= 1) {
        if (t < off) { rsum[t] += rsum[t+off]; rsq[t] += rsq[t+off]; }
        __syncthreads();
    }
    float mu  = rsum[0] * (1.f/1024.f);
    float var = rsq[0]  * (1.f/1024.f) - mu*mu;
    float rstd = rsqrtf(var + 1e-5f);
    float4 gv = *(const float4*)(g  + t*4);
    float4 bv = *(const float4*)(be + t*4);
    float4 o;
    o.x = (x0 - mu)*rstd*gv.x + bv.x;
    o.y = (x1 - mu)*rstd*gv.y + bv.y;
    o.z = (x2 - mu)*rstd*gv.z + bv.z;
    o.w = (x3 - mu)*rstd*gv.w + bv.w;
    *(float4*)(out + (size_t)n*D_MODEL + t*4) = o;
}

// ---------------- router score ----------------------------------------------
__global__ __launch_bounds__(256)
void router_kernel(const float* __restrict__ x, const float* __restrict__ rw,
                   float* __restrict__ out) {
    __shared__ float red[256];
    const int n = blockIdx.x, t = threadIdx.x;
    float4 xv = *(const float4*)(x + (size_t)n*D_MODEL + t*4);
    float4 wv = *(const float4*)(rw + t*4);
    red[t] = xv.x*wv.x + xv.y*wv.y + xv.z*wv.z + xv.w*wv.w;
    __syncthreads();
    for (int off = 128; off > 0; off >>= 1) {
        if (t < off) red[t] += red[t+off];
        __syncthreads();
    }
    if (t == 0) out[n] = red[0];
}

// ---------------- top-k via bitonic sort (desc value, asc index) ------------
__global__ __launch_bounds__(1024)
void topk_kernel(const float* __restrict__ scores, int* __restrict__ sel,
                 float* __restrict__ wout) {
    __shared__ float v[2048];
    __shared__ int  id[2048];
    const int b = blockIdx.x, t = threadIdx.x;
    v[t]        = scores[b*SEQ + t];        id[t]        = t;
    v[t + 1024] = scores[b*SEQ + t + 1024]; id[t + 1024] = t + 1024;
    __syncthreads();
    for (int k = 2; k <= 2048; k <<= 1) {
        for (int j = k >> 1; j > 0; j >>= 1) {
            #pragma unroll
            for (int s = 0; s < 2; s++) {
                int i = t + s*1024;
                int ixj = i ^ j;
                if (ixj > i) {
                    float vi = v[i], vj = v[ixj];
                    int   ii = id[i], ij = id[ixj];
                    bool before = (vi > vj) || (vi == vj && ii < ij);
                    bool up = ((i & k) == 0);
                    bool dosw = up ? (!before) : before;
                    if (dosw) { v[i] = vj; v[ixj] = vi; id[i] = ij; id[ixj] = ii; }
                }
            }
            __syncthreads();
        }
    }
    sel [b*KSEL + t] = id[t];
    wout[b*KSEL + t] = 1.f / (1.f + expf(-v[t]));
}

// ---------------- gather / scatter ------------------------------------------
__global__ __launch_bounds__(256)
void gather_kernel(const float* __restrict__ x, const int* __restrict__ sel,
                   float* __restrict__ xs) {
    const int row = blockIdx.x;
    const int b = row >> 10;
    const int src = b*SEQ + sel[row];
    const int t = threadIdx.x;
    float4 v = *(const float4*)(x + (size_t)src*D_MODEL + t*4);
    *(float4*)(xs + (size_t)row*D_MODEL + t*4) = v;
}

__global__ __launch_bounds__(256)
void scatter_kernel(float* __restrict__ x, const int* __restrict__ sel,
                    const float* __restrict__ w, const float* __restrict__ xs,
                    const float* __restrict__ proc) {
    const int row = blockIdx.x;
    const int b = row >> 10;
    const int dst = b*SEQ + sel[row];
    const float wv = w[row];
    const int t = threadIdx.x;
    float4 p  = *(const float4*)(proc + (size_t)row*D_MODEL + t*4);
    float4 s  = *(const float4*)(xs   + (size_t)row*D_MODEL + t*4);
    float4 xv = *(float4*)(x + (size_t)dst*D_MODEL + t*4);
    xv.x += (p.x - s.x)*wv;
    xv.y += (p.y - s.y)*wv;
    xv.z += (p.z - s.z)*wv;
    xv.w += (p.w - s.w)*wv;
    *(float4*)(x + (size_t)dst*D_MODEL + t*4) = xv;
}

// ---------------- host-side helpers ------------------------------------------
struct WP2 { __half *h, *l; };

static void run_encoder(const float* Xin, float* Xout, int Ncur, int Tcur, int Bcur,
                        WP2 wq, const float* bq, WP2 wo, const float* bo,
                        WP2 w1, const float* b1, WP2 w2, const float* b2,
                        const float* g1, const float* be1, const float* g2, const float* be2,
                        float* qkv, float* attnb, float* t1, float* t2, float* ff,
                        __half* ah, __half* al) {
    split2(Xin, ah, al, (size_t)Ncur * D_MODEL);
    gemm_fp16x2<0><<<dim3(3*D_MODEL/128, Ncur/128), 256, GEMM_SMEM_BYTES>>>(
        ah, al, wq.h, wq.l, bq, qkv, Ncur, 3*D_MODEL, D_MODEL);
    attn_mma<<<dim3(Tcur/64, NHEAD, Bcur), 256, ATTN_SMEM2>>>(qkv, attnb, Tcur);
    split2(attnb, ah, al, (size_t)Ncur * D_MODEL);
    gemm_fp16x2<0><<<dim3(D_MODEL/128, Ncur/128), 256, GEMM_SMEM_BYTES>>>(
        ah, al, wo.h, wo.l, bo, t2, Ncur, D_MODEL, D_MODEL);
    addln_kernel<<<Ncur, 256>>>(Xin, t2, g1, be1, t1);
    split2(t1, ah, al, (size_t)Ncur * D_MODEL);
    gemm_fp16x2<1><<<dim3(DFF_/128, Ncur/128), 256, GEMM_SMEM_BYTES>>>(
        ah, al, w1.h, w1.l, b1, ff, Ncur, DFF_, D_MODEL);
    split2(ff, ah, al, (size_t)Ncur * DFF_);
    gemm_fp16x2<0><<<dim3(D_MODEL/128, Ncur/128), 256, GEMM_SMEM_BYTES>>>(
        ah, al, w2.h, w2.l, b2, t2, Ncur, D_MODEL, DFF_);
    addln_kernel<<<Ncur, 256>>>(t1, t2, g2, be2, Xout);
}

extern "C" void kernel_launch(void* const* d_in, const int* in_sizes, int n_in,
                              void* d_out, int out_size) {
    (void)in_sizes; (void)n_in; (void)out_size;
    const float* x    = (const float*)d_in[0];
    const float* Wqkv = (const float*)d_in[1];
    const float* bqkv = (const float*)d_in[2];
    const float* Wo   = (const float*)d_in[3];
    const float* bo   = (const float*)d_in[4];
    const float* W1   = (const float*)d_in[5];
    const float* b1   = (const float*)d_in[6];
    const float* W2   = (const float*)d_in[7];
    const float* b2   = (const float*)d_in[8];
    const float* g1   = (const float*)d_in[9];
    const float* be1  = (const float*)d_in[10];
    const float* g2   = (const float*)d_in[11];
    const float* be2  = (const float*)d_in[12];
    const float* rw   = (const float*)d_in[13];

    float *gx, *gxsel, *gqkv, *gattn, *gt1, *gt2, *gff, *grs, *gw; int* gsel;
    cudaGetSymbolAddress((void**)&gx,    g_x);
    cudaGetSymbolAddress((void**)&gxsel, g_xsel);
    cudaGetSymbolAddress((void**)&gqkv,  g_qkv);
    cudaGetSymbolAddress((void**)&gattn, g_attn);
    cudaGetSymbolAddress((void**)&gt1,   g_t1);
    cudaGetSymbolAddress((void**)&gt2,   g_t2);
    cudaGetSymbolAddress((void**)&gff,   g_ff);
    cudaGetSymbolAddress((void**)&grs,   g_rs);
    cudaGetSymbolAddress((void**)&gsel,  g_sel);
    cudaGetSymbolAddress((void**)&gw,    g_w);

    __half *wqkv2, *wo2, *w12, *w22, *act2;
    cudaGetSymbolAddress((void**)&wqkv2, g_wqkv2);
    cudaGetSymbolAddress((void**)&wo2,   g_wo2);
    cudaGetSymbolAddress((void**)&w12,   g_w12);
    cudaGetSymbolAddress((void**)&w22,   g_w22);
    cudaGetSymbolAddress((void**)&act2,  g_act2);

    cudaFuncSetAttribute(attn_mma, cudaFuncAttributeMaxDynamicSharedMemorySize, ATTN_SMEM2);
    cudaFuncSetAttribute(gemm_fp16x2<0>, cudaFuncAttributeMaxDynamicSharedMemorySize, GEMM_SMEM_BYTES);
    cudaFuncSetAttribute(gemm_fp16x2<1>, cudaFuncAttributeMaxDynamicSharedMemorySize, GEMM_SMEM_BYTES);

    split2(Wqkv, wqkv2, wqkv2 + WQKV_SZ, WQKV_SZ);
    split2(Wo,   wo2,   wo2   + WO_SZ,   WO_SZ);
    split2(W1,   w12,   w12   + W1_SZ,   W1_SZ);
    split2(W2,   w22,   w22   + W2_SZ,   W2_SZ);

    __half* ah = act2;
    __half* al = act2 + (size_t)ACT_SZ;

    const int n4 = NTOK*D_MODEL/4;
    copy_f4<<<(n4 + 255)/256, 256>>>((const float4*)x, (float4*)gx, n4);

    for (int L = 0; L < NLAYER; L++) {
        WP2 wq_l = { wqkv2 + (size_t)L*3*D_MODEL*D_MODEL,
                     wqkv2 + WQKV_SZ + (size_t)L*3*D_MODEL*D_MODEL };
        WP2 wo_l = { wo2 + (size_t)L*D_MODEL*D_MODEL,
                     wo2 + WO_SZ + (size_t)L*D_MODEL*D_MODEL };
        WP2 w1_l = { w12 + (size_t)L*DFF_*D_MODEL,
                     w12 + W1_SZ + (size_t)L*DFF_*D_MODEL };
        WP2 w2_l = { w22 + (size_t)L*D_MODEL*DFF_,
                     w22 + W2_SZ + (size_t)L*D_MODEL*DFF_ };
        const float* bq_l  = bqkv + (size_t)L*3*D_MODEL;
        const float* bo_l  = bo   + (size_t)L*D_MODEL;
        const float* b1_l  = b1   + (size_t)L*DFF_;
        const float* b2_l  = b2   + (size_t)L*D_MODEL;
        const float* g1_l  = g1   + (size_t)L*D_MODEL;
        const float* be1_l = be1  + (size_t)L*D_MODEL;
        const float* g2_l  = g2   + (size_t)L*D_MODEL;
        const float* be2_l = be2  + (size_t)L*D_MODEL;

        if (L & 1) {
            router_kernel<<<NTOK, 256>>>(gx, rw + (size_t)L*D_MODEL, grs);
            topk_kernel<<<BATCH, 1024>>>(grs, gsel, gw);
            gather_kernel<<<NSEL, 256>>>(gx, gsel, gxsel);
            run_encoder(gxsel, gattn, NSEL, KSEL, BATCH,
                        wq_l, bq_l, wo_l, bo_l, w1_l, b1_l, w2_l, b2_l,
                        g1_l, be1_l, g2_l, be2_l,
                        gqkv, gattn, gt1, gt2, gff, ah, al);
            scatter_kernel<<<NSEL, 256>>>(gx, gsel, gw, gxsel, gattn);
        } else {
            run_encoder(gx, gx, NTOK, SEQ, BATCH,
                        wq_l, bq_l, wo_l, bo_l, w1_l, b1_l, w2_l, b2_l,
                        g1_l, be1_l, g2_l, be2_l,
                        gqkv, gattn, gt1, gt2, gff, ah, al);
        }
    }

    copy_f4<<<(n4 + 255)/256, 256>>>((const float4*)gx, (float4*)d_out, n4);
}

// round 13
// speedup vs baseline: 2.4431x; 1.0401x over previous
#include <cuda_runtime.h>
#include <cuda_fp16.h>
#include <math.h>
#include <stdint.h>

#define D_MODEL 1024
#define NHEAD   16
#define HDIM    64
#define DFF_    4096
#define NLAYER  6
#define BATCH   4
#define SEQ     2048
#define NTOK    (BATCH*SEQ)      /* 8192 */
#define KSEL    1024
#define NSEL    (BATCH*KSEL)     /* 4096 */

#define WQKV_SZ (NLAYER*3*D_MODEL*D_MODEL)
#define WO_SZ   (NLAYER*D_MODEL*D_MODEL)
#define W1_SZ   (NLAYER*DFF_*D_MODEL)
#define W2_SZ   (NLAYER*D_MODEL*DFF_)
#define ACT_SZ  (NTOK*DFF_)
#define QKV_SZ  (NTOK*3*D_MODEL)
#define VT_SZ   (NTOK*D_MODEL)

#define LOW_SCALE   2048.0f
#define LOW_UNSCALE (1.0f/2048.0f)

// ---------------- scratch (device globals; no allocations allowed) ----------
__device__ __align__(256) float g_x   [NTOK*D_MODEL];
__device__ __align__(256) float g_xsel[NSEL*D_MODEL];
__device__ __align__(256) float g_qkv [NTOK*3*D_MODEL];
__device__ __align__(256) float g_attn[NTOK*D_MODEL];
__device__ __align__(256) float g_t1  [NTOK*D_MODEL];
__device__ __align__(256) float g_t2  [NTOK*D_MODEL];
__device__ __align__(256) float g_ff  [NTOK*DFF_];
__device__ __align__(256) float g_rs  [BATCH*SEQ];
__device__ __align__(256) int   g_sel [BATCH*KSEL];
__device__ __align__(256) float g_w   [BATCH*KSEL];

// fp16 split-plane buffers (h, l*2048)
__device__ __align__(256) __half g_wqkv2[2][WQKV_SZ];
__device__ __align__(256) __half g_wo2  [2][WO_SZ];
__device__ __align__(256) __half g_w12  [2][W1_SZ];
__device__ __align__(256) __half g_w22  [2][W2_SZ];
__device__ __align__(256) __half g_act2 [2][ACT_SZ];
__device__ __align__(256) __half g_qkv2 [2][QKV_SZ];
__device__ __align__(256) __half g_vt2  [2][VT_SZ];

// ---------------- simple float4 copy ---------------------------------------
__global__ void copy_f4(const float4* __restrict__ src, float4* __restrict__ dst, int n4) {
    int i = blockIdx.x * blockDim.x + threadIdx.x;
    if (i < n4) dst[i] = src[i];
}

// ---------------- 2-way fp16 split (low plane scaled by 2048) ----------------
__global__ __launch_bounds__(256)
void split2_kernel(const float* __restrict__ in,
                   __half* __restrict__ ph, __half* __restrict__ pl, int n8) {
    int i = blockIdx.x * blockDim.x + threadIdx.x;
    if (i >= n8) return;
    const float4* p = (const float4*)in + (size_t)i * 2;
    float4 x0 = p[0], x1 = p[1];
    float v[8] = {x0.x, x0.y, x0.z, x0.w, x1.x, x1.y, x1.z, x1.w};
    __align__(16) __half hh[8], ll[8];
    #pragma unroll
    for (int k = 0; k < 8; k++) {
        __half h = __float2half_rn(v[k]);
        hh[k] = h;
        float r = (v[k] - __half2float(h)) * LOW_SCALE;
        ll[k] = __float2half_rn(r);
    }
    *(uint4*)(ph + (size_t)i * 8) = *(uint4*)hh;
    *(uint4*)(pl + (size_t)i * 8) = *(uint4*)ll;
}

static inline void split2(const float* in, __half* h, __half* l, size_t n) {
    int n8 = (int)(n / 8);
    split2_kernel<<<(n8 + 255) / 256, 256>>>(in, h, l, n8);
}

// ---------------- V transpose: qkv fp16 planes -> VT [b*h][d][T] -------------
__global__ __launch_bounds__(256)
void vtrans_kernel(const __half* __restrict__ qh, const __half* __restrict__ ql,
                   __half* __restrict__ vth, __half* __restrict__ vtl, int T) {
    __shared__ __half sh[64][72], sl[64][72];
    const int t0 = blockIdx.x * 64, h = blockIdx.y, b = blockIdx.z;
    const int tid = threadIdx.x;
    const int row = tid >> 2;            // token within tile / d-row on write
    const int dg  = (tid & 3) * 16;      // 16-half chunk

    const size_t src_off = (size_t)(b*T + t0 + row) * 3*D_MODEL + 2*D_MODEL + h*HDIM + dg;
    uint4 h0 = *(const uint4*)(qh + src_off);
    uint4 h1 = *(const uint4*)(qh + src_off + 8);
    uint4 l0 = *(const uint4*)(ql + src_off);
    uint4 l1 = *(const uint4*)(ql + src_off + 8);
    __align__(16) __half hb[16], lb[16];
    *(uint4*)&hb[0] = h0; *(uint4*)&hb[8] = h1;
    *(uint4*)&lb[0] = l0; *(uint4*)&lb[8] = l1;
    #pragma unroll
    for (int e = 0; e < 16; e++) {
        sh[dg + e][row] = hb[e];
        sl[dg + e][row] = lb[e];
    }
    __syncthreads();
    // write: row = d, chunk along t
    const size_t dst_off = ((size_t)((b*NHEAD + h)*HDIM + row)) * T + t0 + dg;
    *(uint4*)(vth + dst_off)     = *(uint4*)&sh[row][dg];
    *(uint4*)(vth + dst_off + 8) = *(uint4*)&sh[row][dg + 8];
    *(uint4*)(vtl + dst_off)     = *(uint4*)&sl[row][dg];
    *(uint4*)(vtl + dst_off + 8) = *(uint4*)&sl[row][dg + 8];
}

#define MMA_F16(d, a, b) \
    asm volatile("mma.sync.aligned.m16n8k16.row.col.f32.f16.f16.f32 " \
        "{%0,%1,%2,%3}, {%4,%5,%6,%7}, {%8,%9}, {%0,%1,%2,%3};" \
        : "+f"((d)[0]), "+f"((d)[1]), "+f"((d)[2]), "+f"((d)[3]) \
        : "r"((a)[0]), "r"((a)[1]), "r"((a)[2]), "r"((a)[3]), "r"((b)[0]), "r"((b)[1]))

#define LDSM4(r, addr) \
    asm volatile("ldmatrix.sync.aligned.m8n8.x4.shared.b16 {%0,%1,%2,%3}, [%4];" \
        : "=r"((r)[0]), "=r"((r)[1]), "=r"((r)[2]), "=r"((r)[3]) : "r"(addr))

__device__ __forceinline__ void cp_async16(uint32_t smem_addr, const void* gptr) {
    asm volatile("cp.async.ca.shared.global [%0], [%1], 16;" :: "r"(smem_addr), "l"(gptr));
}
#define CP_COMMIT() asm volatile("cp.async.commit_group;" ::: "memory")
#define CP_WAIT_1() asm volatile("cp.async.wait_group 1;" ::: "memory")
#define CP_WAIT_0() asm volatile("cp.async.wait_group 0;" ::: "memory")

// ---------------- fast exp on FMA pipe (no MUFU), rel err ~1.5e-6 ------------
__device__ __forceinline__ float fexp(float x) {
    x = fmaxf(x, -80.0f);
    float t  = x * 1.4426950408889634f;
    float fl = floorf(t);
    float f  = t - fl;
    float p  = 1.5252734e-5f;
    p = fmaf(p, f, 1.5403530e-4f);
    p = fmaf(p, f, 1.3333558e-3f);
    p = fmaf(p, f, 9.6181291e-3f);
    p = fmaf(p, f, 5.5504109e-2f);
    p = fmaf(p, f, 2.4022651e-1f);
    p = fmaf(p, f, 6.9314718e-1f);
    p = fmaf(p, f, 1.0f);
    int i = (int)fl;
    float sc = __int_as_float((i + 127) << 23);
    return p * sc;
}

// ---------------- fp16 2-plane split GEMM, cp.async + ldmatrix ---------------
#define BK2 32
#define SROW2 40
#define PLANE_HALVES (128*SROW2)
#define GEMM_SMEM_BYTES (2*2*2*PLANE_HALVES*2)

template<int RELU>
__global__ __launch_bounds__(256)
void gemm_fp16x2(const __half* __restrict__ Ah, const __half* __restrict__ Al,
                 const __half* __restrict__ Wh, const __half* __restrict__ Wl,
                 const float* __restrict__ bias, float* __restrict__ C,
                 int N, int M, int K) {
    extern __shared__ __half smh[];
    const int t    = threadIdx.x;
    const int lane = t & 31;
    const int warp = t >> 5;
    const int wm   = warp >> 2;
    const int wn   = warp & 3;
    const int rn   = blockIdx.y * 128;
    const int cm   = blockIdx.x * 128;
    const int g    = lane >> 2;
    const int tg   = lane & 3;

    const int la_row = (lane & 7) + ((lane >> 3) & 1) * 8;
    const int la_k   = (lane >> 4) * 8;
    const int lb_row = (lane & 7);
    const int lb_jn  = (lane >> 4);
    const int lb_k   = ((lane >> 3) & 1) * 8;

    const __half* Ap[2] = { Ah, Al };
    const __half* Wp[2] = { Wh, Wl };

    const uint32_t smem_u32 = (uint32_t)__cvta_generic_to_shared(smh);
    const int c0r = t >> 2,        c0k = (t & 3) * 8;
    const int c1r = (t + 256) >> 2, c1k = ((t + 256) & 3) * 8;

    float acc1[4][4][4], acc2[4][4][4];
    #pragma unroll
    for (int i = 0; i < 4; i++)
        #pragma unroll
        for (int j = 0; j < 4; j++)
            #pragma unroll
            for (int r = 0; r < 4; r++) { acc1[i][j][r] = 0.f; acc2[i][j][r] = 0.f; }

    const int KT = K / BK2;

    auto issue_stage = [&](int buf, int k0) {
        #pragma unroll
        for (int p = 0; p < 2; p++) {
            uint32_t baseA = smem_u32 + (uint32_t)(((buf*2 + 0)*2 + p) * PLANE_HALVES) * 2;
            uint32_t baseW = smem_u32 + (uint32_t)(((buf*2 + 1)*2 + p) * PLANE_HALVES) * 2;
            cp_async16(baseA + (uint32_t)(c0r*SROW2 + c0k)*2, Ap[p] + (size_t)(rn + c0r)*K + k0 + c0k);
            cp_async16(baseA + (uint32_t)(c1r*SROW2 + c1k)*2, Ap[p] + (size_t)(rn + c1r)*K + k0 + c1k);
            cp_async16(baseW + (uint32_t)(c0r*SROW2 + c0k)*2, Wp[p] + (size_t)(cm + c0r)*K + k0 + c0k);
            cp_async16(baseW + (uint32_t)(c1r*SROW2 + c1k)*2, Wp[p] + (size_t)(cm + c1r)*K + k0 + c1k);
        }
        CP_COMMIT();
    };

    issue_stage(0, 0);

    for (int kt = 0; kt < KT; kt++) {
        const int cur = kt & 1;
        const bool more = (kt + 1) < KT;
        if (more) issue_stage(cur ^ 1, (kt + 1) * BK2);
        if (more) CP_WAIT_1(); else CP_WAIT_0();
        __syncthreads();

        const uint32_t uA0 = smem_u32 + (uint32_t)(((cur*2 + 0)*2 + 0) * PLANE_HALVES) * 2;
        const uint32_t uA1 = smem_u32 + (uint32_t)(((cur*2 + 0)*2 + 1) * PLANE_HALVES) * 2;
        const uint32_t uW0 = smem_u32 + (uint32_t)(((cur*2 + 1)*2 + 0) * PLANE_HALVES) * 2;
        const uint32_t uW1 = smem_u32 + (uint32_t)(((cur*2 + 1)*2 + 1) * PLANE_HALVES) * 2;

        #pragma unroll
        for (int ks0 = 0; ks0 < BK2; ks0 += 16) {
            uint32_t fbv[2][8];
            #pragma unroll
            for (int jp = 0; jp < 2; jp++) {
                uint32_t boff = (uint32_t)((wn*32 + jp*16 + lb_jn*8 + lb_row)*SROW2 + ks0 + lb_k) * 2;
                LDSM4(&fbv[0][jp*4], uW0 + boff);
                LDSM4(&fbv[1][jp*4], uW1 + boff);
            }
            #pragma unroll
            for (int im = 0; im < 4; im++) {
                const int r0 = wm * 64 + im * 16;
                uint32_t aoff = (uint32_t)((r0 + la_row)*SROW2 + ks0 + la_k) * 2;
                uint32_t fa[2][4];
                LDSM4(fa[0], uA0 + aoff);
                LDSM4(fa[1], uA1 + aoff);
                #pragma unroll
                for (int jn = 0; jn < 4; jn++) {
                    MMA_F16(acc1[im][jn], fa[0], &fbv[0][jn*2]);
                    MMA_F16(acc2[im][jn], fa[0], &fbv[1][jn*2]);
                    MMA_F16(acc2[im][jn], fa[1], &fbv[0][jn*2]);
                }
            }
        }
        __syncthreads();
    }

    #pragma unroll
    for (int im = 0; im < 4; im++) {
        #pragma unroll
        for (int jn = 0; jn < 4; jn++) {
            const int row = rn + wm * 64 + im * 16 + g;
            const int col = cm + wn * 32 + jn * 8 + tg * 2;
            float b0 = bias[col], b1 = bias[col + 1];
            float v0 = acc1[im][jn][0] + acc2[im][jn][0] * LOW_UNSCALE + b0;
            float v1 = acc1[im][jn][1] + acc2[im][jn][1] * LOW_UNSCALE + b1;
            float v2 = acc1[im][jn][2] + acc2[im][jn][2] * LOW_UNSCALE + b0;
            float v3 = acc1[im][jn][3] + acc2[im][jn][3] * LOW_UNSCALE + b1;
            if (RELU) {
                v0 = fmaxf(v0, 0.f); v1 = fmaxf(v1, 0.f);
                v2 = fmaxf(v2, 0.f); v3 = fmaxf(v3, 0.f);
            }
            *(float2*)&C[(size_t)row * M + col]       = make_float2(v0, v1);
            *(float2*)&C[(size_t)(row + 8) * M + col] = make_float2(v2, v3);
        }
    }
}

// ---------------- MMA flash attention: pre-split inputs, cp.async pipeline ---
#define QS 72
#define SS 68
#define APL (64*QS)     /* 4608 halves per plane-tile */
#define ATTN_SMEM3 (12*APL*2 + (64*SS + 3*64)*4)

__global__ __launch_bounds__(256)
void attn_mma(const __half* __restrict__ qkvh, const __half* __restrict__ qkvl,
              const __half* __restrict__ vth,  const __half* __restrict__ vtl,
              float* __restrict__ out, int T) {
    extern __shared__ char sm_raw[];
    __half* smh = (__half*)sm_raw;
    // layout (halves): Q[2] | K[2buf][2pl] | V[2buf][2pl] | P[2]
    __half* Ph = smh + 10*APL;
    __half* Pl = smh + 11*APL;
    float*  Ssm  = (float*)(smh + 12*APL);
    float*  mrow = Ssm + 64*SS;
    float*  lrow = mrow + 64;
    float*  arow = lrow + 64;

    const int t    = threadIdx.x;
    const int lane = t & 31;
    const int warp = t >> 5;
    const int wm   = warp >> 2;
    const int wn   = warp & 3;
    const int g    = lane >> 2;
    const int tg   = lane & 3;
    const int qt = blockIdx.x, h = blockIdx.y, b = blockIdx.z;
    const int stride3 = 3 * D_MODEL;

    const int la_row = (lane & 7) + ((lane >> 3) & 1) * 8;
    const int la_k   = (lane >> 4) * 8;
    const int lb_row = (lane & 7);
    const int lb_jn  = (lane >> 4);
    const int lb_k   = ((lane >> 3) & 1) * 8;

    const uint32_t uS = (uint32_t)__cvta_generic_to_shared(smh);
    const uint32_t uQ = uS;
    const uint32_t uK = uS + 2*APL*2;
    const uint32_t uV = uS + 6*APL*2;
    const uint32_t uP = uS + 10*APL*2;

    const __half* qp[2] = { qkvh, qkvl };
    const __half* vp[2] = { vth,  vtl  };

    // prologue: Q tile (4 chunks/thread) + K/V stage 0 (one group)
    {
        #pragma unroll
        for (int i = 0; i < 4; i++) {
            int c = t + 256*i;
            int plane = c >> 9, rem = c & 511, row = rem >> 3, ch = (rem & 7) * 8;
            const __half* qg = qp[plane] + (size_t)(b*T + qt*64 + row)*stride3 + h*HDIM + ch;
            cp_async16(uQ + (uint32_t)(plane*APL + row*QS + ch)*2, qg);
        }
    }
    auto issue_kv = [&](int buf, int kt) {
        #pragma unroll
        for (int i = 0; i < 4; i++) {
            int c = t + 256*i;
            int plane = c >> 9, rem = c & 511, row = rem >> 3, ch = (rem & 7) * 8;
            const __half* kg = qp[plane] + (size_t)(b*T + kt*64 + row)*stride3 + D_MODEL + h*HDIM + ch;
            cp_async16(uK + (uint32_t)((buf*2 + plane)*APL + row*QS + ch)*2, kg);
            const __half* vg = vp[plane] + ((size_t)((b*NHEAD + h)*HDIM + row))*T + kt*64 + ch;
            cp_async16(uV + (uint32_t)((buf*2 + plane)*APL + row*QS + ch)*2, vg);
        }
        CP_COMMIT();
    };
    issue_kv(0, 0);

    if (t < 64) { mrow[t] = -1e30f; lrow[t] = 0.f; }

    float o1[2][2][4], o2[2][2][4];
    #pragma unroll
    for (int i = 0; i < 2; i++)
        #pragma unroll
        for (int j = 0; j < 2; j++)
            #pragma unroll
            for (int r = 0; r < 4; r++) { o1[i][j][r] = 0.f; o2[i][j][r] = 0.f; }

    const int nkt = T / 64;
    for (int kt2 = 0; kt2 < nkt; kt2++) {
        const int cur = kt2 & 1;
        const bool more = (kt2 + 1) < nkt;
        __syncthreads();                       // prior buffers fully consumed
        if (more) issue_kv(cur ^ 1, kt2 + 1);
        if (more) CP_WAIT_1(); else CP_WAIT_0();
        __syncthreads();

        const uint32_t uK0 = uK + (uint32_t)(cur*2 + 0)*APL*2;
        const uint32_t uK1 = uK + (uint32_t)(cur*2 + 1)*APL*2;
        const uint32_t uV0 = uV + (uint32_t)(cur*2 + 0)*APL*2;
        const uint32_t uV1 = uV + (uint32_t)(cur*2 + 1)*APL*2;

        // ---- S = Q K^T (split, 3 terms) ----
        float s1[2][2][4], s2[2][2][4];
        #pragma unroll
        for (int i = 0; i < 2; i++)
            #pragma unroll
            for (int j = 0; j < 2; j++)
                #pragma unroll
                for (int r = 0; r < 4; r++) { s1[i][j][r] = 0.f; s2[i][j][r] = 0.f; }

        #pragma unroll
        for (int ks0 = 0; ks0 < 64; ks0 += 16) {
            uint32_t fbv[2][4];
            {
                uint32_t boff = (uint32_t)((wn*16 + lb_jn*8 + lb_row)*QS + ks0 + lb_k) * 2;
                LDSM4(fbv[0], uK0 + boff);
                LDSM4(fbv[1], uK1 + boff);
            }
            #pragma unroll
            for (int im = 0; im < 2; im++) {
                const int r0 = wm * 32 + im * 16;
                uint32_t aoff = (uint32_t)((r0 + la_row)*QS + ks0 + la_k) * 2;
                uint32_t fa[2][4];
                LDSM4(fa[0], uQ + aoff);
                LDSM4(fa[1], uQ + (uint32_t)APL*2 + aoff);
                #pragma unroll
                for (int jn = 0; jn < 2; jn++) {
                    MMA_F16(s1[im][jn], fa[0], &fbv[0][jn*2]);
                    MMA_F16(s2[im][jn], fa[0], &fbv[1][jn*2]);
                    MMA_F16(s2[im][jn], fa[1], &fbv[0][jn*2]);
                }
            }
        }
        #pragma unroll
        for (int im = 0; im < 2; im++) {
            #pragma unroll
            for (int jn = 0; jn < 2; jn++) {
                const int r = wm * 32 + im * 16 + g;
                const int c = wn * 16 + jn * 8 + tg * 2;
                float v0 = (s1[im][jn][0] + s2[im][jn][0]*LOW_UNSCALE) * 0.125f;
                float v1 = (s1[im][jn][1] + s2[im][jn][1]*LOW_UNSCALE) * 0.125f;
                float v2 = (s1[im][jn][2] + s2[im][jn][2]*LOW_UNSCALE) * 0.125f;
                float v3 = (s1[im][jn][3] + s2[im][jn][3]*LOW_UNSCALE) * 0.125f;
                *(float2*)&Ssm[r*SS + c]       = make_float2(v0, v1);
                *(float2*)&Ssm[(r + 8)*SS + c] = make_float2(v2, v3);
            }
        }
        __syncthreads();

        // ---- softmax: 4 threads per row, poly exp ----
        {
            const int row = t >> 2, q4 = (t & 3) * 16;
            float vals[16];
            float mloc = -1e30f;
            #pragma unroll
            for (int j = 0; j < 16; j++) {
                vals[j] = Ssm[row*SS + q4 + j];
                mloc = fmaxf(mloc, vals[j]);
            }
            mloc = fmaxf(mloc, __shfl_xor_sync(0xFFFFFFFF, mloc, 1));
            mloc = fmaxf(mloc, __shfl_xor_sync(0xFFFFFFFF, mloc, 2));
            float mo = mrow[row];
            float mn = fmaxf(mo, mloc);
            float sum = 0.f;
            #pragma unroll
            for (int j = 0; j < 16; j++) {
                float p = fexp(vals[j] - mn);
                sum += p;
                __half hv = __float2half_rn(p);
                Ph[row*QS + q4 + j] = hv;
                Pl[row*QS + q4 + j] = __float2half_rn((p - __half2float(hv)) * LOW_SCALE);
            }
            sum += __shfl_xor_sync(0xFFFFFFFF, sum, 1);
            sum += __shfl_xor_sync(0xFFFFFFFF, sum, 2);
            if ((t & 3) == 0) {
                float al = fexp(mo - mn);
                mrow[row] = mn;
                lrow[row] = lrow[row]*al + sum;
                arow[row] = al;
            }
        }
        __syncthreads();

        // ---- rescale O accumulators, then O += P V ----
        #pragma unroll
        for (int im = 0; im < 2; im++) {
            const int r0 = wm * 32 + im * 16;
            float a0 = arow[r0 + g], a1 = arow[r0 + g + 8];
            #pragma unroll
            for (int jn = 0; jn < 2; jn++) {
                o1[im][jn][0] *= a0; o1[im][jn][1] *= a0;
                o1[im][jn][2] *= a1; o1[im][jn][3] *= a1;
                o2[im][jn][0] *= a0; o2[im][jn][1] *= a0;
                o2[im][jn][2] *= a1; o2[im][jn][3] *= a1;
            }
        }
        #pragma unroll
        for (int ks0 = 0; ks0 < 64; ks0 += 16) {
            uint32_t fbv[2][4];
            {
                uint32_t boff = (uint32_t)((wn*16 + lb_jn*8 + lb_row)*QS + ks0 + lb_k) * 2;
                LDSM4(fbv[0], uV0 + boff);
                LDSM4(fbv[1], uV1 + boff);
            }
            #pragma unroll
            for (int im = 0; im < 2; im++) {
                const int r0 = wm * 32 + im * 16;
                uint32_t aoff = (uint32_t)((r0 + la_row)*QS + ks0 + la_k) * 2;
                uint32_t fa[2][4];
                LDSM4(fa[0], uP + aoff);
                LDSM4(fa[1], uP + (uint32_t)APL*2 + aoff);
                #pragma unroll
                for (int jn = 0; jn < 2; jn++) {
                    MMA_F16(o1[im][jn], fa[0], &fbv[0][jn*2]);
                    MMA_F16(o2[im][jn], fa[0], &fbv[1][jn*2]);
                    MMA_F16(o2[im][jn], fa[1], &fbv[0][jn*2]);
                }
            }
        }
    }
    __syncthreads();

    // ---- final: normalize and store ----
    const int n0 = b*T + qt*64;
    #pragma unroll
    for (int im = 0; im < 2; im++) {
        #pragma unroll
        for (int jn = 0; jn < 2; jn++) {
            const int r = wm * 32 + im * 16 + g;
            const int c = wn * 16 + jn * 8 + tg * 2;
            float inv0 = 1.f / lrow[r];
            float inv1 = 1.f / lrow[r + 8];
            float v0 = (o1[im][jn][0] + o2[im][jn][0]*LOW_UNSCALE) * inv0;
            float v1 = (o1[im][jn][1] + o2[im][jn][1]*LOW_UNSCALE) * inv0;
            float v2 = (o1[im][jn][2] + o2[im][jn][2]*LOW_UNSCALE) * inv1;
            float v3 = (o1[im][jn][3] + o2[im][jn][3]*LOW_UNSCALE) * inv1;
            *(float2*)&out[(size_t)(n0 + r)*D_MODEL + h*HDIM + c]     = make_float2(v0, v1);
            *(float2*)&out[(size_t)(n0 + r + 8)*D_MODEL + h*HDIM + c] = make_float2(v2, v3);
        }
    }
}

// ---------------- residual add + LayerNorm ----------------------------------
__global__ __launch_bounds__(256)
void addln_kernel(const float* __restrict__ a, const float* __restrict__ r,
                  const float* __restrict__ g, const float* __restrict__ be,
                  float* __restrict__ out) {
    __shared__ float rsum[256], rsq[256];
    const int n = blockIdx.x, t = threadIdx.x;
    float4 av = *(const float4*)(a + (size_t)n*D_MODEL + t*4);
    float4 rv = *(const float4*)(r + (size_t)n*D_MODEL + t*4);
    float x0 = av.x + rv.x, x1 = av.y + rv.y, x2 = av.z + rv.z, x3 = av.w + rv.w;
    rsum[t] = x0 + x1 + x2 + x3;
    rsq [t] = x0*x0 + x1*x1 + x2*x2 + x3*x3;
    __syncthreads();
    for (int off = 128; off > 0; off >>= 1) {
        if (t < off) { rsum[t] += rsum[t+off]; rsq[t] += rsq[t+off]; }
        __syncthreads();
    }
    float mu  = rsum[0] * (1.f/1024.f);
    float var = rsq[0]  * (1.f/1024.f) - mu*mu;
    float rstd = rsqrtf(var + 1e-5f);
    float4 gv = *(const float4*)(g  + t*4);
    float4 bv = *(const float4*)(be + t*4);
    float4 o;
    o.x = (x0 - mu)*rstd*gv.x + bv.x;
    o.y = (x1 - mu)*rstd*gv.y + bv.y;
    o.z = (x2 - mu)*rstd*gv.z + bv.z;
    o.w = (x3 - mu)*rstd*gv.w + bv.w;
    *(float4*)(out + (size_t)n*D_MODEL + t*4) = o;
}

// ---------------- router score ----------------------------------------------
__global__ __launch_bounds__(256)
void router_kernel(const float* __restrict__ x, const float* __restrict__ rw,
                   float* __restrict__ out) {
    __shared__ float red[256];
    const int n = blockIdx.x, t = threadIdx.x;
    float4 xv = *(const float4*)(x + (size_t)n*D_MODEL + t*4);
    float4 wv = *(const float4*)(rw + t*4);
    red[t] = xv.x*wv.x + xv.y*wv.y + xv.z*wv.z + xv.w*wv.w;
    __syncthreads();
    for (int off = 128; off > 0; off >>= 1) {
        if (t < off) red[t] += red[t+off];
        __syncthreads();
    }
    if (t == 0) out[n] = red[0];
}

// ---------------- top-k via bitonic sort (desc value, asc index) ------------
__global__ __launch_bounds__(1024)
void topk_kernel(const float* __restrict__ scores, int* __restrict__ sel,
                 float* __restrict__ wout) {
    __shared__ float v[2048];
    __shared__ int  id[2048];
    const int b = blockIdx.x, t = threadIdx.x;
    v[t]        = scores[b*SEQ + t];        id[t]        = t;
    v[t + 1024] = scores[b*SEQ + t + 1024]; id[t + 1024] = t + 1024;
    __syncthreads();
    for (int k = 2; k <= 2048; k <<= 1) {
        for (int j = k >> 1; j > 0; j >>= 1) {
            #pragma unroll
            for (int s = 0; s < 2; s++) {
                int i = t + s*1024;
                int ixj = i ^ j;
                if (ixj > i) {
                    float vi = v[i], vj = v[ixj];
                    int   ii = id[i], ij = id[ixj];
                    bool before = (vi > vj) || (vi == vj && ii < ij);
                    bool up = ((i & k) == 0);
                    bool dosw = up ? (!before) : before;
                    if (dosw) { v[i] = vj; v[ixj] = vi; id[i] = ij; id[ixj] = ii; }
                }
            }
            __syncthreads();
        }
    }
    sel [b*KSEL + t] = id[t];
    wout[b*KSEL + t] = 1.f / (1.f + expf(-v[t]));
}

// ---------------- gather / scatter ------------------------------------------
__global__ __launch_bounds__(256)
void gather_kernel(const float* __restrict__ x, const int* __restrict__ sel,
                   float* __restrict__ xs) {
    const int row = blockIdx.x;
    const int b = row >> 10;
    const int src = b*SEQ + sel[row];
    const int t = threadIdx.x;
    float4 v = *(const float4*)(x + (size_t)src*D_MODEL + t*4);
    *(float4*)(xs + (size_t)row*D_MODEL + t*4) = v;
}

__global__ __launch_bounds__(256)
void scatter_kernel(float* __restrict__ x, const int* __restrict__ sel,
                    const float* __restrict__ w, const float* __restrict__ xs,
                    const float* __restrict__ proc) {
    const int row = blockIdx.x;
    const int b = row >> 10;
    const int dst = b*SEQ + sel[row];
    const float wv = w[row];
    const int t = threadIdx.x;
    float4 p  = *(const float4*)(proc + (size_t)row*D_MODEL + t*4);
    float4 s  = *(const float4*)(xs   + (size_t)row*D_MODEL + t*4);
    float4 xv = *(float4*)(x + (size_t)dst*D_MODEL + t*4);
    xv.x += (p.x - s.x)*wv;
    xv.y += (p.y - s.y)*wv;
    xv.z += (p.z - s.z)*wv;
    xv.w += (p.w - s.w)*wv;
    *(float4*)(x + (size_t)dst*D_MODEL + t*4) = xv;
}

// ---------------- host-side helpers ------------------------------------------
struct WP2 { __half *h, *l; };

static void run_encoder(const float* Xin, float* Xout, int Ncur, int Tcur, int Bcur,
                        WP2 wq, const float* bq, WP2 wo, const float* bo,
                        WP2 w1, const float* b1, WP2 w2, const float* b2,
                        const float* g1, const float* be1, const float* g2, const float* be2,
                        float* qkv, float* attnb, float* t1, float* t2, float* ff,
                        __half* ah, __half* al, __half* qkvh, __half* qkvl,
                        __half* vth, __half* vtl) {
    split2(Xin, ah, al, (size_t)Ncur * D_MODEL);
    gemm_fp16x2<0><<<dim3(3*D_MODEL/128, Ncur/128), 256, GEMM_SMEM_BYTES>>>(
        ah, al, wq.h, wq.l, bq, qkv, Ncur, 3*D_MODEL, D_MODEL);
    split2(qkv, qkvh, qkvl, (size_t)Ncur * 3 * D_MODEL);
    vtrans_kernel<<<dim3(Tcur/64, NHEAD, Bcur), 256>>>(qkvh, qkvl,
        vth, vtl, Tcur);
    attn_mma<<<dim3(Tcur/64, NHEAD, Bcur), 256, ATTN_SMEM3>>>(qkvh, qkvl, vth, vtl, attnb, Tcur);
    split2(attnb, ah, al, (size_t)Ncur * D_MODEL);
    gemm_fp16x2<0><<<dim3(D_MODEL/128, Ncur/128), 256, GEMM_SMEM_BYTES>>>(
        ah, al, wo.h, wo.l, bo, t2, Ncur, D_MODEL, D_MODEL);
    addln_kernel<<<Ncur, 256>>>(Xin, t2, g1, be1, t1);
    split2(t1, ah, al, (size_t)Ncur * D_MODEL);
    gemm_fp16x2<1><<<dim3(DFF_/128, Ncur/128), 256, GEMM_SMEM_BYTES>>>(
        ah, al, w1.h, w1.l, b1, ff, Ncur, DFF_, D_MODEL);
    split2(ff, ah, al, (size_t)Ncur * DFF_);
    gemm_fp16x2<0><<<dim3(D_MODEL/128, Ncur/128), 256, GEMM_SMEM_BYTES>>>(
        ah, al, w2.h, w2.l, b2, t2, Ncur, D_MODEL, DFF_);
    addln_kernel<<<Ncur, 256>>>(t1, t2, g2, be2, Xout);
}

extern "C" void kernel_launch(void* const* d_in, const int* in_sizes, int n_in,
                              void* d_out, int out_size) {
    (void)in_sizes; (void)n_in; (void)out_size;
    const float* x    = (const float*)d_in[0];
    const float* Wqkv = (const float*)d_in[1];
    const float* bqkv = (const float*)d_in[2];
    const float* Wo   = (const float*)d_in[3];
    const float* bo   = (const float*)d_in[4];
    const float* W1   = (const float*)d_in[5];
    const float* b1   = (const float*)d_in[6];
    const float* W2   = (const float*)d_in[7];
    const float* b2   = (const float*)d_in[8];
    const float* g1   = (const float*)d_in[9];
    const float* be1  = (const float*)d_in[10];
    const float* g2   = (const float*)d_in[11];
    const float* be2  = (const float*)d_in[12];
    const float* rw   = (const float*)d_in[13];

    float *gx, *gxsel, *gqkv, *gattn, *gt1, *gt2, *gff, *grs, *gw; int* gsel;
    cudaGetSymbolAddress((void**)&gx,    g_x);
    cudaGetSymbolAddress((void**)&gxsel, g_xsel);
    cudaGetSymbolAddress((void**)&gqkv,  g_qkv);
    cudaGetSymbolAddress((void**)&gattn, g_attn);
    cudaGetSymbolAddress((void**)&gt1,   g_t1);
    cudaGetSymbolAddress((void**)&gt2,   g_t2);
    cudaGetSymbolAddress((void**)&gff,   g_ff);
    cudaGetSymbolAddress((void**)&grs,   g_rs);
    cudaGetSymbolAddress((void**)&gsel,  g_sel);
    cudaGetSymbolAddress((void**)&gw,    g_w);

    __half *wqkv2, *wo2, *w12, *w22, *act2, *qkv2, *vt2;
    cudaGetSymbolAddress((void**)&wqkv2, g_wqkv2);
    cudaGetSymbolAddress((void**)&wo2,   g_wo2);
    cudaGetSymbolAddress((void**)&w12,   g_w12);
    cudaGetSymbolAddress((void**)&w22,   g_w22);
    cudaGetSymbolAddress((void**)&act2,  g_act2);
    cudaGetSymbolAddress((void**)&qkv2,  g_qkv2);
    cudaGetSymbolAddress((void**)&vt2,   g_vt2);

    cudaFuncSetAttribute(attn_mma, cudaFuncAttributeMaxDynamicSharedMemorySize, ATTN_SMEM3);
    cudaFuncSetAttribute(gemm_fp16x2<0>, cudaFuncAttributeMaxDynamicSharedMemorySize, GEMM_SMEM_BYTES);
    cudaFuncSetAttribute(gemm_fp16x2<1>, cudaFuncAttributeMaxDynamicSharedMemorySize, GEMM_SMEM_BYTES);

    split2(Wqkv, wqkv2, wqkv2 + WQKV_SZ, WQKV_SZ);
    split2(Wo,   wo2,   wo2   + WO_SZ,   WO_SZ);
    split2(W1,   w12,   w12   + W1_SZ,   W1_SZ);
    split2(W2,   w22,   w22   + W2_SZ,   W2_SZ);

    __half* ah = act2;
    __half* al = act2 + (size_t)ACT_SZ;
    __half* qkvh = qkv2;
    __half* qkvl = qkv2 + (size_t)QKV_SZ;
    __half* vth = vt2;
    __half* vtl = vt2 + (size_t)VT_SZ;

    const int n4 = NTOK*D_MODEL/4;
    copy_f4<<<(n4 + 255)/256, 256>>>((const float4*)x, (float4*)gx, n4);

    for (int L = 0; L < NLAYER; L++) {
        WP2 wq_l = { wqkv2 + (size_t)L*3*D_MODEL*D_MODEL,
                     wqkv2 + WQKV_SZ + (size_t)L*3*D_MODEL*D_MODEL };
        WP2 wo_l = { wo2 + (size_t)L*D_MODEL*D_MODEL,
                     wo2 + WO_SZ + (size_t)L*D_MODEL*D_MODEL };
        WP2 w1_l = { w12 + (size_t)L*DFF_*D_MODEL,
                     w12 + W1_SZ + (size_t)L*DFF_*D_MODEL };
        WP2 w2_l = { w22 + (size_t)L*D_MODEL*DFF_,
                     w22 + W2_SZ + (size_t)L*D_MODEL*DFF_ };
        const float* bq_l  = bqkv + (size_t)L*3*D_MODEL;
        const float* bo_l  = bo   + (size_t)L*D_MODEL;
        const float* b1_l  = b1   + (size_t)L*DFF_;
        const float* b2_l  = b2   + (size_t)L*D_MODEL;
        const float* g1_l  = g1   + (size_t)L*D_MODEL;
        const float* be1_l = be1  + (size_t)L*D_MODEL;
        const float* g2_l  = g2   + (size_t)L*D_MODEL;
        const float* be2_l = be2  + (size_t)L*D_MODEL;

        if (L & 1) {
            router_kernel<<<NTOK, 256>>>(gx, rw + (size_t)L*D_MODEL, grs);
            topk_kernel<<<BATCH, 1024>>>(grs, gsel, gw);
            gather_kernel<<<NSEL, 256>>>(gx, gsel, gxsel);
            run_encoder(gxsel, gattn, NSEL, KSEL, BATCH,
                        wq_l, bq_l, wo_l, bo_l, w1_l, b1_l, w2_l, b2_l,
                        g1_l, be1_l, g2_l, be2_l,
                        gqkv, gattn, gt1, gt2, gff, ah, al, qkvh, qkvl, vth, vtl);
            scatter_kernel<<<NSEL, 256>>>(gx, gsel, gw, gxsel, gattn);
        } else {
            run_encoder(gx, gx, NTOK, SEQ, BATCH,
                        wq_l, bq_l, wo_l, bo_l, w1_l, b1_l, w2_l, b2_l,
                        g1_l, be1_l, g2_l, be2_l,
                        gqkv, gattn, gt1, gt2, gff, ah, al, qkvh, qkvl, vth, vtl);
        }
    }

    copy_f4<<<(n4 + 255)/256, 256>>>((const float4*)gx, (float4*)d_out, n4);
}

// round 14
// speedup vs baseline: 2.4432x; 1.0000x over previous
#include <cuda_runtime.h>
#include <cuda_fp16.h>
#include <math.h>
#include <stdint.h>

#define D_MODEL 1024
#define NHEAD   16
#define HDIM    64
#define DFF_    4096
#define NLAYER  6
#define BATCH   4
#define SEQ     2048
#define NTOK    (BATCH*SEQ)      /* 8192 */
#define KSEL    1024
#define NSEL    (BATCH*KSEL)     /* 4096 */

#define WQKV_SZ (NLAYER*3*D_MODEL*D_MODEL)
#define WO_SZ   (NLAYER*D_MODEL*D_MODEL)
#define W1_SZ   (NLAYER*DFF_*D_MODEL)
#define W2_SZ   (NLAYER*D_MODEL*DFF_)
#define ACT_SZ  (NTOK*DFF_)
#define QKV_SZ  (NTOK*3*D_MODEL)
#define VT_SZ   (NTOK*D_MODEL)
#define XP_SZ   (NTOK*D_MODEL)

#define LOW_SCALE   2048.0f
#define LOW_UNSCALE (1.0f/2048.0f)

// ---------------- scratch (device globals; no allocations allowed) ----------
__device__ __align__(256) float g_x   [NTOK*D_MODEL];
__device__ __align__(256) float g_xsel[NSEL*D_MODEL];
__device__ __align__(256) float g_t1  [NTOK*D_MODEL];
__device__ __align__(256) float g_t2  [NTOK*D_MODEL];
__device__ __align__(256) float g_xo  [NTOK*D_MODEL];   /* odd-layer encoder out */
__device__ __align__(256) float g_rs  [BATCH*SEQ];
__device__ __align__(256) int   g_sel [BATCH*KSEL];
__device__ __align__(256) float g_w   [BATCH*KSEL];

// fp16 split-plane buffers (h, l*2048)
__device__ __align__(256) __half g_wqkv2[2][WQKV_SZ];
__device__ __align__(256) __half g_wo2  [2][WO_SZ];
__device__ __align__(256) __half g_w12  [2][W1_SZ];
__device__ __align__(256) __half g_w22  [2][W2_SZ];
__device__ __align__(256) __half g_ffp  [2][ACT_SZ];    /* FF1 out planes */
__device__ __align__(256) __half g_qkv2 [2][QKV_SZ];
__device__ __align__(256) __half g_vt2  [2][VT_SZ];
__device__ __align__(256) __half g_px   [2][XP_SZ];     /* x planes */
__device__ __align__(256) __half g_pa   [2][XP_SZ];     /* attn out planes */
__device__ __align__(256) __half g_pt1  [2][XP_SZ];     /* t1 planes */
__device__ __align__(256) __half g_pxs  [2][NSEL*D_MODEL]; /* xsel planes */

// ---------------- simple float4 copy ---------------------------------------
__global__ void copy_f4(const float4* __restrict__ src, float4* __restrict__ dst, int n4) {
    int i = blockIdx.x * blockDim.x + threadIdx.x;
    if (i < n4) dst[i] = src[i];
}

// ---------------- 2-way fp16 split (low plane scaled by 2048) ----------------
__device__ __forceinline__ void split1(float v, __half& h, __half& l) {
    h = __float2half_rn(v);
    l = __float2half_rn((v - __half2float(h)) * LOW_SCALE);
}

__global__ __launch_bounds__(256)
void split2_kernel(const float* __restrict__ in,
                   __half* __restrict__ ph, __half* __restrict__ pl, int n8) {
    int i = blockIdx.x * blockDim.x + threadIdx.x;
    if (i >= n8) return;
    const float4* p = (const float4*)in + (size_t)i * 2;
    float4 x0 = p[0], x1 = p[1];
    float v[8] = {x0.x, x0.y, x0.z, x0.w, x1.x, x1.y, x1.z, x1.w};
    __align__(16) __half hh[8], ll[8];
    #pragma unroll
    for (int k = 0; k < 8; k++) split1(v[k], hh[k], ll[k]);
    *(uint4*)(ph + (size_t)i * 8) = *(uint4*)hh;
    *(uint4*)(pl + (size_t)i * 8) = *(uint4*)ll;
}

static inline void split2(const float* in, __half* h, __half* l, size_t n) {
    int n8 = (int)(n / 8);
    split2_kernel<<<(n8 + 255) / 256, 256>>>(in, h, l, n8);
}

// ---------------- V transpose: qkv fp16 planes -> VT [b*h][d][T] -------------
__global__ __launch_bounds__(256)
void vtrans_kernel(const __half* __restrict__ qh, const __half* __restrict__ ql,
                   __half* __restrict__ vth, __half* __restrict__ vtl, int T) {
    __shared__ __half sh[64][72], sl[64][72];
    const int t0 = blockIdx.x * 64, h = blockIdx.y, b = blockIdx.z;
    const int tid = threadIdx.x;
    const int row = tid >> 2;
    const int dg  = (tid & 3) * 16;

    const size_t src_off = (size_t)(b*T + t0 + row) * 3*D_MODEL + 2*D_MODEL + h*HDIM + dg;
    uint4 h0 = *(const uint4*)(qh + src_off);
    uint4 h1 = *(const uint4*)(qh + src_off + 8);
    uint4 l0 = *(const uint4*)(ql + src_off);
    uint4 l1 = *(const uint4*)(ql + src_off + 8);
    __align__(16) __half hb[16], lb[16];
    *(uint4*)&hb[0] = h0; *(uint4*)&hb[8] = h1;
    *(uint4*)&lb[0] = l0; *(uint4*)&lb[8] = l1;
    #pragma unroll
    for (int e = 0; e < 16; e++) {
        sh[dg + e][row] = hb[e];
        sl[dg + e][row] = lb[e];
    }
    __syncthreads();
    const size_t dst_off = ((size_t)((b*NHEAD + h)*HDIM + row)) * T + t0 + dg;
    *(uint4*)(vth + dst_off)     = *(uint4*)&sh[row][dg];
    *(uint4*)(vth + dst_off + 8) = *(uint4*)&sh[row][dg + 8];
    *(uint4*)(vtl + dst_off)     = *(uint4*)&sl[row][dg];
    *(uint4*)(vtl + dst_off + 8) = *(uint4*)&sl[row][dg + 8];
}

#define MMA_F16(d, a, b) \
    asm volatile("mma.sync.aligned.m16n8k16.row.col.f32.f16.f16.f32 " \
        "{%0,%1,%2,%3}, {%4,%5,%6,%7}, {%8,%9}, {%0,%1,%2,%3};" \
        : "+f"((d)[0]), "+f"((d)[1]), "+f"((d)[2]), "+f"((d)[3]) \
        : "r"((a)[0]), "r"((a)[1]), "r"((a)[2]), "r"((a)[3]), "r"((b)[0]), "r"((b)[1]))

#define LDSM4(r, addr) \
    asm volatile("ldmatrix.sync.aligned.m8n8.x4.shared.b16 {%0,%1,%2,%3}, [%4];" \
        : "=r"((r)[0]), "=r"((r)[1]), "=r"((r)[2]), "=r"((r)[3]) : "r"(addr))

__device__ __forceinline__ void cp_async16(uint32_t smem_addr, const void* gptr) {
    asm volatile("cp.async.ca.shared.global [%0], [%1], 16;" :: "r"(smem_addr), "l"(gptr));
}
#define CP_COMMIT() asm volatile("cp.async.commit_group;" ::: "memory")
#define CP_WAIT_1() asm volatile("cp.async.wait_group 1;" ::: "memory")
#define CP_WAIT_0() asm volatile("cp.async.wait_group 0;" ::: "memory")

// ---------------- fast exp on FMA pipe (no MUFU), rel err ~1.5e-6 ------------
__device__ __forceinline__ float fexp(float x) {
    x = fmaxf(x, -80.0f);
    float t  = x * 1.4426950408889634f;
    float fl = floorf(t);
    float f  = t - fl;
    float p  = 1.5252734e-5f;
    p = fmaf(p, f, 1.5403530e-4f);
    p = fmaf(p, f, 1.3333558e-3f);
    p = fmaf(p, f, 9.6181291e-3f);
    p = fmaf(p, f, 5.5504109e-2f);
    p = fmaf(p, f, 2.4022651e-1f);
    p = fmaf(p, f, 6.9314718e-1f);
    p = fmaf(p, f, 1.0f);
    int i = (int)fl;
    float sc = __int_as_float((i + 127) << 23);
    return p * sc;
}

// ---------------- fp16 2-plane split GEMM, cp.async + ldmatrix ---------------
// EMIT 0: fp32 C.  EMIT 1: fp16 h/l planes (split in epilogue).
#define BK2 32
#define SROW2 40
#define PLANE_HALVES (128*SROW2)
#define GEMM_SMEM_BYTES (2*2*2*PLANE_HALVES*2)

template<int RELU, int EMIT>
__global__ __launch_bounds__(256)
void gemm_fp16x2(const __half* __restrict__ Ah, const __half* __restrict__ Al,
                 const __half* __restrict__ Wh, const __half* __restrict__ Wl,
                 const float* __restrict__ bias, float* __restrict__ C,
                 __half* __restrict__ Ch, __half* __restrict__ Cl,
                 int N, int M, int K) {
    extern __shared__ __half smh[];
    const int t    = threadIdx.x;
    const int lane = t & 31;
    const int warp = t >> 5;
    const int wm   = warp >> 2;
    const int wn   = warp & 3;
    const int rn   = blockIdx.y * 128;
    const int cm   = blockIdx.x * 128;
    const int g    = lane >> 2;
    const int tg   = lane & 3;

    const int la_row = (lane & 7) + ((lane >> 3) & 1) * 8;
    const int la_k   = (lane >> 4) * 8;
    const int lb_row = (lane & 7);
    const int lb_jn  = (lane >> 4);
    const int lb_k   = ((lane >> 3) & 1) * 8;

    const __half* Ap[2] = { Ah, Al };
    const __half* Wp[2] = { Wh, Wl };

    const uint32_t smem_u32 = (uint32_t)__cvta_generic_to_shared(smh);
    const int c0r = t >> 2,        c0k = (t & 3) * 8;
    const int c1r = (t + 256) >> 2, c1k = ((t + 256) & 3) * 8;

    float acc1[4][4][4], acc2[4][4][4];
    #pragma unroll
    for (int i = 0; i < 4; i++)
        #pragma unroll
        for (int j = 0; j < 4; j++)
            #pragma unroll
            for (int r = 0; r < 4; r++) { acc1[i][j][r] = 0.f; acc2[i][j][r] = 0.f; }

    const int KT = K / BK2;

    auto issue_stage = [&](int buf, int k0) {
        #pragma unroll
        for (int p = 0; p < 2; p++) {
            uint32_t baseA = smem_u32 + (uint32_t)(((buf*2 + 0)*2 + p) * PLANE_HALVES) * 2;
            uint32_t baseW = smem_u32 + (uint32_t)(((buf*2 + 1)*2 + p) * PLANE_HALVES) * 2;
            cp_async16(baseA + (uint32_t)(c0r*SROW2 + c0k)*2, Ap[p] + (size_t)(rn + c0r)*K + k0 + c0k);
            cp_async16(baseA + (uint32_t)(c1r*SROW2 + c1k)*2, Ap[p] + (size_t)(rn + c1r)*K + k0 + c1k);
            cp_async16(baseW + (uint32_t)(c0r*SROW2 + c0k)*2, Wp[p] + (size_t)(cm + c0r)*K + k0 + c0k);
            cp_async16(baseW + (uint32_t)(c1r*SROW2 + c1k)*2, Wp[p] + (size_t)(cm + c1r)*K + k0 + c1k);
        }
        CP_COMMIT();
    };

    issue_stage(0, 0);

    for (int kt = 0; kt < KT; kt++) {
        const int cur = kt & 1;
        const bool more = (kt + 1) < KT;
        if (more) issue_stage(cur ^ 1, (kt + 1) * BK2);
        if (more) CP_WAIT_1(); else CP_WAIT_0();
        __syncthreads();

        const uint32_t uA0 = smem_u32 + (uint32_t)(((cur*2 + 0)*2 + 0) * PLANE_HALVES) * 2;
        const uint32_t uA1 = smem_u32 + (uint32_t)(((cur*2 + 0)*2 + 1) * PLANE_HALVES) * 2;
        const uint32_t uW0 = smem_u32 + (uint32_t)(((cur*2 + 1)*2 + 0) * PLANE_HALVES) * 2;
        const uint32_t uW1 = smem_u32 + (uint32_t)(((cur*2 + 1)*2 + 1) * PLANE_HALVES) * 2;

        #pragma unroll
        for (int ks0 = 0; ks0 < BK2; ks0 += 16) {
            uint32_t fbv[2][8];
            #pragma unroll
            for (int jp = 0; jp < 2; jp++) {
                uint32_t boff = (uint32_t)((wn*32 + jp*16 + lb_jn*8 + lb_row)*SROW2 + ks0 + lb_k) * 2;
                LDSM4(&fbv[0][jp*4], uW0 + boff);
                LDSM4(&fbv[1][jp*4], uW1 + boff);
            }
            #pragma unroll
            for (int im = 0; im < 4; im++) {
                const int r0 = wm * 64 + im * 16;
                uint32_t aoff = (uint32_t)((r0 + la_row)*SROW2 + ks0 + la_k) * 2;
                uint32_t fa[2][4];
                LDSM4(fa[0], uA0 + aoff);
                LDSM4(fa[1], uA1 + aoff);
                #pragma unroll
                for (int jn = 0; jn < 4; jn++) {
                    MMA_F16(acc1[im][jn], fa[0], &fbv[0][jn*2]);
                    MMA_F16(acc2[im][jn], fa[0], &fbv[1][jn*2]);
                    MMA_F16(acc2[im][jn], fa[1], &fbv[0][jn*2]);
                }
            }
        }
        __syncthreads();
    }

    #pragma unroll
    for (int im = 0; im < 4; im++) {
        #pragma unroll
        for (int jn = 0; jn < 4; jn++) {
            const int row = rn + wm * 64 + im * 16 + g;
            const int col = cm + wn * 32 + jn * 8 + tg * 2;
            float b0 = bias[col], b1 = bias[col + 1];
            float v0 = acc1[im][jn][0] + acc2[im][jn][0] * LOW_UNSCALE + b0;
            float v1 = acc1[im][jn][1] + acc2[im][jn][1] * LOW_UNSCALE + b1;
            float v2 = acc1[im][jn][2] + acc2[im][jn][2] * LOW_UNSCALE + b0;
            float v3 = acc1[im][jn][3] + acc2[im][jn][3] * LOW_UNSCALE + b1;
            if (RELU) {
                v0 = fmaxf(v0, 0.f); v1 = fmaxf(v1, 0.f);
                v2 = fmaxf(v2, 0.f); v3 = fmaxf(v3, 0.f);
            }
            if (EMIT == 0) {
                *(float2*)&C[(size_t)row * M + col]       = make_float2(v0, v1);
                *(float2*)&C[(size_t)(row + 8) * M + col] = make_float2(v2, v3);
            } else {
                __half h0, l0, h1, l1, h2, l2, h3, l3;
                split1(v0, h0, l0); split1(v1, h1, l1);
                split1(v2, h2, l2); split1(v3, h3, l3);
                __half2 H01; H01.x = h0; H01.y = h1;
                __half2 L01; L01.x = l0; L01.y = l1;
                __half2 H23; H23.x = h2; H23.y = h3;
                __half2 L23; L23.x = l2; L23.y = l3;
                *(__half2*)&Ch[(size_t)row * M + col]       = H01;
                *(__half2*)&Cl[(size_t)row * M + col]       = L01;
                *(__half2*)&Ch[(size_t)(row + 8) * M + col] = H23;
                *(__half2*)&Cl[(size_t)(row + 8) * M + col] = L23;
            }
        }
    }
}

// ---------------- MMA flash attention: plane in/out, cp.async pipeline -------
#define QS 72
#define SS 68
#define APL (64*QS)
#define ATTN_SMEM3 (12*APL*2 + (64*SS + 3*64)*4)

__global__ __launch_bounds__(256)
void attn_mma(const __half* __restrict__ qkvh, const __half* __restrict__ qkvl,
              const __half* __restrict__ vth,  const __half* __restrict__ vtl,
              __half* __restrict__ outh, __half* __restrict__ outl, int T) {
    extern __shared__ char sm_raw[];
    __half* smh = (__half*)sm_raw;
    __half* Ph = smh + 10*APL;
    __half* Pl = smh + 11*APL;
    float*  Ssm  = (float*)(smh + 12*APL);
    float*  mrow = Ssm + 64*SS;
    float*  lrow = mrow + 64;
    float*  arow = lrow + 64;

    const int t    = threadIdx.x;
    const int lane = t & 31;
    const int warp = t >> 5;
    const int wm   = warp >> 2;
    const int wn   = warp & 3;
    const int g    = lane >> 2;
    const int tg   = lane & 3;
    const int qt = blockIdx.x, h = blockIdx.y, b = blockIdx.z;
    const int stride3 = 3 * D_MODEL;

    const int la_row = (lane & 7) + ((lane >> 3) & 1) * 8;
    const int la_k   = (lane >> 4) * 8;
    const int lb_row = (lane & 7);
    const int lb_jn  = (lane >> 4);
    const int lb_k   = ((lane >> 3) & 1) * 8;

    const uint32_t uS = (uint32_t)__cvta_generic_to_shared(smh);
    const uint32_t uQ = uS;
    const uint32_t uK = uS + 2*APL*2;
    const uint32_t uV = uS + 6*APL*2;
    const uint32_t uP = uS + 10*APL*2;

    const __half* qp[2] = { qkvh, qkvl };
    const __half* vp[2] = { vth,  vtl  };

    {
        #pragma unroll
        for (int i = 0; i < 4; i++) {
            int c = t + 256*i;
            int plane = c >> 9, rem = c & 511, row = rem >> 3, ch = (rem & 7) * 8;
            const __half* qg = qp[plane] + (size_t)(b*T + qt*64 + row)*stride3 + h*HDIM + ch;
            cp_async16(uQ + (uint32_t)(plane*APL + row*QS + ch)*2, qg);
        }
    }
    auto issue_kv = [&](int buf, int kt) {
        #pragma unroll
        for (int i = 0; i < 4; i++) {
            int c = t + 256*i;
            int plane = c >> 9, rem = c & 511, row = rem >> 3, ch = (rem & 7) * 8;
            const __half* kg = qp[plane] + (size_t)(b*T + kt*64 + row)*stride3 + D_MODEL + h*HDIM + ch;
            cp_async16(uK + (uint32_t)((buf*2 + plane)*APL + row*QS + ch)*2, kg);
            const __half* vg = vp[plane] + ((size_t)((b*NHEAD + h)*HDIM + row))*T + kt*64 + ch;
            cp_async16(uV + (uint32_t)((buf*2 + plane)*APL + row*QS + ch)*2, vg);
        }
        CP_COMMIT();
    };
    issue_kv(0, 0);

    if (t < 64) { mrow[t] = -1e30f; lrow[t] = 0.f; }

    float o1[2][2][4], o2[2][2][4];
    #pragma unroll
    for (int i = 0; i < 2; i++)
        #pragma unroll
        for (int j = 0; j < 2; j++)
            #pragma unroll
            for (int r = 0; r < 4; r++) { o1[i][j][r] = 0.f; o2[i][j][r] = 0.f; }

    const int nkt = T / 64;
    for (int kt2 = 0; kt2 < nkt; kt2++) {
        const int cur = kt2 & 1;
        const bool more = (kt2 + 1) < nkt;
        __syncthreads();
        if (more) issue_kv(cur ^ 1, kt2 + 1);
        if (more) CP_WAIT_1(); else CP_WAIT_0();
        __syncthreads();

        const uint32_t uK0 = uK + (uint32_t)(cur*2 + 0)*APL*2;
        const uint32_t uK1 = uK + (uint32_t)(cur*2 + 1)*APL*2;
        const uint32_t uV0 = uV + (uint32_t)(cur*2 + 0)*APL*2;
        const uint32_t uV1 = uV + (uint32_t)(cur*2 + 1)*APL*2;

        float s1[2][2][4], s2[2][2][4];
        #pragma unroll
        for (int i = 0; i < 2; i++)
            #pragma unroll
            for (int j = 0; j < 2; j++)
                #pragma unroll
                for (int r = 0; r < 4; r++) { s1[i][j][r] = 0.f; s2[i][j][r] = 0.f; }

        #pragma unroll
        for (int ks0 = 0; ks0 < 64; ks0 += 16) {
            uint32_t fbv[2][4];
            {
                uint32_t boff = (uint32_t)((wn*16 + lb_jn*8 + lb_row)*QS + ks0 + lb_k) * 2;
                LDSM4(fbv[0], uK0 + boff);
                LDSM4(fbv[1], uK1 + boff);
            }
            #pragma unroll
            for (int im = 0; im < 2; im++) {
                const int r0 = wm * 32 + im * 16;
                uint32_t aoff = (uint32_t)((r0 + la_row)*QS + ks0 + la_k) * 2;
                uint32_t fa[2][4];
                LDSM4(fa[0], uQ + aoff);
                LDSM4(fa[1], uQ + (uint32_t)APL*2 + aoff);
                #pragma unroll
                for (int jn = 0; jn < 2; jn++) {
                    MMA_F16(s1[im][jn], fa[0], &fbv[0][jn*2]);
                    MMA_F16(s2[im][jn], fa[0], &fbv[1][jn*2]);
                    MMA_F16(s2[im][jn], fa[1], &fbv[0][jn*2]);
                }
            }
        }
        #pragma unroll
        for (int im = 0; im < 2; im++) {
            #pragma unroll
            for (int jn = 0; jn < 2; jn++) {
                const int r = wm * 32 + im * 16 + g;
                const int c = wn * 16 + jn * 8 + tg * 2;
                float v0 = (s1[im][jn][0] + s2[im][jn][0]*LOW_UNSCALE) * 0.125f;
                float v1 = (s1[im][jn][1] + s2[im][jn][1]*LOW_UNSCALE) * 0.125f;
                float v2 = (s1[im][jn][2] + s2[im][jn][2]*LOW_UNSCALE) * 0.125f;
                float v3 = (s1[im][jn][3] + s2[im][jn][3]*LOW_UNSCALE) * 0.125f;
                *(float2*)&Ssm[r*SS + c]       = make_float2(v0, v1);
                *(float2*)&Ssm[(r + 8)*SS + c] = make_float2(v2, v3);
            }
        }
        __syncthreads();

        {
            const int row = t >> 2, q4 = (t & 3) * 16;
            float vals[16];
            float mloc = -1e30f;
            #pragma unroll
            for (int j = 0; j < 16; j++) {
                vals[j] = Ssm[row*SS + q4 + j];
                mloc = fmaxf(mloc, vals[j]);
            }
            mloc = fmaxf(mloc, __shfl_xor_sync(0xFFFFFFFF, mloc, 1));
            mloc = fmaxf(mloc, __shfl_xor_sync(0xFFFFFFFF, mloc, 2));
            float mo = mrow[row];
            float mn = fmaxf(mo, mloc);
            float sum = 0.f;
            #pragma unroll
            for (int j = 0; j < 16; j++) {
                float p = fexp(vals[j] - mn);
                sum += p;
                __half hv = __float2half_rn(p);
                Ph[row*QS + q4 + j] = hv;
                Pl[row*QS + q4 + j] = __float2half_rn((p - __half2float(hv)) * LOW_SCALE);
            }
            sum += __shfl_xor_sync(0xFFFFFFFF, sum, 1);
            sum += __shfl_xor_sync(0xFFFFFFFF, sum, 2);
            if ((t & 3) == 0) {
                float al = fexp(mo - mn);
                mrow[row] = mn;
                lrow[row] = lrow[row]*al + sum;
                arow[row] = al;
            }
        }
        __syncthreads();

        #pragma unroll
        for (int im = 0; im < 2; im++) {
            const int r0 = wm * 32 + im * 16;
            float a0 = arow[r0 + g], a1 = arow[r0 + g + 8];
            #pragma unroll
            for (int jn = 0; jn < 2; jn++) {
                o1[im][jn][0] *= a0; o1[im][jn][1] *= a0;
                o1[im][jn][2] *= a1; o1[im][jn][3] *= a1;
                o2[im][jn][0] *= a0; o2[im][jn][1] *= a0;
                o2[im][jn][2] *= a1; o2[im][jn][3] *= a1;
            }
        }
        #pragma unroll
        for (int ks0 = 0; ks0 < 64; ks0 += 16) {
            uint32_t fbv[2][4];
            {
                uint32_t boff = (uint32_t)((wn*16 + lb_jn*8 + lb_row)*QS + ks0 + lb_k) * 2;
                LDSM4(fbv[0], uV0 + boff);
                LDSM4(fbv[1], uV1 + boff);
            }
            #pragma unroll
            for (int im = 0; im < 2; im++) {
                const int r0 = wm * 32 + im * 16;
                uint32_t aoff = (uint32_t)((r0 + la_row)*QS + ks0 + la_k) * 2;
                uint32_t fa[2][4];
                LDSM4(fa[0], uP + aoff);
                LDSM4(fa[1], uP + (uint32_t)APL*2 + aoff);
                #pragma unroll
                for (int jn = 0; jn < 2; jn++) {
                    MMA_F16(o1[im][jn], fa[0], &fbv[0][jn*2]);
                    MMA_F16(o2[im][jn], fa[0], &fbv[1][jn*2]);
                    MMA_F16(o2[im][jn], fa[1], &fbv[0][jn*2]);
                }
            }
        }
    }
    __syncthreads();

    // ---- final: normalize, split, store planes ----
    const int n0 = b*T + qt*64;
    #pragma unroll
    for (int im = 0; im < 2; im++) {
        #pragma unroll
        for (int jn = 0; jn < 2; jn++) {
            const int r = wm * 32 + im * 16 + g;
            const int c = wn * 16 + jn * 8 + tg * 2;
            float inv0 = 1.f / lrow[r];
            float inv1 = 1.f / lrow[r + 8];
            float v0 = (o1[im][jn][0] + o2[im][jn][0]*LOW_UNSCALE) * inv0;
            float v1 = (o1[im][jn][1] + o2[im][jn][1]*LOW_UNSCALE) * inv0;
            float v2 = (o1[im][jn][2] + o2[im][jn][2]*LOW_UNSCALE) * inv1;
            float v3 = (o1[im][jn][3] + o2[im][jn][3]*LOW_UNSCALE) * inv1;
            __half h0, l0, h1, l1, h2, l2, h3, l3;
            split1(v0, h0, l0); split1(v1, h1, l1);
            split1(v2, h2, l2); split1(v3, h3, l3);
            __half2 H01; H01.x = h0; H01.y = h1;
            __half2 L01; L01.x = l0; L01.y = l1;
            __half2 H23; H23.x = h2; H23.y = h3;
            __half2 L23; L23.x = l2; L23.y = l3;
            *(__half2*)&outh[(size_t)(n0 + r)*D_MODEL + h*HDIM + c]     = H01;
            *(__half2*)&outl[(size_t)(n0 + r)*D_MODEL + h*HDIM + c]     = L01;
            *(__half2*)&outh[(size_t)(n0 + r + 8)*D_MODEL + h*HDIM + c] = H23;
            *(__half2*)&outl[(size_t)(n0 + r + 8)*D_MODEL + h*HDIM + c] = L23;
        }
    }
}

// ---------------- residual add + LayerNorm (emits fp32 + planes) -------------
__global__ __launch_bounds__(256)
void addln_kernel(const float* __restrict__ a, const float* __restrict__ r,
                  const float* __restrict__ g, const float* __restrict__ be,
                  float* __restrict__ out, __half* __restrict__ outh,
                  __half* __restrict__ outl) {
    __shared__ float rsum[256], rsq[256];
    const int n = blockIdx.x, t = threadIdx.x;
    float4 av = *(const float4*)(a + (size_t)n*D_MODEL + t*4);
    float4 rv = *(const float4*)(r + (size_t)n*D_MODEL + t*4);
    float x0 = av.x + rv.x, x1 = av.y + rv.y, x2 = av.z + rv.z, x3 = av.w + rv.w;
    rsum[t] = x0 + x1 + x2 + x3;
    rsq [t] = x0*x0 + x1*x1 + x2*x2 + x3*x3;
    __syncthreads();
    for (int off = 128; off > 0; off >>= 1) {
        if (t < off) { rsum[t] += rsum[t+off]; rsq[t] += rsq[t+off]; }
        __syncthreads();
    }
    float mu  = rsum[0] * (1.f/1024.f);
    float var = rsq[0]  * (1.f/1024.f) - mu*mu;
    float rstd = rsqrtf(var + 1e-5f);
    float4 gv = *(const float4*)(g  + t*4);
    float4 bv = *(const float4*)(be + t*4);
    float4 o;
    o.x = (x0 - mu)*rstd*gv.x + bv.x;
    o.y = (x1 - mu)*rstd*gv.y + bv.y;
    o.z = (x2 - mu)*rstd*gv.z + bv.z;
    o.w = (x3 - mu)*rstd*gv.w + bv.w;
    *(float4*)(out + (size_t)n*D_MODEL + t*4) = o;
    __align__(8) __half hh[4], ll[4];
    split1(o.x, hh[0], ll[0]); split1(o.y, hh[1], ll[1]);
    split1(o.z, hh[2], ll[2]); split1(o.w, hh[3], ll[3]);
    *(uint2*)(outh + (size_t)n*D_MODEL + t*4) = *(uint2*)hh;
    *(uint2*)(outl + (size_t)n*D_MODEL + t*4) = *(uint2*)ll;
}

// ---------------- router score ----------------------------------------------
__global__ __launch_bounds__(256)
void router_kernel(const float* __restrict__ x, const float* __restrict__ rw,
                   float* __restrict__ out) {
    __shared__ float red[256];
    const int n = blockIdx.x, t = threadIdx.x;
    float4 xv = *(const float4*)(x + (size_t)n*D_MODEL + t*4);
    float4 wv = *(const float4*)(rw + t*4);
    red[t] = xv.x*wv.x + xv.y*wv.y + xv.z*wv.z + xv.w*wv.w;
    __syncthreads();
    for (int off = 128; off > 0; off >>= 1) {
        if (t < off) red[t] += red[t+off];
        __syncthreads();
    }
    if (t == 0) out[n] = red[0];
}

// ---------------- top-k via bitonic sort (desc value, asc index) ------------
__global__ __launch_bounds__(1024)
void topk_kernel(const float* __restrict__ scores, int* __restrict__ sel,
                 float* __restrict__ wout) {
    __shared__ float v[2048];
    __shared__ int  id[2048];
    const int b = blockIdx.x, t = threadIdx.x;
    v[t]        = scores[b*SEQ + t];        id[t]        = t;
    v[t + 1024] = scores[b*SEQ + t + 1024]; id[t + 1024] = t + 1024;
    __syncthreads();
    for (int k = 2; k <= 2048; k <<= 1) {
        for (int j = k >> 1; j > 0; j >>= 1) {
            #pragma unroll
            for (int s = 0; s < 2; s++) {
                int i = t + s*1024;
                int ixj = i ^ j;
                if (ixj > i) {
                    float vi = v[i], vj = v[ixj];
                    int   ii = id[i], ij = id[ixj];
                    bool before = (vi > vj) || (vi == vj && ii < ij);
                    bool up = ((i & k) == 0);
                    bool dosw = up ? (!before) : before;
                    if (dosw) { v[i] = vj; v[ixj] = vi; id[i] = ij; id[ixj] = ii; }
                }
            }
            __syncthreads();
        }
    }
    sel [b*KSEL + t] = id[t];
    wout[b*KSEL + t] = 1.f / (1.f + expf(-v[t]));
}

// ---------------- gather (fp32 + planes) / scatter ---------------------------
__global__ __launch_bounds__(256)
void gather_kernel(const float* __restrict__ x,
                   const __half* __restrict__ xh, const __half* __restrict__ xl,
                   const int* __restrict__ sel,
                   float* __restrict__ xs,
                   __half* __restrict__ xsh, __half* __restrict__ xsl) {
    const int row = blockIdx.x;
    const int b = row >> 10;
    const int src = b*SEQ + sel[row];
    const int t = threadIdx.x;
    float4 v = *(const float4*)(x + (size_t)src*D_MODEL + t*4);
    *(float4*)(xs + (size_t)row*D_MODEL + t*4) = v;
    uint2 hv = *(const uint2*)(xh + (size_t)src*D_MODEL + t*4);
    uint2 lv = *(const uint2*)(xl + (size_t)src*D_MODEL + t*4);
    *(uint2*)(xsh + (size_t)row*D_MODEL + t*4) = hv;
    *(uint2*)(xsl + (size_t)row*D_MODEL + t*4) = lv;
}

__global__ __launch_bounds__(256)
void scatter_kernel(float* __restrict__ x, const int* __restrict__ sel,
                    const float* __restrict__ w, const float* __restrict__ xs,
                    const float* __restrict__ proc) {
    const int row = blockIdx.x;
    const int b = row >> 10;
    const int dst = b*SEQ + sel[row];
    const float wv = w[row];
    const int t = threadIdx.x;
    float4 p  = *(const float4*)(proc + (size_t)row*D_MODEL + t*4);
    float4 s  = *(const float4*)(xs   + (size_t)row*D_MODEL + t*4);
    float4 xv = *(float4*)(x + (size_t)dst*D_MODEL + t*4);
    xv.x += (p.x - s.x)*wv;
    xv.y += (p.y - s.y)*wv;
    xv.z += (p.z - s.z)*wv;
    xv.w += (p.w - s.w)*wv;
    *(float4*)(x + (size_t)dst*D_MODEL + t*4) = xv;
}

// ---------------- host-side helpers ------------------------------------------
struct WP2 { __half *h, *l; };

static void run_encoder(const float* Xin, const __half* xinh, const __half* xinl,
                        float* Xout, __half* xouth, __half* xoutl,
                        int Ncur, int Tcur, int Bcur,
                        WP2 wq, const float* bq, WP2 wo, const float* bo,
                        WP2 w1, const float* b1, WP2 w2, const float* b2,
                        const float* g1, const float* be1, const float* g2, const float* be2,
                        float* t1, float* t2,
                        __half* qkvh, __half* qkvl, __half* vth, __half* vtl,
                        __half* pah, __half* pal, __half* pt1h, __half* pt1l,
                        __half* ffh, __half* ffl) {
    gemm_fp16x2<0,1><<<dim3(3*D_MODEL/128, Ncur/128), 256, GEMM_SMEM_BYTES>>>(
        xinh, xinl, wq.h, wq.l, bq, nullptr, qkvh, qkvl, Ncur, 3*D_MODEL, D_MODEL);
    vtrans_kernel<<<dim3(Tcur/64, NHEAD, Bcur), 256>>>(qkvh, qkvl, vth, vtl, Tcur);
    attn_mma<<<dim3(Tcur/64, NHEAD, Bcur), 256, ATTN_SMEM3>>>(qkvh, qkvl, vth, vtl, pah, pal, Tcur);
    gemm_fp16x2<0,0><<<dim3(D_MODEL/128, Ncur/128), 256, GEMM_SMEM_BYTES>>>(
        pah, pal, wo.h, wo.l, bo, t2, nullptr, nullptr, Ncur, D_MODEL, D_MODEL);
    addln_kernel<<<Ncur, 256>>>(Xin, t2, g1, be1, t1, pt1h, pt1l);
    gemm_fp16x2<1,1><<<dim3(DFF_/128, Ncur/128), 256, GEMM_SMEM_BYTES>>>(
        pt1h, pt1l, w1.h, w1.l, b1, nullptr, ffh, ffl, Ncur, DFF_, D_MODEL);
    gemm_fp16x2<0,0><<<dim3(D_MODEL/128, Ncur/128), 256, GEMM_SMEM_BYTES>>>(
        ffh, ffl, w2.h, w2.l, b2, t2, nullptr, nullptr, Ncur, D_MODEL, DFF_);
    addln_kernel<<<Ncur, 256>>>(t1, t2, g2, be2, Xout, xouth, xoutl);
}

extern "C" void kernel_launch(void* const* d_in, const int* in_sizes, int n_in,
                              void* d_out, int out_size) {
    (void)in_sizes; (void)n_in; (void)out_size;
    const float* x    = (const float*)d_in[0];
    const float* Wqkv = (const float*)d_in[1];
    const float* bqkv = (const float*)d_in[2];
    const float* Wo   = (const float*)d_in[3];
    const float* bo   = (const float*)d_in[4];
    const float* W1   = (const float*)d_in[5];
    const float* b1   = (const float*)d_in[6];
    const float* W2   = (const float*)d_in[7];
    const float* b2   = (const float*)d_in[8];
    const float* g1   = (const float*)d_in[9];
    const float* be1  = (const float*)d_in[10];
    const float* g2   = (const float*)d_in[11];
    const float* be2  = (const float*)d_in[12];
    const float* rw   = (const float*)d_in[13];

    float *gx, *gxsel, *gt1, *gt2, *gxo, *grs, *gw; int* gsel;
    cudaGetSymbolAddress((void**)&gx,    g_x);
    cudaGetSymbolAddress((void**)&gxsel, g_xsel);
    cudaGetSymbolAddress((void**)&gt1,   g_t1);
    cudaGetSymbolAddress((void**)&gt2,   g_t2);
    cudaGetSymbolAddress((void**)&gxo,   g_xo);
    cudaGetSymbolAddress((void**)&grs,   g_rs);
    cudaGetSymbolAddress((void**)&gsel,  g_sel);
    cudaGetSymbolAddress((void**)&gw,    g_w);

    __half *wqkv2, *wo2, *w12, *w22, *ffp, *qkv2, *vt2, *px, *pa, *pt1, *pxs;
    cudaGetSymbolAddress((void**)&wqkv2, g_wqkv2);
    cudaGetSymbolAddress((void**)&wo2,   g_wo2);
    cudaGetSymbolAddress((void**)&w12,   g_w12);
    cudaGetSymbolAddress((void**)&w22,   g_w22);
    cudaGetSymbolAddress((void**)&ffp,   g_ffp);
    cudaGetSymbolAddress((void**)&qkv2,  g_qkv2);
    cudaGetSymbolAddress((void**)&vt2,   g_vt2);
    cudaGetSymbolAddress((void**)&px,    g_px);
    cudaGetSymbolAddress((void**)&pa,    g_pa);
    cudaGetSymbolAddress((void**)&pt1,   g_pt1);
    cudaGetSymbolAddress((void**)&pxs,   g_pxs);

    cudaFuncSetAttribute(attn_mma, cudaFuncAttributeMaxDynamicSharedMemorySize, ATTN_SMEM3);
    cudaFuncSetAttribute(gemm_fp16x2<0,0>, cudaFuncAttributeMaxDynamicSharedMemorySize, GEMM_SMEM_BYTES);
    cudaFuncSetAttribute(gemm_fp16x2<0,1>, cudaFuncAttributeMaxDynamicSharedMemorySize, GEMM_SMEM_BYTES);
    cudaFuncSetAttribute(gemm_fp16x2<1,1>, cudaFuncAttributeMaxDynamicSharedMemorySize, GEMM_SMEM_BYTES);

    split2(Wqkv, wqkv2, wqkv2 + WQKV_SZ, WQKV_SZ);
    split2(Wo,   wo2,   wo2   + WO_SZ,   WO_SZ);
    split2(W1,   w12,   w12   + W1_SZ,   W1_SZ);
    split2(W2,   w22,   w22   + W2_SZ,   W2_SZ);

    __half* qkvh = qkv2;
    __half* qkvl = qkv2 + (size_t)QKV_SZ;
    __half* vth = vt2;
    __half* vtl = vt2 + (size_t)VT_SZ;
    __half* pxh = px;
    __half* pxl = px + (size_t)XP_SZ;
    __half* pah = pa;
    __half* pal = pa + (size_t)XP_SZ;
    __half* pt1h = pt1;
    __half* pt1l = pt1 + (size_t)XP_SZ;
    __half* ffh = ffp;
    __half* ffl = ffp + (size_t)ACT_SZ;
    __half* pxsh = pxs;
    __half* pxsl = pxs + (size_t)(NSEL*D_MODEL);

    const int n4 = NTOK*D_MODEL/4;
    copy_f4<<<(n4 + 255)/256, 256>>>((const float4*)x, (float4*)gx, n4);
    split2(gx, pxh, pxl, (size_t)NTOK * D_MODEL);

    for (int L = 0; L < NLAYER; L++) {
        WP2 wq_l = { wqkv2 + (size_t)L*3*D_MODEL*D_MODEL,
                     wqkv2 + WQKV_SZ + (size_t)L*3*D_MODEL*D_MODEL };
        WP2 wo_l = { wo2 + (size_t)L*D_MODEL*D_MODEL,
                     wo2 + WO_SZ + (size_t)L*D_MODEL*D_MODEL };
        WP2 w1_l = { w12 + (size_t)L*DFF_*D_MODEL,
                     w12 + W1_SZ + (size_t)L*DFF_*D_MODEL };
        WP2 w2_l = { w22 + (size_t)L*D_MODEL*DFF_,
                     w22 + W2_SZ + (size_t)L*D_MODEL*DFF_ };
        const float* bq_l  = bqkv + (size_t)L*3*D_MODEL;
        const float* bo_l  = bo   + (size_t)L*D_MODEL;
        const float* b1_l  = b1   + (size_t)L*DFF_;
        const float* b2_l  = b2   + (size_t)L*D_MODEL;
        const float* g1_l  = g1   + (size_t)L*D_MODEL;
        const float* be1_l = be1  + (size_t)L*D_MODEL;
        const float* g2_l  = g2   + (size_t)L*D_MODEL;
        const float* be2_l = be2  + (size_t)L*D_MODEL;

        if (L & 1) {
            router_kernel<<<NTOK, 256>>>(gx, rw + (size_t)L*D_MODEL, grs);
            topk_kernel<<<BATCH, 1024>>>(grs, gsel, gw);
            gather_kernel<<<NSEL, 256>>>(gx, pxh, pxl, gsel, gxsel, pxsh, pxsl);
            run_encoder(gxsel, pxsh, pxsl, gxo, pt1h, pt1l,  /* out planes unused */
                        NSEL, KSEL, BATCH,
                        wq_l, bq_l, wo_l, bo_l, w1_l, b1_l, w2_l, b2_l,
                        g1_l, be1_l, g2_l, be2_l,
                        gt1, gt2, qkvh, qkvl, vth, vtl,
                        pah, pal, pt1h, pt1l, ffh, ffl);
            scatter_kernel<<<NSEL, 256>>>(gx, gsel, gw, gxsel, gxo);
            if (L + 1 < NLAYER)
                split2(gx, pxh, pxl, (size_t)NTOK * D_MODEL);
        } else {
            run_encoder(gx, pxh, pxl, gx, pxh, pxl, NTOK, SEQ, BATCH,
                        wq_l, bq_l, wo_l, bo_l, w1_l, b1_l, w2_l, b2_l,
                        g1_l, be1_l, g2_l, be2_l,
                        gt1, gt2, qkvh, qkvl, vth, vtl,
                        pah, pal, pt1h, pt1l, ffh, ffl);
        }
    }

    copy_f4<<<(n4 + 255)/256, 256>>>((const float4*)gx, (float4*)d_out, n4);
}

// round 15
// speedup vs baseline: 2.5282x; 1.0348x over previous
#include <cuda_runtime.h>
#include <cuda_fp16.h>
#include <math.h>
#include <stdint.h>

#define D_MODEL 1024
#define NHEAD   16
#define HDIM    64
#define DFF_    4096
#define NLAYER  6
#define BATCH   4
#define SEQ     2048
#define NTOK    (BATCH*SEQ)      /* 8192 */
#define KSEL    1024
#define NSEL    (BATCH*KSEL)     /* 4096 */

#define WQKV_SZ (NLAYER*3*D_MODEL*D_MODEL)
#define WO_SZ   (NLAYER*D_MODEL*D_MODEL)
#define W1_SZ   (NLAYER*DFF_*D_MODEL)
#define W2_SZ   (NLAYER*D_MODEL*DFF_)
#define ACT_SZ  (NTOK*DFF_)
#define QKV_SZ  (NTOK*3*D_MODEL)
#define VT_SZ   (NTOK*D_MODEL)
#define XP_SZ   (NTOK*D_MODEL)

#define LOW_SCALE   2048.0f
#define LOW_UNSCALE (1.0f/2048.0f)

// ---------------- scratch (device globals; no allocations allowed) ----------
__device__ __align__(256) float g_x   [NTOK*D_MODEL];
__device__ __align__(256) float g_xsel[NSEL*D_MODEL];
__device__ __align__(256) float g_t1  [NTOK*D_MODEL];
__device__ __align__(256) float g_t2  [NTOK*D_MODEL];
__device__ __align__(256) float g_xo  [NTOK*D_MODEL];
__device__ __align__(256) float g_rs  [BATCH*SEQ];
__device__ __align__(256) int   g_sel [BATCH*KSEL];
__device__ __align__(256) float g_w   [BATCH*KSEL];

// fp16 split-plane buffers (h, l*2048)
__device__ __align__(256) __half g_wqkv2[2][WQKV_SZ];
__device__ __align__(256) __half g_wo2  [2][WO_SZ];
__device__ __align__(256) __half g_w12  [2][W1_SZ];
__device__ __align__(256) __half g_w22  [2][W2_SZ];
__device__ __align__(256) __half g_ffp  [2][ACT_SZ];
__device__ __align__(256) __half g_qkv2 [2][QKV_SZ];
__device__ __align__(256) __half g_vt2  [2][VT_SZ];
__device__ __align__(256) __half g_px   [2][XP_SZ];
__device__ __align__(256) __half g_pa   [2][XP_SZ];
__device__ __align__(256) __half g_pt1  [2][XP_SZ];
__device__ __align__(256) __half g_pxs  [2][NSEL*D_MODEL];

// ---------------- simple float4 copy ---------------------------------------
__global__ void copy_f4(const float4* __restrict__ src, float4* __restrict__ dst, int n4) {
    int i = blockIdx.x * blockDim.x + threadIdx.x;
    if (i < n4) dst[i] = src[i];
}

// ---------------- 2-way fp16 split (low plane scaled by 2048) ----------------
__device__ __forceinline__ void split1(float v, __half& h, __half& l) {
    h = __float2half_rn(v);
    l = __float2half_rn((v - __half2float(h)) * LOW_SCALE);
}

__global__ __launch_bounds__(256)
void split2_kernel(const float* __restrict__ in,
                   __half* __restrict__ ph, __half* __restrict__ pl, int n8) {
    int i = blockIdx.x * blockDim.x + threadIdx.x;
    if (i >= n8) return;
    const float4* p = (const float4*)in + (size_t)i * 2;
    float4 x0 = p[0], x1 = p[1];
    float v[8] = {x0.x, x0.y, x0.z, x0.w, x1.x, x1.y, x1.z, x1.w};
    __align__(16) __half hh[8], ll[8];
    #pragma unroll
    for (int k = 0; k < 8; k++) split1(v[k], hh[k], ll[k]);
    *(uint4*)(ph + (size_t)i * 8) = *(uint4*)hh;
    *(uint4*)(pl + (size_t)i * 8) = *(uint4*)ll;
}

static inline void split2(const float* in, __half* h, __half* l, size_t n) {
    int n8 = (int)(n / 8);
    split2_kernel<<<(n8 + 255) / 256, 256>>>(in, h, l, n8);
}

// ---------------- V transpose: qkv fp16 planes -> VT [b*h][d][T] -------------
__global__ __launch_bounds__(256)
void vtrans_kernel(const __half* __restrict__ qh, const __half* __restrict__ ql,
                   __half* __restrict__ vth, __half* __restrict__ vtl, int T) {
    __shared__ __half sh[64][72], sl[64][72];
    const int t0 = blockIdx.x * 64, h = blockIdx.y, b = blockIdx.z;
    const int tid = threadIdx.x;
    const int row = tid >> 2;
    const int dg  = (tid & 3) * 16;

    const size_t src_off = (size_t)(b*T + t0 + row) * 3*D_MODEL + 2*D_MODEL + h*HDIM + dg;
    uint4 h0 = *(const uint4*)(qh + src_off);
    uint4 h1 = *(const uint4*)(qh + src_off + 8);
    uint4 l0 = *(const uint4*)(ql + src_off);
    uint4 l1 = *(const uint4*)(ql + src_off + 8);
    __align__(16) __half hb[16], lb[16];
    *(uint4*)&hb[0] = h0; *(uint4*)&hb[8] = h1;
    *(uint4*)&lb[0] = l0; *(uint4*)&lb[8] = l1;
    #pragma unroll
    for (int e = 0; e < 16; e++) {
        sh[dg + e][row] = hb[e];
        sl[dg + e][row] = lb[e];
    }
    __syncthreads();
    const size_t dst_off = ((size_t)((b*NHEAD + h)*HDIM + row)) * T + t0 + dg;
    *(uint4*)(vth + dst_off)     = *(uint4*)&sh[row][dg];
    *(uint4*)(vth + dst_off + 8) = *(uint4*)&sh[row][dg + 8];
    *(uint4*)(vtl + dst_off)     = *(uint4*)&sl[row][dg];
    *(uint4*)(vtl + dst_off + 8) = *(uint4*)&sl[row][dg + 8];
}

#define MMA_F16(d, a, b) \
    asm volatile("mma.sync.aligned.m16n8k16.row.col.f32.f16.f16.f32 " \
        "{%0,%1,%2,%3}, {%4,%5,%6,%7}, {%8,%9}, {%0,%1,%2,%3};" \
        : "+f"((d)[0]), "+f"((d)[1]), "+f"((d)[2]), "+f"((d)[3]) \
        : "r"((a)[0]), "r"((a)[1]), "r"((a)[2]), "r"((a)[3]), "r"((b)[0]), "r"((b)[1]))

#define LDSM4(r, addr) \
    asm volatile("ldmatrix.sync.aligned.m8n8.x4.shared.b16 {%0,%1,%2,%3}, [%4];" \
        : "=r"((r)[0]), "=r"((r)[1]), "=r"((r)[2]), "=r"((r)[3]) : "r"(addr))

__device__ __forceinline__ void cp_async16(uint32_t smem_addr, const void* gptr) {
    asm volatile("cp.async.ca.shared.global [%0], [%1], 16;" :: "r"(smem_addr), "l"(gptr));
}
#define CP_COMMIT() asm volatile("cp.async.commit_group;" ::: "memory")
#define CP_WAIT_1() asm volatile("cp.async.wait_group 1;" ::: "memory")
#define CP_WAIT_0() asm volatile("cp.async.wait_group 0;" ::: "memory")

// ---------------- fast exp on FMA pipe (no MUFU), rel err ~1.5e-6 ------------
__device__ __forceinline__ float fexp(float x) {
    x = fmaxf(x, -80.0f);
    float t  = x * 1.4426950408889634f;
    float fl = floorf(t);
    float f  = t - fl;
    float p  = 1.5252734e-5f;
    p = fmaf(p, f, 1.5403530e-4f);
    p = fmaf(p, f, 1.3333558e-3f);
    p = fmaf(p, f, 9.6181291e-3f);
    p = fmaf(p, f, 5.5504109e-2f);
    p = fmaf(p, f, 2.4022651e-1f);
    p = fmaf(p, f, 6.9314718e-1f);
    p = fmaf(p, f, 1.0f);
    int i = (int)fl;
    float sc = __int_as_float((i + 127) << 23);
    return p * sc;
}

// ---------------- fp16 2-plane split GEMM, cp.async + ldmatrix ---------------
#define BK2 32
#define SROW2 40
#define PLANE_HALVES (128*SROW2)
#define GEMM_SMEM_BYTES (2*2*2*PLANE_HALVES*2)

template<int RELU, int EMIT>
__global__ __launch_bounds__(256)
void gemm_fp16x2(const __half* __restrict__ Ah, const __half* __restrict__ Al,
                 const __half* __restrict__ Wh, const __half* __restrict__ Wl,
                 const float* __restrict__ bias, float* __restrict__ C,
                 __half* __restrict__ Ch, __half* __restrict__ Cl,
                 int N, int M, int K) {
    extern __shared__ __half smh[];
    const int t    = threadIdx.x;
    const int lane = t & 31;
    const int warp = t >> 5;
    const int wm   = warp >> 2;
    const int wn   = warp & 3;
    const int rn   = blockIdx.y * 128;
    const int cm   = blockIdx.x * 128;
    const int g    = lane >> 2;
    const int tg   = lane & 3;

    const int la_row = (lane & 7) + ((lane >> 3) & 1) * 8;
    const int la_k   = (lane >> 4) * 8;
    const int lb_row = (lane & 7);
    const int lb_jn  = (lane >> 4);
    const int lb_k   = ((lane >> 3) & 1) * 8;

    const __half* Ap[2] = { Ah, Al };
    const __half* Wp[2] = { Wh, Wl };

    const uint32_t smem_u32 = (uint32_t)__cvta_generic_to_shared(smh);
    const int c0r = t >> 2,        c0k = (t & 3) * 8;
    const int c1r = (t + 256) >> 2, c1k = ((t + 256) & 3) * 8;

    float acc1[4][4][4], acc2[4][4][4];
    #pragma unroll
    for (int i = 0; i < 4; i++)
        #pragma unroll
        for (int j = 0; j < 4; j++)
            #pragma unroll
            for (int r = 0; r < 4; r++) { acc1[i][j][r] = 0.f; acc2[i][j][r] = 0.f; }

    const int KT = K / BK2;

    auto issue_stage = [&](int buf, int k0) {
        #pragma unroll
        for (int p = 0; p < 2; p++) {
            uint32_t baseA = smem_u32 + (uint32_t)(((buf*2 + 0)*2 + p) * PLANE_HALVES) * 2;
            uint32_t baseW = smem_u32 + (uint32_t)(((buf*2 + 1)*2 + p) * PLANE_HALVES) * 2;
            cp_async16(baseA + (uint32_t)(c0r*SROW2 + c0k)*2, Ap[p] + (size_t)(rn + c0r)*K + k0 + c0k);
            cp_async16(baseA + (uint32_t)(c1r*SROW2 + c1k)*2, Ap[p] + (size_t)(rn + c1r)*K + k0 + c1k);
            cp_async16(baseW + (uint32_t)(c0r*SROW2 + c0k)*2, Wp[p] + (size_t)(cm + c0r)*K + k0 + c0k);
            cp_async16(baseW + (uint32_t)(c1r*SROW2 + c1k)*2, Wp[p] + (size_t)(cm + c1r)*K + k0 + c1k);
        }
        CP_COMMIT();
    };

    issue_stage(0, 0);

    for (int kt = 0; kt < KT; kt++) {
        const int cur = kt & 1;
        const bool more = (kt + 1) < KT;
        if (more) issue_stage(cur ^ 1, (kt + 1) * BK2);
        if (more) CP_WAIT_1(); else CP_WAIT_0();
        __syncthreads();

        const uint32_t uA0 = smem_u32 + (uint32_t)(((cur*2 + 0)*2 + 0) * PLANE_HALVES) * 2;
        const uint32_t uA1 = smem_u32 + (uint32_t)(((cur*2 + 0)*2 + 1) * PLANE_HALVES) * 2;
        const uint32_t uW0 = smem_u32 + (uint32_t)(((cur*2 + 1)*2 + 0) * PLANE_HALVES) * 2;
        const uint32_t uW1 = smem_u32 + (uint32_t)(((cur*2 + 1)*2 + 1) * PLANE_HALVES) * 2;

        #pragma unroll
        for (int ks0 = 0; ks0 < BK2; ks0 += 16) {
            uint32_t fbv[2][8];
            #pragma unroll
            for (int jp = 0; jp < 2; jp++) {
                uint32_t boff = (uint32_t)((wn*32 + jp*16 + lb_jn*8 + lb_row)*SROW2 + ks0 + lb_k) * 2;
                LDSM4(&fbv[0][jp*4], uW0 + boff);
                LDSM4(&fbv[1][jp*4], uW1 + boff);
            }
            #pragma unroll
            for (int im = 0; im < 4; im++) {
                const int r0 = wm * 64 + im * 16;
                uint32_t aoff = (uint32_t)((r0 + la_row)*SROW2 + ks0 + la_k) * 2;
                uint32_t fa[2][4];
                LDSM4(fa[0], uA0 + aoff);
                LDSM4(fa[1], uA1 + aoff);
                #pragma unroll
                for (int jn = 0; jn < 4; jn++) {
                    MMA_F16(acc1[im][jn], fa[0], &fbv[0][jn*2]);
                    MMA_F16(acc2[im][jn], fa[0], &fbv[1][jn*2]);
                    MMA_F16(acc2[im][jn], fa[1], &fbv[0][jn*2]);
                }
            }
        }
        __syncthreads();
    }

    #pragma unroll
    for (int im = 0; im < 4; im++) {
        #pragma unroll
        for (int jn = 0; jn < 4; jn++) {
            const int row = rn + wm * 64 + im * 16 + g;
            const int col = cm + wn * 32 + jn * 8 + tg * 2;
            float b0 = bias[col], b1 = bias[col + 1];
            float v0 = acc1[im][jn][0] + acc2[im][jn][0] * LOW_UNSCALE + b0;
            float v1 = acc1[im][jn][1] + acc2[im][jn][1] * LOW_UNSCALE + b1;
            float v2 = acc1[im][jn][2] + acc2[im][jn][2] * LOW_UNSCALE + b0;
            float v3 = acc1[im][jn][3] + acc2[im][jn][3] * LOW_UNSCALE + b1;
            if (RELU) {
                v0 = fmaxf(v0, 0.f); v1 = fmaxf(v1, 0.f);
                v2 = fmaxf(v2, 0.f); v3 = fmaxf(v3, 0.f);
            }
            if (EMIT == 0) {
                *(float2*)&C[(size_t)row * M + col]       = make_float2(v0, v1);
                *(float2*)&C[(size_t)(row + 8) * M + col] = make_float2(v2, v3);
            } else {
                __half h0, l0, h1, l1, h2, l2, h3, l3;
                split1(v0, h0, l0); split1(v1, h1, l1);
                split1(v2, h2, l2); split1(v3, h3, l3);
                __half2 H01; H01.x = h0; H01.y = h1;
                __half2 L01; L01.x = l0; L01.y = l1;
                __half2 H23; H23.x = h2; H23.y = h3;
                __half2 L23; L23.x = l2; L23.y = l3;
                *(__half2*)&Ch[(size_t)row * M + col]       = H01;
                *(__half2*)&Cl[(size_t)row * M + col]       = L01;
                *(__half2*)&Ch[(size_t)(row + 8) * M + col] = H23;
                *(__half2*)&Cl[(size_t)(row + 8) * M + col] = L23;
            }
        }
    }
}

// ---------------- MMA flash attention: Q-tile 128, 8 warps (4m x 2n) ---------
#define QS 72
#define SS 68
#define QPL (128*QS)    /* Q/P plane: 128 rows */
#define KPL (64*QS)     /* K/V plane: 64 rows  */
// smem halves layout: Q[2pl] | K[2buf][2pl] | V[2buf][2pl] | P[2pl] | floats
#define OFF_K  (2*QPL)
#define OFF_V  (2*QPL + 4*KPL)
#define OFF_P  (2*QPL + 8*KPL)
#define OFF_F  (4*QPL + 8*KPL)
#define ATTN_SMEM4 (OFF_F*2 + (128*SS + 3*128)*4)

__global__ __launch_bounds__(256)
void attn_mma(const __half* __restrict__ qkvh, const __half* __restrict__ qkvl,
              const __half* __restrict__ vth,  const __half* __restrict__ vtl,
              __half* __restrict__ outh, __half* __restrict__ outl, int T) {
    extern __shared__ char sm_raw[];
    __half* smh = (__half*)sm_raw;
    __half* Ph = smh + OFF_P;
    __half* Pl = smh + OFF_P + QPL;
    float*  Ssm  = (float*)(smh + OFF_F);
    float*  mrow = Ssm + 128*SS;
    float*  lrow = mrow + 128;
    float*  arow = lrow + 128;

    const int t    = threadIdx.x;
    const int lane = t & 31;
    const int warp = t >> 5;
    const int wm   = warp >> 1;      // 0..3 (32 query rows each)
    const int wn   = warp & 1;       // 0..1 (32 cols each)
    const int g    = lane >> 2;
    const int tg   = lane & 3;
    const int qt = blockIdx.x, h = blockIdx.y, b = blockIdx.z;
    const int stride3 = 3 * D_MODEL;

    const int la_row = (lane & 7) + ((lane >> 3) & 1) * 8;
    const int la_k   = (lane >> 4) * 8;
    const int lb_row = (lane & 7);
    const int lb_jn  = (lane >> 4);
    const int lb_k   = ((lane >> 3) & 1) * 8;

    const uint32_t uS = (uint32_t)__cvta_generic_to_shared(smh);
    const uint32_t uQ = uS;
    const uint32_t uK = uS + OFF_K*2;
    const uint32_t uV = uS + OFF_V*2;
    const uint32_t uP = uS + OFF_P*2;

    const __half* qp[2] = { qkvh, qkvl };
    const __half* vp[2] = { vth,  vtl  };

    // prologue: Q tile 128x64, 2 planes = 2048 16B-chunks, 8 per thread
    {
        #pragma unroll
        for (int i = 0; i < 8; i++) {
            int c = t + 256*i;
            int plane = c >> 10, rem = c & 1023, row = rem >> 3, ch = (rem & 7) * 8;
            const __half* qg = qp[plane] + (size_t)(b*T + qt*128 + row)*stride3 + h*HDIM + ch;
            cp_async16(uQ + (uint32_t)(plane*QPL + row*QS + ch)*2, qg);
        }
    }
    auto issue_kv = [&](int buf, int kt) {
        #pragma unroll
        for (int i = 0; i < 4; i++) {
            int c = t + 256*i;
            int plane = c >> 9, rem = c & 511, row = rem >> 3, ch = (rem & 7) * 8;
            const __half* kg = qp[plane] + (size_t)(b*T + kt*64 + row)*stride3 + D_MODEL + h*HDIM + ch;
            cp_async16(uK + (uint32_t)((buf*2 + plane)*KPL + row*QS + ch)*2, kg);
            const __half* vg = vp[plane] + ((size_t)((b*NHEAD + h)*HDIM + row))*T + kt*64 + ch;
            cp_async16(uV + (uint32_t)((buf*2 + plane)*KPL + row*QS + ch)*2, vg);
        }
        CP_COMMIT();
    };
    issue_kv(0, 0);

    if (t < 128) { mrow[t] = -1e30f; lrow[t] = 0.f; }

    float o1[2][4][4], o2[2][4][4];
    #pragma unroll
    for (int i = 0; i < 2; i++)
        #pragma unroll
        for (int j = 0; j < 4; j++)
            #pragma unroll
            for (int r = 0; r < 4; r++) { o1[i][j][r] = 0.f; o2[i][j][r] = 0.f; }

    const int nkt = T / 64;
    for (int kt2 = 0; kt2 < nkt; kt2++) {
        const int cur = kt2 & 1;
        const bool more = (kt2 + 1) < nkt;
        __syncthreads();
        if (more) issue_kv(cur ^ 1, kt2 + 1);
        if (more) CP_WAIT_1(); else CP_WAIT_0();
        __syncthreads();

        const uint32_t uK0 = uK + (uint32_t)(cur*2 + 0)*KPL*2;
        const uint32_t uK1 = uK + (uint32_t)(cur*2 + 1)*KPL*2;
        const uint32_t uV0 = uV + (uint32_t)(cur*2 + 0)*KPL*2;
        const uint32_t uV1 = uV + (uint32_t)(cur*2 + 1)*KPL*2;

        // ---- S = Q K^T (split, 3 terms); warp covers 32 rows x 32 cols ----
        float s1[2][4][4], s2[2][4][4];
        #pragma unroll
        for (int i = 0; i < 2; i++)
            #pragma unroll
            for (int j = 0; j < 4; j++)
                #pragma unroll
                for (int r = 0; r < 4; r++) { s1[i][j][r] = 0.f; s2[i][j][r] = 0.f; }

        #pragma unroll
        for (int ks0 = 0; ks0 < 64; ks0 += 16) {
            uint32_t fbv[2][8];
            #pragma unroll
            for (int jp = 0; jp < 2; jp++) {
                uint32_t boff = (uint32_t)((wn*32 + jp*16 + lb_jn*8 + lb_row)*QS + ks0 + lb_k) * 2;
                LDSM4(&fbv[0][jp*4], uK0 + boff);
                LDSM4(&fbv[1][jp*4], uK1 + boff);
            }
            #pragma unroll
            for (int im = 0; im < 2; im++) {
                const int r0 = wm * 32 + im * 16;
                uint32_t aoff = (uint32_t)((r0 + la_row)*QS + ks0 + la_k) * 2;
                uint32_t fa[2][4];
                LDSM4(fa[0], uQ + aoff);
                LDSM4(fa[1], uQ + (uint32_t)QPL*2 + aoff);
                #pragma unroll
                for (int jn = 0; jn < 4; jn++) {
                    MMA_F16(s1[im][jn], fa[0], &fbv[0][jn*2]);
                    MMA_F16(s2[im][jn], fa[0], &fbv[1][jn*2]);
                    MMA_F16(s2[im][jn], fa[1], &fbv[0][jn*2]);
                }
            }
        }
        #pragma unroll
        for (int im = 0; im < 2; im++) {
            #pragma unroll
            for (int jn = 0; jn < 4; jn++) {
                const int r = wm * 32 + im * 16 + g;
                const int c = wn * 32 + jn * 8 + tg * 2;
                float v0 = (s1[im][jn][0] + s2[im][jn][0]*LOW_UNSCALE) * 0.125f;
                float v1 = (s1[im][jn][1] + s2[im][jn][1]*LOW_UNSCALE) * 0.125f;
                float v2 = (s1[im][jn][2] + s2[im][jn][2]*LOW_UNSCALE) * 0.125f;
                float v3 = (s1[im][jn][3] + s2[im][jn][3]*LOW_UNSCALE) * 0.125f;
                *(float2*)&Ssm[r*SS + c]       = make_float2(v0, v1);
                *(float2*)&Ssm[(r + 8)*SS + c] = make_float2(v2, v3);
            }
        }
        __syncthreads();

        // ---- softmax: 2 threads per row, poly exp ----
        {
            const int row = t >> 1, q4 = (t & 1) * 32;
            float vals[32];
            float mloc = -1e30f;
            #pragma unroll
            for (int j = 0; j < 32; j++) {
                vals[j] = Ssm[row*SS + q4 + j];
                mloc = fmaxf(mloc, vals[j]);
            }
            mloc = fmaxf(mloc, __shfl_xor_sync(0xFFFFFFFF, mloc, 1));
            float mo = mrow[row];
            float mn = fmaxf(mo, mloc);
            float suma = 0.f, sumb = 0.f;
            #pragma unroll
            for (int j = 0; j < 16; j++) {
                float p = fexp(vals[j] - mn);
                suma += p;
                __half hv = __float2half_rn(p);
                Ph[row*QS + q4 + j] = hv;
                Pl[row*QS + q4 + j] = __float2half_rn((p - __half2float(hv)) * LOW_SCALE);
            }
            #pragma unroll
            for (int j = 16; j < 32; j++) {
                float p = fexp(vals[j] - mn);
                sumb += p;
                __half hv = __float2half_rn(p);
                Ph[row*QS + q4 + j] = hv;
                Pl[row*QS + q4 + j] = __float2half_rn((p - __half2float(hv)) * LOW_SCALE);
            }
            float sum = suma + sumb;
            sum += __shfl_xor_sync(0xFFFFFFFF, sum, 1);
            if ((t & 1) == 0) {
                float al = fexp(mo - mn);
                mrow[row] = mn;
                lrow[row] = lrow[row]*al + sum;
                arow[row] = al;
            }
        }
        __syncthreads();

        // ---- rescale O accumulators, then O += P V ----
        #pragma unroll
        for (int im = 0; im < 2; im++) {
            const int r0 = wm * 32 + im * 16;
            float a0 = arow[r0 + g], a1 = arow[r0 + g + 8];
            #pragma unroll
            for (int jn = 0; jn < 4; jn++) {
                o1[im][jn][0] *= a0; o1[im][jn][1] *= a0;
                o1[im][jn][2] *= a1; o1[im][jn][3] *= a1;
                o2[im][jn][0] *= a0; o2[im][jn][1] *= a0;
                o2[im][jn][2] *= a1; o2[im][jn][3] *= a1;
            }
        }
        #pragma unroll
        for (int ks0 = 0; ks0 < 64; ks0 += 16) {
            uint32_t fbv[2][8];
            #pragma unroll
            for (int jp = 0; jp < 2; jp++) {
                uint32_t boff = (uint32_t)((wn*32 + jp*16 + lb_jn*8 + lb_row)*QS + ks0 + lb_k) * 2;
                LDSM4(&fbv[0][jp*4], uV0 + boff);
                LDSM4(&fbv[1][jp*4], uV1 + boff);
            }
            #pragma unroll
            for (int im = 0; im < 2; im++) {
                const int r0 = wm * 32 + im * 16;
                uint32_t aoff = (uint32_t)((r0 + la_row)*QS + ks0 + la_k) * 2;
                uint32_t fa[2][4];
                LDSM4(fa[0], uP + aoff);
                LDSM4(fa[1], uP + (uint32_t)QPL*2 + aoff);
                #pragma unroll
                for (int jn = 0; jn < 4; jn++) {
                    MMA_F16(o1[im][jn], fa[0], &fbv[0][jn*2]);
                    MMA_F16(o2[im][jn], fa[0], &fbv[1][jn*2]);
                    MMA_F16(o2[im][jn], fa[1], &fbv[0][jn*2]);
                }
            }
        }
    }
    __syncthreads();

    // ---- final: normalize, split, store planes ----
    const int n0 = b*T + qt*128;
    #pragma unroll
    for (int im = 0; im < 2; im++) {
        #pragma unroll
        for (int jn = 0; jn < 4; jn++) {
            const int r = wm * 32 + im * 16 + g;
            const int c = wn * 32 + jn * 8 + tg * 2;
            float inv0 = 1.f / lrow[r];
            float inv1 = 1.f / lrow[r + 8];
            float v0 = (o1[im][jn][0] + o2[im][jn][0]*LOW_UNSCALE) * inv0;
            float v1 = (o1[im][jn][1] + o2[im][jn][1]*LOW_UNSCALE) * inv0;
            float v2 = (o1[im][jn][2] + o2[im][jn][2]*LOW_UNSCALE) * inv1;
            float v3 = (o1[im][jn][3] + o2[im][jn][3]*LOW_UNSCALE) * inv1;
            __half h0, l0, h1, l1, h2, l2, h3, l3;
            split1(v0, h0, l0); split1(v1, h1, l1);
            split1(v2, h2, l2); split1(v3, h3, l3);
            __half2 H01; H01.x = h0; H01.y = h1;
            __half2 L01; L01.x = l0; L01.y = l1;
            __half2 H23; H23.x = h2; H23.y = h3;
            __half2 L23; L23.x = l2; L23.y = l3;
            *(__half2*)&outh[(size_t)(n0 + r)*D_MODEL + h*HDIM + c]     = H01;
            *(__half2*)&outl[(size_t)(n0 + r)*D_MODEL + h*HDIM + c]     = L01;
            *(__half2*)&outh[(size_t)(n0 + r + 8)*D_MODEL + h*HDIM + c] = H23;
            *(__half2*)&outl[(size_t)(n0 + r + 8)*D_MODEL + h*HDIM + c] = L23;
        }
    }
}

// ---------------- residual add + LayerNorm (emits fp32 + planes) -------------
__global__ __launch_bounds__(256)
void addln_kernel(const float* __restrict__ a, const float* __restrict__ r,
                  const float* __restrict__ g, const float* __restrict__ be,
                  float* __restrict__ out, __half* __restrict__ outh,
                  __half* __restrict__ outl) {
    __shared__ float rsum[256], rsq[256];
    const int n = blockIdx.x, t = threadIdx.x;
    float4 av = *(const float4*)(a + (size_t)n*D_MODEL + t*4);
    float4 rv = *(const float4*)(r + (size_t)n*D_MODEL + t*4);
    float x0 = av.x + rv.x, x1 = av.y + rv.y, x2 = av.z + rv.z, x3 = av.w + rv.w;
    rsum[t] = x0 + x1 + x2 + x3;
    rsq [t] = x0*x0 + x1*x1 + x2*x2 + x3*x3;
    __syncthreads();
    for (int off = 128; off > 0; off >>= 1) {
        if (t < off) { rsum[t] += rsum[t+off]; rsq[t] += rsq[t+off]; }
        __syncthreads();
    }
    float mu  = rsum[0] * (1.f/1024.f);
    float var = rsq[0]  * (1.f/1024.f) - mu*mu;
    float rstd = rsqrtf(var + 1e-5f);
    float4 gv = *(const float4*)(g  + t*4);
    float4 bv = *(const float4*)(be + t*4);
    float4 o;
    o.x = (x0 - mu)*rstd*gv.x + bv.x;
    o.y = (x1 - mu)*rstd*gv.y + bv.y;
    o.z = (x2 - mu)*rstd*gv.z + bv.z;
    o.w = (x3 - mu)*rstd*gv.w + bv.w;
    *(float4*)(out + (size_t)n*D_MODEL + t*4) = o;
    __align__(8) __half hh[4], ll[4];
    split1(o.x, hh[0], ll[0]); split1(o.y, hh[1], ll[1]);
    split1(o.z, hh[2], ll[2]); split1(o.w, hh[3], ll[3]);
    *(uint2*)(outh + (size_t)n*D_MODEL + t*4) = *(uint2*)hh;
    *(uint2*)(outl + (size_t)n*D_MODEL + t*4) = *(uint2*)ll;
}

// ---------------- router score ----------------------------------------------
__global__ __launch_bounds__(256)
void router_kernel(const float* __restrict__ x, const float* __restrict__ rw,
                   float* __restrict__ out) {
    __shared__ float red[256];
    const int n = blockIdx.x, t = threadIdx.x;
    float4 xv = *(const float4*)(x + (size_t)n*D_MODEL + t*4);
    float4 wv = *(const float4*)(rw + t*4);
    red[t] = xv.x*wv.x + xv.y*wv.y + xv.z*wv.z + xv.w*wv.w;
    __syncthreads();
    for (int off = 128; off > 0; off >>= 1) {
        if (t < off) red[t] += red[t+off];
        __syncthreads();
    }
    if (t == 0) out[n] = red[0];
}

// ---------------- top-k via bitonic sort (desc value, asc index) ------------
__global__ __launch_bounds__(1024)
void topk_kernel(const float* __restrict__ scores, int* __restrict__ sel,
                 float* __restrict__ wout) {
    __shared__ float v[2048];
    __shared__ int  id[2048];
    const int b = blockIdx.x, t = threadIdx.x;
    v[t]        = scores[b*SEQ + t];        id[t]        = t;
    v[t + 1024] = scores[b*SEQ + t + 1024]; id[t + 1024] = t + 1024;
    __syncthreads();
    for (int k = 2; k <= 2048; k <<= 1) {
        for (int j = k >> 1; j > 0; j >>= 1) {
            #pragma unroll
            for (int s = 0; s < 2; s++) {
                int i = t + s*1024;
                int ixj = i ^ j;
                if (ixj > i) {
                    float vi = v[i], vj = v[ixj];
                    int   ii = id[i], ij = id[ixj];
                    bool before = (vi > vj) || (vi == vj && ii < ij);
                    bool up = ((i & k) == 0);
                    bool dosw = up ? (!before) : before;
                    if (dosw) { v[i] = vj; v[ixj] = vi; id[i] = ij; id[ixj] = ii; }
                }
            }
            __syncthreads();
        }
    }
    sel [b*KSEL + t] = id[t];
    wout[b*KSEL + t] = 1.f / (1.f + expf(-v[t]));
}

// ---------------- gather (fp32 + planes) / scatter ---------------------------
__global__ __launch_bounds__(256)
void gather_kernel(const float* __restrict__ x,
                   const __half* __restrict__ xh, const __half* __restrict__ xl,
                   const int* __restrict__ sel,
                   float* __restrict__ xs,
                   __half* __restrict__ xsh, __half* __restrict__ xsl) {
    const int row = blockIdx.x;
    const int b = row >> 10;
    const int src = b*SEQ + sel[row];
    const int t = threadIdx.x;
    float4 v = *(const float4*)(x + (size_t)src*D_MODEL + t*4);
    *(float4*)(xs + (size_t)row*D_MODEL + t*4) = v;
    uint2 hv = *(const uint2*)(xh + (size_t)src*D_MODEL + t*4);
    uint2 lv = *(const uint2*)(xl + (size_t)src*D_MODEL + t*4);
    *(uint2*)(xsh + (size_t)row*D_MODEL + t*4) = hv;
    *(uint2*)(xsl + (size_t)row*D_MODEL + t*4) = lv;
}

__global__ __launch_bounds__(256)
void scatter_kernel(float* __restrict__ x, const int* __restrict__ sel,
                    const float* __restrict__ w, const float* __restrict__ xs,
                    const float* __restrict__ proc) {
    const int row = blockIdx.x;
    const int b = row >> 10;
    const int dst = b*SEQ + sel[row];
    const float wv = w[row];
    const int t = threadIdx.x;
    float4 p  = *(const float4*)(proc + (size_t)row*D_MODEL + t*4);
    float4 s  = *(const float4*)(xs   + (size_t)row*D_MODEL + t*4);
    float4 xv = *(float4*)(x + (size_t)dst*D_MODEL + t*4);
    xv.x += (p.x - s.x)*wv;
    xv.y += (p.y - s.y)*wv;
    xv.z += (p.z - s.z)*wv;
    xv.w += (p.w - s.w)*wv;
    *(float4*)(x + (size_t)dst*D_MODEL + t*4) = xv;
}

// ---------------- host-side helpers ------------------------------------------
struct WP2 { __half *h, *l; };

static void run_encoder(const float* Xin, const __half* xinh, const __half* xinl,
                        float* Xout, __half* xouth, __half* xoutl,
                        int Ncur, int Tcur, int Bcur,
                        WP2 wq, const float* bq, WP2 wo, const float* bo,
                        WP2 w1, const float* b1, WP2 w2, const float* b2,
                        const float* g1, const float* be1, const float* g2, const float* be2,
                        float* t1, float* t2,
                        __half* qkvh, __half* qkvl, __half* vth, __half* vtl,
                        __half* pah, __half* pal, __half* pt1h, __half* pt1l,
                        __half* ffh, __half* ffl) {
    gemm_fp16x2<0,1><<<dim3(3*D_MODEL/128, Ncur/128), 256, GEMM_SMEM_BYTES>>>(
        xinh, xinl, wq.h, wq.l, bq, nullptr, qkvh, qkvl, Ncur, 3*D_MODEL, D_MODEL);
    vtrans_kernel<<<dim3(Tcur/64, NHEAD, Bcur), 256>>>(qkvh, qkvl, vth, vtl, Tcur);
    attn_mma<<<dim3(Tcur/128, NHEAD, Bcur), 256, ATTN_SMEM4>>>(qkvh, qkvl, vth, vtl, pah, pal, Tcur);
    gemm_fp16x2<0,0><<<dim3(D_MODEL/128, Ncur/128), 256, GEMM_SMEM_BYTES>>>(
        pah, pal, wo.h, wo.l, bo, t2, nullptr, nullptr, Ncur, D_MODEL, D_MODEL);
    addln_kernel<<<Ncur, 256>>>(Xin, t2, g1, be1, t1, pt1h, pt1l);
    gemm_fp16x2<1,1><<<dim3(DFF_/128, Ncur/128), 256, GEMM_SMEM_BYTES>>>(
        pt1h, pt1l, w1.h, w1.l, b1, nullptr, ffh, ffl, Ncur, DFF_, D_MODEL);
    gemm_fp16x2<0,0><<<dim3(D_MODEL/128, Ncur/128), 256, GEMM_SMEM_BYTES>>>(
        ffh, ffl, w2.h, w2.l, b2, t2, nullptr, nullptr, Ncur, D_MODEL, DFF_);
    addln_kernel<<<Ncur, 256>>>(t1, t2, g2, be2, Xout, xouth, xoutl);
}

extern "C" void kernel_launch(void* const* d_in, const int* in_sizes, int n_in,
                              void* d_out, int out_size) {
    (void)in_sizes; (void)n_in; (void)out_size;
    const float* x    = (const float*)d_in[0];
    const float* Wqkv = (const float*)d_in[1];
    const float* bqkv = (const float*)d_in[2];
    const float* Wo   = (const float*)d_in[3];
    const float* bo   = (const float*)d_in[4];
    const float* W1   = (const float*)d_in[5];
    const float* b1   = (const float*)d_in[6];
    const float* W2   = (const float*)d_in[7];
    const float* b2   = (const float*)d_in[8];
    const float* g1   = (const float*)d_in[9];
    const float* be1  = (const float*)d_in[10];
    const float* g2   = (const float*)d_in[11];
    const float* be2  = (const float*)d_in[12];
    const float* rw   = (const float*)d_in[13];

    float *gx, *gxsel, *gt1, *gt2, *gxo, *grs, *gw; int* gsel;
    cudaGetSymbolAddress((void**)&gx,    g_x);
    cudaGetSymbolAddress((void**)&gxsel, g_xsel);
    cudaGetSymbolAddress((void**)&gt1,   g_t1);
    cudaGetSymbolAddress((void**)&gt2,   g_t2);
    cudaGetSymbolAddress((void**)&gxo,   g_xo);
    cudaGetSymbolAddress((void**)&grs,   g_rs);
    cudaGetSymbolAddress((void**)&gsel,  g_sel);
    cudaGetSymbolAddress((void**)&gw,    g_w);

    __half *wqkv2, *wo2, *w12, *w22, *ffp, *qkv2, *vt2, *px, *pa, *pt1, *pxs;
    cudaGetSymbolAddress((void**)&wqkv2, g_wqkv2);
    cudaGetSymbolAddress((void**)&wo2,   g_wo2);
    cudaGetSymbolAddress((void**)&w12,   g_w12);
    cudaGetSymbolAddress((void**)&w22,   g_w22);
    cudaGetSymbolAddress((void**)&ffp,   g_ffp);
    cudaGetSymbolAddress((void**)&qkv2,  g_qkv2);
    cudaGetSymbolAddress((void**)&vt2,   g_vt2);
    cudaGetSymbolAddress((void**)&px,    g_px);
    cudaGetSymbolAddress((void**)&pa,    g_pa);
    cudaGetSymbolAddress((void**)&pt1,   g_pt1);
    cudaGetSymbolAddress((void**)&pxs,   g_pxs);

    cudaFuncSetAttribute(attn_mma, cudaFuncAttributeMaxDynamicSharedMemorySize, ATTN_SMEM4);
    cudaFuncSetAttribute(gemm_fp16x2<0,0>, cudaFuncAttributeMaxDynamicSharedMemorySize, GEMM_SMEM_BYTES);
    cudaFuncSetAttribute(gemm_fp16x2<0,1>, cudaFuncAttributeMaxDynamicSharedMemorySize, GEMM_SMEM_BYTES);
    cudaFuncSetAttribute(gemm_fp16x2<1,1>, cudaFuncAttributeMaxDynamicSharedMemorySize, GEMM_SMEM_BYTES);

    split2(Wqkv, wqkv2, wqkv2 + WQKV_SZ, WQKV_SZ);
    split2(Wo,   wo2,   wo2   + WO_SZ,   WO_SZ);
    split2(W1,   w12,   w12   + W1_SZ,   W1_SZ);
    split2(W2,   w22,   w22   + W2_SZ,   W2_SZ);

    __half* qkvh = qkv2;
    __half* qkvl = qkv2 + (size_t)QKV_SZ;
    __half* vth = vt2;
    __half* vtl = vt2 + (size_t)VT_SZ;
    __half* pxh = px;
    __half* pxl = px + (size_t)XP_SZ;
    __half* pah = pa;
    __half* pal = pa + (size_t)XP_SZ;
    __half* pt1h = pt1;
    __half* pt1l = pt1 + (size_t)XP_SZ;
    __half* ffh = ffp;
    __half* ffl = ffp + (size_t)ACT_SZ;
    __half* pxsh = pxs;
    __half* pxsl = pxs + (size_t)(NSEL*D_MODEL);

    const int n4 = NTOK*D_MODEL/4;
    copy_f4<<<(n4 + 255)/256, 256>>>((const float4*)x, (float4*)gx, n4);
    split2(gx, pxh, pxl, (size_t)NTOK * D_MODEL);

    for (int L = 0; L < NLAYER; L++) {
        WP2 wq_l = { wqkv2 + (size_t)L*3*D_MODEL*D_MODEL,
                     wqkv2 + WQKV_SZ + (size_t)L*3*D_MODEL*D_MODEL };
        WP2 wo_l = { wo2 + (size_t)L*D_MODEL*D_MODEL,
                     wo2 + WO_SZ + (size_t)L*D_MODEL*D_MODEL };
        WP2 w1_l = { w12 + (size_t)L*DFF_*D_MODEL,
                     w12 + W1_SZ + (size_t)L*DFF_*D_MODEL };
        WP2 w2_l = { w22 + (size_t)L*D_MODEL*DFF_,
                     w22 + W2_SZ + (size_t)L*D_MODEL*DFF_ };
        const float* bq_l  = bqkv + (size_t)L*3*D_MODEL;
        const float* bo_l  = bo   + (size_t)L*D_MODEL;
        const float* b1_l  = b1   + (size_t)L*DFF_;
        const float* b2_l  = b2   + (size_t)L*D_MODEL;
        const float* g1_l  = g1   + (size_t)L*D_MODEL;
        const float* be1_l = be1  + (size_t)L*D_MODEL;
        const float* g2_l  = g2   + (size_t)L*D_MODEL;
        const float* be2_l = be2  + (size_t)L*D_MODEL;

        if (L & 1) {
            router_kernel<<<NTOK, 256>>>(gx, rw + (size_t)L*D_MODEL, grs);
            topk_kernel<<<BATCH, 1024>>>(grs, gsel, gw);
            gather_kernel<<<NSEL, 256>>>(gx, pxh, pxl, gsel, gxsel, pxsh, pxsl);
            run_encoder(gxsel, pxsh, pxsl, gxo, pt1h, pt1l,
                        NSEL, KSEL, BATCH,
                        wq_l, bq_l, wo_l, bo_l, w1_l, b1_l, w2_l, b2_l,
                        g1_l, be1_l, g2_l, be2_l,
                        gt1, gt2, qkvh, qkvl, vth, vtl,
                        pah, pal, pt1h, pt1l, ffh, ffl);
            scatter_kernel<<<NSEL, 256>>>(gx, gsel, gw, gxsel, gxo);
            if (L + 1 < NLAYER)
                split2(gx, pxh, pxl, (size_t)NTOK * D_MODEL);
        } else {
            run_encoder(gx, pxh, pxl, gx, pxh, pxl, NTOK, SEQ, BATCH,
                        wq_l, bq_l, wo_l, bo_l, w1_l, b1_l, w2_l, b2_l,
                        g1_l, be1_l, g2_l, be2_l,
                        gt1, gt2, qkvh, qkvl, vth, vtl,
                        pah, pal, pt1h, pt1l, ffh, ffl);
        }
    }

    copy_f4<<<(n4 + 255)/256, 256>>>((const float4*)gx, (float4*)d_out, n4);
}

// round 16
// speedup vs baseline: 2.5406x; 1.0049x over previous
#include <cuda_runtime.h>
#include <cuda_fp16.h>
#include <math.h>
#include <stdint.h>

#define D_MODEL 1024
#define NHEAD   16
#define HDIM    64
#define DFF_    4096
#define NLAYER  6
#define BATCH   4
#define SEQ     2048
#define NTOK    (BATCH*SEQ)      /* 8192 */
#define KSEL    1024
#define NSEL    (BATCH*KSEL)     /* 4096 */

#define WQKV_SZ (NLAYER*3*D_MODEL*D_MODEL)
#define WO_SZ   (NLAYER*D_MODEL*D_MODEL)
#define W1_SZ   (NLAYER*DFF_*D_MODEL)
#define W2_SZ   (NLAYER*D_MODEL*DFF_)
#define ACT_SZ  (NTOK*DFF_)
#define QKV_SZ  (NTOK*3*D_MODEL)
#define VT_SZ   (NTOK*D_MODEL)
#define XP_SZ   (NTOK*D_MODEL)

#define LOW_SCALE   2048.0f
#define LOW_UNSCALE (1.0f/2048.0f)

// ---------------- scratch (device globals; no allocations allowed) ----------
__device__ __align__(256) float g_x   [NTOK*D_MODEL];
__device__ __align__(256) float g_xsel[NSEL*D_MODEL];
__device__ __align__(256) float g_t1  [NTOK*D_MODEL];
__device__ __align__(256) float g_t2  [NTOK*D_MODEL];
__device__ __align__(256) float g_xo  [NTOK*D_MODEL];
__device__ __align__(256) float g_rs  [BATCH*SEQ];
__device__ __align__(256) int   g_sel [BATCH*KSEL];
__device__ __align__(256) float g_w   [BATCH*KSEL];

// fp16 split-plane buffers (h, l*2048)
__device__ __align__(256) __half g_wqkv2[2][WQKV_SZ];
__device__ __align__(256) __half g_wo2  [2][WO_SZ];
__device__ __align__(256) __half g_w12  [2][W1_SZ];
__device__ __align__(256) __half g_w22  [2][W2_SZ];
__device__ __align__(256) __half g_ffp  [2][ACT_SZ];
__device__ __align__(256) __half g_qkv2 [2][QKV_SZ];
__device__ __align__(256) __half g_vt2  [2][VT_SZ];
__device__ __align__(256) __half g_px   [2][XP_SZ];
__device__ __align__(256) __half g_pa   [2][XP_SZ];
__device__ __align__(256) __half g_pt1  [2][XP_SZ];
__device__ __align__(256) __half g_pxs  [2][NSEL*D_MODEL];

// ---------------- simple float4 copy ---------------------------------------
__global__ void copy_f4(const float4* __restrict__ src, float4* __restrict__ dst, int n4) {
    int i = blockIdx.x * blockDim.x + threadIdx.x;
    if (i < n4) dst[i] = src[i];
}

// ---------------- 2-way fp16 split (low plane scaled by 2048) ----------------
__device__ __forceinline__ void split1(float v, __half& h, __half& l) {
    h = __float2half_rn(v);
    l = __float2half_rn((v - __half2float(h)) * LOW_SCALE);
}

__global__ __launch_bounds__(256)
void split2_kernel(const float* __restrict__ in,
                   __half* __restrict__ ph, __half* __restrict__ pl, int n8) {
    int i = blockIdx.x * blockDim.x + threadIdx.x;
    if (i >= n8) return;
    const float4* p = (const float4*)in + (size_t)i * 2;
    float4 x0 = p[0], x1 = p[1];
    float v[8] = {x0.x, x0.y, x0.z, x0.w, x1.x, x1.y, x1.z, x1.w};
    __align__(16) __half hh[8], ll[8];
    #pragma unroll
    for (int k = 0; k < 8; k++) split1(v[k], hh[k], ll[k]);
    *(uint4*)(ph + (size_t)i * 8) = *(uint4*)hh;
    *(uint4*)(pl + (size_t)i * 8) = *(uint4*)ll;
}

static inline void split2(const float* in, __half* h, __half* l, size_t n) {
    int n8 = (int)(n / 8);
    split2_kernel<<<(n8 + 255) / 256, 256>>>(in, h, l, n8);
}

// ---------------- V transpose: qkv fp16 planes -> VT [b*h][d][T] -------------
__global__ __launch_bounds__(256)
void vtrans_kernel(const __half* __restrict__ qh, const __half* __restrict__ ql,
                   __half* __restrict__ vth, __half* __restrict__ vtl, int T) {
    __shared__ __half sh[64][72], sl[64][72];
    const int t0 = blockIdx.x * 64, h = blockIdx.y, b = blockIdx.z;
    const int tid = threadIdx.x;
    const int row = tid >> 2;
    const int dg  = (tid & 3) * 16;

    const size_t src_off = (size_t)(b*T + t0 + row) * 3*D_MODEL + 2*D_MODEL + h*HDIM + dg;
    uint4 h0 = *(const uint4*)(qh + src_off);
    uint4 h1 = *(const uint4*)(qh + src_off + 8);
    uint4 l0 = *(const uint4*)(ql + src_off);
    uint4 l1 = *(const uint4*)(ql + src_off + 8);
    __align__(16) __half hb[16], lb[16];
    *(uint4*)&hb[0] = h0; *(uint4*)&hb[8] = h1;
    *(uint4*)&lb[0] = l0; *(uint4*)&lb[8] = l1;
    #pragma unroll
    for (int e = 0; e < 16; e++) {
        sh[dg + e][row] = hb[e];
        sl[dg + e][row] = lb[e];
    }
    __syncthreads();
    const size_t dst_off = ((size_t)((b*NHEAD + h)*HDIM + row)) * T + t0 + dg;
    *(uint4*)(vth + dst_off)     = *(uint4*)&sh[row][dg];
    *(uint4*)(vth + dst_off + 8) = *(uint4*)&sh[row][dg + 8];
    *(uint4*)(vtl + dst_off)     = *(uint4*)&sl[row][dg];
    *(uint4*)(vtl + dst_off + 8) = *(uint4*)&sl[row][dg + 8];
}

#define MMA_F16(d, a, b) \
    asm volatile("mma.sync.aligned.m16n8k16.row.col.f32.f16.f16.f32 " \
        "{%0,%1,%2,%3}, {%4,%5,%6,%7}, {%8,%9}, {%0,%1,%2,%3};" \
        : "+f"((d)[0]), "+f"((d)[1]), "+f"((d)[2]), "+f"((d)[3]) \
        : "r"((a)[0]), "r"((a)[1]), "r"((a)[2]), "r"((a)[3]), "r"((b)[0]), "r"((b)[1]))

#define LDSM4(r, addr) \
    asm volatile("ldmatrix.sync.aligned.m8n8.x4.shared.b16 {%0,%1,%2,%3}, [%4];" \
        : "=r"((r)[0]), "=r"((r)[1]), "=r"((r)[2]), "=r"((r)[3]) : "r"(addr))

__device__ __forceinline__ void cp_async16(uint32_t smem_addr, const void* gptr) {
    asm volatile("cp.async.ca.shared.global [%0], [%1], 16;" :: "r"(smem_addr), "l"(gptr));
}
#define CP_COMMIT() asm volatile("cp.async.commit_group;" ::: "memory")
#define CP_WAIT_1() asm volatile("cp.async.wait_group 1;" ::: "memory")
#define CP_WAIT_0() asm volatile("cp.async.wait_group 0;" ::: "memory")

// ---------------- fast exp on FMA pipe (no MUFU), rel err ~1.5e-6 ------------
__device__ __forceinline__ float fexp(float x) {
    x = fmaxf(x, -80.0f);
    float t  = x * 1.4426950408889634f;
    float fl = floorf(t);
    float f  = t - fl;
    float p  = 1.5252734e-5f;
    p = fmaf(p, f, 1.5403530e-4f);
    p = fmaf(p, f, 1.3333558e-3f);
    p = fmaf(p, f, 9.6181291e-3f);
    p = fmaf(p, f, 5.5504109e-2f);
    p = fmaf(p, f, 2.4022651e-1f);
    p = fmaf(p, f, 6.9314718e-1f);
    p = fmaf(p, f, 1.0f);
    int i = (int)fl;
    float sc = __int_as_float((i + 127) << 23);
    return p * sc;
}

// ---------------- fp16 2-plane split GEMM, 3-stage cp.async + ldmatrix -------
#define BK2 32
#define SROW2 40
#define PLANE_HALVES (128*SROW2)
#define GEMM_SMEM_BYTES (3*2*2*PLANE_HALVES*2)

template<int RELU, int EMIT>
__global__ __launch_bounds__(256)
void gemm_fp16x2(const __half* __restrict__ Ah, const __half* __restrict__ Al,
                 const __half* __restrict__ Wh, const __half* __restrict__ Wl,
                 const float* __restrict__ bias, float* __restrict__ C,
                 __half* __restrict__ Ch, __half* __restrict__ Cl,
                 int N, int M, int K) {
    extern __shared__ __half smh[];
    const int t    = threadIdx.x;
    const int lane = t & 31;
    const int warp = t >> 5;
    const int wm   = warp >> 2;
    const int wn   = warp & 3;
    const int rn   = blockIdx.y * 128;
    const int cm   = blockIdx.x * 128;
    const int g    = lane >> 2;
    const int tg   = lane & 3;

    const int la_row = (lane & 7) + ((lane >> 3) & 1) * 8;
    const int la_k   = (lane >> 4) * 8;
    const int lb_row = (lane & 7);
    const int lb_jn  = (lane >> 4);
    const int lb_k   = ((lane >> 3) & 1) * 8;

    const __half* Ap[2] = { Ah, Al };
    const __half* Wp[2] = { Wh, Wl };

    const uint32_t smem_u32 = (uint32_t)__cvta_generic_to_shared(smh);
    const int c0r = t >> 2,        c0k = (t & 3) * 8;
    const int c1r = (t + 256) >> 2, c1k = ((t + 256) & 3) * 8;

    float acc1[4][4][4], acc2[4][4][4];
    #pragma unroll
    for (int i = 0; i < 4; i++)
        #pragma unroll
        for (int j = 0; j < 4; j++)
            #pragma unroll
            for (int r = 0; r < 4; r++) { acc1[i][j][r] = 0.f; acc2[i][j][r] = 0.f; }

    const int KT = K / BK2;

    auto issue_stage = [&](int buf, int k0) {
        #pragma unroll
        for (int p = 0; p < 2; p++) {
            uint32_t baseA = smem_u32 + (uint32_t)(((buf*2 + 0)*2 + p) * PLANE_HALVES) * 2;
            uint32_t baseW = smem_u32 + (uint32_t)(((buf*2 + 1)*2 + p) * PLANE_HALVES) * 2;
            cp_async16(baseA + (uint32_t)(c0r*SROW2 + c0k)*2, Ap[p] + (size_t)(rn + c0r)*K + k0 + c0k);
            cp_async16(baseA + (uint32_t)(c1r*SROW2 + c1k)*2, Ap[p] + (size_t)(rn + c1r)*K + k0 + c1k);
            cp_async16(baseW + (uint32_t)(c0r*SROW2 + c0k)*2, Wp[p] + (size_t)(cm + c0r)*K + k0 + c0k);
            cp_async16(baseW + (uint32_t)(c1r*SROW2 + c1k)*2, Wp[p] + (size_t)(cm + c1r)*K + k0 + c1k);
        }
        CP_COMMIT();
    };

    // 3-stage prologue: two stages in flight
    issue_stage(0, 0);
    issue_stage(1, BK2);

    int cur = 0;
    for (int kt = 0; kt < KT; kt++) {
        // wait for stage kt (leave at most the next stage pending)
        if (kt + 1 < KT) CP_WAIT_1(); else CP_WAIT_0();
        __syncthreads();   // all data visible; all readers of buffer (kt-1)%3 done
        if (kt + 2 < KT) issue_stage((cur + 2 >= 3) ? cur - 1 : cur + 2, (kt + 2) * BK2);

        const uint32_t uA0 = smem_u32 + (uint32_t)(((cur*2 + 0)*2 + 0) * PLANE_HALVES) * 2;
        const uint32_t uA1 = smem_u32 + (uint32_t)(((cur*2 + 0)*2 + 1) * PLANE_HALVES) * 2;
        const uint32_t uW0 = smem_u32 + (uint32_t)(((cur*2 + 1)*2 + 0) * PLANE_HALVES) * 2;
        const uint32_t uW1 = smem_u32 + (uint32_t)(((cur*2 + 1)*2 + 1) * PLANE_HALVES) * 2;

        #pragma unroll
        for (int ks0 = 0; ks0 < BK2; ks0 += 16) {
            uint32_t fbv[2][8];
            #pragma unroll
            for (int jp = 0; jp < 2; jp++) {
                uint32_t boff = (uint32_t)((wn*32 + jp*16 + lb_jn*8 + lb_row)*SROW2 + ks0 + lb_k) * 2;
                LDSM4(&fbv[0][jp*4], uW0 + boff);
                LDSM4(&fbv[1][jp*4], uW1 + boff);
            }
            #pragma unroll
            for (int im = 0; im < 4; im++) {
                const int r0 = wm * 64 + im * 16;
                uint32_t aoff = (uint32_t)((r0 + la_row)*SROW2 + ks0 + la_k) * 2;
                uint32_t fa[2][4];
                LDSM4(fa[0], uA0 + aoff);
                LDSM4(fa[1], uA1 + aoff);
                #pragma unroll
                for (int jn = 0; jn < 4; jn++) {
                    MMA_F16(acc1[im][jn], fa[0], &fbv[0][jn*2]);
                    MMA_F16(acc2[im][jn], fa[0], &fbv[1][jn*2]);
                    MMA_F16(acc2[im][jn], fa[1], &fbv[0][jn*2]);
                }
            }
        }
        cur = (cur + 1 == 3) ? 0 : cur + 1;
    }
    __syncthreads();

    #pragma unroll
    for (int im = 0; im < 4; im++) {
        #pragma unroll
        for (int jn = 0; jn < 4; jn++) {
            const int row = rn + wm * 64 + im * 16 + g;
            const int col = cm + wn * 32 + jn * 8 + tg * 2;
            float b0 = bias[col], b1 = bias[col + 1];
            float v0 = acc1[im][jn][0] + acc2[im][jn][0] * LOW_UNSCALE + b0;
            float v1 = acc1[im][jn][1] + acc2[im][jn][1] * LOW_UNSCALE + b1;
            float v2 = acc1[im][jn][2] + acc2[im][jn][2] * LOW_UNSCALE + b0;
            float v3 = acc1[im][jn][3] + acc2[im][jn][3] * LOW_UNSCALE + b1;
            if (RELU) {
                v0 = fmaxf(v0, 0.f); v1 = fmaxf(v1, 0.f);
                v2 = fmaxf(v2, 0.f); v3 = fmaxf(v3, 0.f);
            }
            if (EMIT == 0) {
                *(float2*)&C[(size_t)row * M + col]       = make_float2(v0, v1);
                *(float2*)&C[(size_t)(row + 8) * M + col] = make_float2(v2, v3);
            } else {
                __half h0, l0, h1, l1, h2, l2, h3, l3;
                split1(v0, h0, l0); split1(v1, h1, l1);
                split1(v2, h2, l2); split1(v3, h3, l3);
                __half2 H01; H01.x = h0; H01.y = h1;
                __half2 L01; L01.x = l0; L01.y = l1;
                __half2 H23; H23.x = h2; H23.y = h3;
                __half2 L23; L23.x = l2; L23.y = l3;
                *(__half2*)&Ch[(size_t)row * M + col]       = H01;
                *(__half2*)&Cl[(size_t)row * M + col]       = L01;
                *(__half2*)&Ch[(size_t)(row + 8) * M + col] = H23;
                *(__half2*)&Cl[(size_t)(row + 8) * M + col] = L23;
            }
        }
    }
}

// ---------------- MMA flash attention: Q-tile 128, 8 warps (4m x 2n) ---------
#define QS 72
#define SS 68
#define QPL (128*QS)
#define KPL (64*QS)
#define OFF_K  (2*QPL)
#define OFF_V  (2*QPL + 4*KPL)
#define OFF_P  (2*QPL + 8*KPL)
#define OFF_F  (4*QPL + 8*KPL)
#define ATTN_SMEM4 (OFF_F*2 + (128*SS + 3*128)*4)

__global__ __launch_bounds__(256)
void attn_mma(const __half* __restrict__ qkvh, const __half* __restrict__ qkvl,
              const __half* __restrict__ vth,  const __half* __restrict__ vtl,
              __half* __restrict__ outh, __half* __restrict__ outl, int T) {
    extern __shared__ char sm_raw[];
    __half* smh = (__half*)sm_raw;
    __half* Ph = smh + OFF_P;
    __half* Pl = smh + OFF_P + QPL;
    float*  Ssm  = (float*)(smh + OFF_F);
    float*  mrow = Ssm + 128*SS;
    float*  lrow = mrow + 128;
    float*  arow = lrow + 128;

    const int t    = threadIdx.x;
    const int lane = t & 31;
    const int warp = t >> 5;
    const int wm   = warp >> 1;
    const int wn   = warp & 1;
    const int g    = lane >> 2;
    const int tg   = lane & 3;
    const int qt = blockIdx.x, h = blockIdx.y, b = blockIdx.z;
    const int stride3 = 3 * D_MODEL;

    const int la_row = (lane & 7) + ((lane >> 3) & 1) * 8;
    const int la_k   = (lane >> 4) * 8;
    const int lb_row = (lane & 7);
    const int lb_jn  = (lane >> 4);
    const int lb_k   = ((lane >> 3) & 1) * 8;

    const uint32_t uS = (uint32_t)__cvta_generic_to_shared(smh);
    const uint32_t uQ = uS;
    const uint32_t uK = uS + OFF_K*2;
    const uint32_t uV = uS + OFF_V*2;
    const uint32_t uP = uS + OFF_P*2;

    const __half* qp[2] = { qkvh, qkvl };
    const __half* vp[2] = { vth,  vtl  };

    {
        #pragma unroll
        for (int i = 0; i < 8; i++) {
            int c = t + 256*i;
            int plane = c >> 10, rem = c & 1023, row = rem >> 3, ch = (rem & 7) * 8;
            const __half* qg = qp[plane] + (size_t)(b*T + qt*128 + row)*stride3 + h*HDIM + ch;
            cp_async16(uQ + (uint32_t)(plane*QPL + row*QS + ch)*2, qg);
        }
    }
    auto issue_kv = [&](int buf, int kt) {
        #pragma unroll
        for (int i = 0; i < 4; i++) {
            int c = t + 256*i;
            int plane = c >> 9, rem = c & 511, row = rem >> 3, ch = (rem & 7) * 8;
            const __half* kg = qp[plane] + (size_t)(b*T + kt*64 + row)*stride3 + D_MODEL + h*HDIM + ch;
            cp_async16(uK + (uint32_t)((buf*2 + plane)*KPL + row*QS + ch)*2, kg);
            const __half* vg = vp[plane] + ((size_t)((b*NHEAD + h)*HDIM + row))*T + kt*64 + ch;
            cp_async16(uV + (uint32_t)((buf*2 + plane)*KPL + row*QS + ch)*2, vg);
        }
        CP_COMMIT();
    };
    issue_kv(0, 0);

    if (t < 128) { mrow[t] = -1e30f; lrow[t] = 0.f; }

    float o1[2][4][4], o2[2][4][4];
    #pragma unroll
    for (int i = 0; i < 2; i++)
        #pragma unroll
        for (int j = 0; j < 4; j++)
            #pragma unroll
            for (int r = 0; r < 4; r++) { o1[i][j][r] = 0.f; o2[i][j][r] = 0.f; }

    const int nkt = T / 64;
    for (int kt2 = 0; kt2 < nkt; kt2++) {
        const int cur = kt2 & 1;
        const bool more = (kt2 + 1) < nkt;
        __syncthreads();
        if (more) issue_kv(cur ^ 1, kt2 + 1);
        if (more) CP_WAIT_1(); else CP_WAIT_0();
        __syncthreads();

        const uint32_t uK0 = uK + (uint32_t)(cur*2 + 0)*KPL*2;
        const uint32_t uK1 = uK + (uint32_t)(cur*2 + 1)*KPL*2;
        const uint32_t uV0 = uV + (uint32_t)(cur*2 + 0)*KPL*2;
        const uint32_t uV1 = uV + (uint32_t)(cur*2 + 1)*KPL*2;

        float s1[2][4][4], s2[2][4][4];
        #pragma unroll
        for (int i = 0; i < 2; i++)
            #pragma unroll
            for (int j = 0; j < 4; j++)
                #pragma unroll
                for (int r = 0; r < 4; r++) { s1[i][j][r] = 0.f; s2[i][j][r] = 0.f; }

        #pragma unroll
        for (int ks0 = 0; ks0 < 64; ks0 += 16) {
            uint32_t fbv[2][8];
            #pragma unroll
            for (int jp = 0; jp < 2; jp++) {
                uint32_t boff = (uint32_t)((wn*32 + jp*16 + lb_jn*8 + lb_row)*QS + ks0 + lb_k) * 2;
                LDSM4(&fbv[0][jp*4], uK0 + boff);
                LDSM4(&fbv[1][jp*4], uK1 + boff);
            }
            #pragma unroll
            for (int im = 0; im < 2; im++) {
                const int r0 = wm * 32 + im * 16;
                uint32_t aoff = (uint32_t)((r0 + la_row)*QS + ks0 + la_k) * 2;
                uint32_t fa[2][4];
                LDSM4(fa[0], uQ + aoff);
                LDSM4(fa[1], uQ + (uint32_t)QPL*2 + aoff);
                #pragma unroll
                for (int jn = 0; jn < 4; jn++) {
                    MMA_F16(s1[im][jn], fa[0], &fbv[0][jn*2]);
                    MMA_F16(s2[im][jn], fa[0], &fbv[1][jn*2]);
                    MMA_F16(s2[im][jn], fa[1], &fbv[0][jn*2]);
                }
            }
        }
        #pragma unroll
        for (int im = 0; im < 2; im++) {
            #pragma unroll
            for (int jn = 0; jn < 4; jn++) {
                const int r = wm * 32 + im * 16 + g;
                const int c = wn * 32 + jn * 8 + tg * 2;
                float v0 = (s1[im][jn][0] + s2[im][jn][0]*LOW_UNSCALE) * 0.125f;
                float v1 = (s1[im][jn][1] + s2[im][jn][1]*LOW_UNSCALE) * 0.125f;
                float v2 = (s1[im][jn][2] + s2[im][jn][2]*LOW_UNSCALE) * 0.125f;
                float v3 = (s1[im][jn][3] + s2[im][jn][3]*LOW_UNSCALE) * 0.125f;
                *(float2*)&Ssm[r*SS + c]       = make_float2(v0, v1);
                *(float2*)&Ssm[(r + 8)*SS + c] = make_float2(v2, v3);
            }
        }
        __syncthreads();

        {
            const int row = t >> 1, q4 = (t & 1) * 32;
            float vals[32];
            float mloc = -1e30f;
            #pragma unroll
            for (int j = 0; j < 32; j++) {
                vals[j] = Ssm[row*SS + q4 + j];
                mloc = fmaxf(mloc, vals[j]);
            }
            mloc = fmaxf(mloc, __shfl_xor_sync(0xFFFFFFFF, mloc, 1));
            float mo = mrow[row];
            float mn = fmaxf(mo, mloc);
            float suma = 0.f, sumb = 0.f;
            #pragma unroll
            for (int j = 0; j < 16; j++) {
                float p = fexp(vals[j] - mn);
                suma += p;
                __half hv = __float2half_rn(p);
                Ph[row*QS + q4 + j] = hv;
                Pl[row*QS + q4 + j] = __float2half_rn((p - __half2float(hv)) * LOW_SCALE);
            }
            #pragma unroll
            for (int j = 16; j < 32; j++) {
                float p = fexp(vals[j] - mn);
                sumb += p;
                __half hv = __float2half_rn(p);
                Ph[row*QS + q4 + j] = hv;
                Pl[row*QS + q4 + j] = __float2half_rn((p - __half2float(hv)) * LOW_SCALE);
            }
            float sum = suma + sumb;
            sum += __shfl_xor_sync(0xFFFFFFFF, sum, 1);
            if ((t & 1) == 0) {
                float al = fexp(mo - mn);
                mrow[row] = mn;
                lrow[row] = lrow[row]*al + sum;
                arow[row] = al;
            }
        }
        __syncthreads();

        #pragma unroll
        for (int im = 0; im < 2; im++) {
            const int r0 = wm * 32 + im * 16;
            float a0 = arow[r0 + g], a1 = arow[r0 + g + 8];
            #pragma unroll
            for (int jn = 0; jn < 4; jn++) {
                o1[im][jn][0] *= a0; o1[im][jn][1] *= a0;
                o1[im][jn][2] *= a1; o1[im][jn][3] *= a1;
                o2[im][jn][0] *= a0; o2[im][jn][1] *= a0;
                o2[im][jn][2] *= a1; o2[im][jn][3] *= a1;
            }
        }
        #pragma unroll
        for (int ks0 = 0; ks0 < 64; ks0 += 16) {
            uint32_t fbv[2][8];
            #pragma unroll
            for (int jp = 0; jp < 2; jp++) {
                uint32_t boff = (uint32_t)((wn*32 + jp*16 + lb_jn*8 + lb_row)*QS + ks0 + lb_k) * 2;
                LDSM4(&fbv[0][jp*4], uV0 + boff);
                LDSM4(&fbv[1][jp*4], uV1 + boff);
            }
            #pragma unroll
            for (int im = 0; im < 2; im++) {
                const int r0 = wm * 32 + im * 16;
                uint32_t aoff = (uint32_t)((r0 + la_row)*QS + ks0 + la_k) * 2;
                uint32_t fa[2][4];
                LDSM4(fa[0], uP + aoff);
                LDSM4(fa[1], uP + (uint32_t)QPL*2 + aoff);
                #pragma unroll
                for (int jn = 0; jn < 4; jn++) {
                    MMA_F16(o1[im][jn], fa[0], &fbv[0][jn*2]);
                    MMA_F16(o2[im][jn], fa[0], &fbv[1][jn*2]);
                    MMA_F16(o2[im][jn], fa[1], &fbv[0][jn*2]);
                }
            }
        }
    }
    __syncthreads();

    const int n0 = b*T + qt*128;
    #pragma unroll
    for (int im = 0; im < 2; im++) {
        #pragma unroll
        for (int jn = 0; jn < 4; jn++) {
            const int r = wm * 32 + im * 16 + g;
            const int c = wn * 32 + jn * 8 + tg * 2;
            float inv0 = 1.f / lrow[r];
            float inv1 = 1.f / lrow[r + 8];
            float v0 = (o1[im][jn][0] + o2[im][jn][0]*LOW_UNSCALE) * inv0;
            float v1 = (o1[im][jn][1] + o2[im][jn][1]*LOW_UNSCALE) * inv0;
            float v2 = (o1[im][jn][2] + o2[im][jn][2]*LOW_UNSCALE) * inv1;
            float v3 = (o1[im][jn][3] + o2[im][jn][3]*LOW_UNSCALE) * inv1;
            __half h0, l0, h1, l1, h2, l2, h3, l3;
            split1(v0, h0, l0); split1(v1, h1, l1);
            split1(v2, h2, l2); split1(v3, h3, l3);
            __half2 H01; H01.x = h0; H01.y = h1;
            __half2 L01; L01.x = l0; L01.y = l1;
            __half2 H23; H23.x = h2; H23.y = h3;
            __half2 L23; L23.x = l2; L23.y = l3;
            *(__half2*)&outh[(size_t)(n0 + r)*D_MODEL + h*HDIM + c]     = H01;
            *(__half2*)&outl[(size_t)(n0 + r)*D_MODEL + h*HDIM + c]     = L01;
            *(__half2*)&outh[(size_t)(n0 + r + 8)*D_MODEL + h*HDIM + c] = H23;
            *(__half2*)&outl[(size_t)(n0 + r + 8)*D_MODEL + h*HDIM + c] = L23;
        }
    }
}

// ---------------- residual add + LayerNorm (emits fp32 + planes) -------------
__global__ __launch_bounds__(256)
void addln_kernel(const float* __restrict__ a, const float* __restrict__ r,
                  const float* __restrict__ g, const float* __restrict__ be,
                  float* __restrict__ out, __half* __restrict__ outh,
                  __half* __restrict__ outl) {
    __shared__ float rsum[256], rsq[256];
    const int n = blockIdx.x, t = threadIdx.x;
    float4 av = *(const float4*)(a + (size_t)n*D_MODEL + t*4);
    float4 rv = *(const float4*)(r + (size_t)n*D_MODEL + t*4);
    float x0 = av.x + rv.x, x1 = av.y + rv.y, x2 = av.z + rv.z, x3 = av.w + rv.w;
    rsum[t] = x0 + x1 + x2 + x3;
    rsq [t] = x0*x0 + x1*x1 + x2*x2 + x3*x3;
    __syncthreads();
    for (int off = 128; off > 0; off >>= 1) {
        if (t < off) { rsum[t] += rsum[t+off]; rsq[t] += rsq[t+off]; }
        __syncthreads();
    }
    float mu  = rsum[0] * (1.f/1024.f);
    float var = rsq[0]  * (1.f/1024.f) - mu*mu;
    float rstd = rsqrtf(var + 1e-5f);
    float4 gv = *(const float4*)(g  + t*4);
    float4 bv = *(const float4*)(be + t*4);
    float4 o;
    o.x = (x0 - mu)*rstd*gv.x + bv.x;
    o.y = (x1 - mu)*rstd*gv.y + bv.y;
    o.z = (x2 - mu)*rstd*gv.z + bv.z;
    o.w = (x3 - mu)*rstd*gv.w + bv.w;
    *(float4*)(out + (size_t)n*D_MODEL + t*4) = o;
    __align__(8) __half hh[4], ll[4];
    split1(o.x, hh[0], ll[0]); split1(o.y, hh[1], ll[1]);
    split1(o.z, hh[2], ll[2]); split1(o.w, hh[3], ll[3]);
    *(uint2*)(outh + (size_t)n*D_MODEL + t*4) = *(uint2*)hh;
    *(uint2*)(outl + (size_t)n*D_MODEL + t*4) = *(uint2*)ll;
}

// ---------------- router score ----------------------------------------------
__global__ __launch_bounds__(256)
void router_kernel(const float* __restrict__ x, const float* __restrict__ rw,
                   float* __restrict__ out) {
    __shared__ float red[256];
    const int n = blockIdx.x, t = threadIdx.x;
    float4 xv = *(const float4*)(x + (size_t)n*D_MODEL + t*4);
    float4 wv = *(const float4*)(rw + t*4);
    red[t] = xv.x*wv.x + xv.y*wv.y + xv.z*wv.z + xv.w*wv.w;
    __syncthreads();
    for (int off = 128; off > 0; off >>= 1) {
        if (t < off) red[t] += red[t+off];
        __syncthreads();
    }
    if (t == 0) out[n] = red[0];
}

// ---------------- top-k via bitonic sort (desc value, asc index) ------------
__global__ __launch_bounds__(1024)
void topk_kernel(const float* __restrict__ scores, int* __restrict__ sel,
                 float* __restrict__ wout) {
    __shared__ float v[2048];
    __shared__ int  id[2048];
    const int b = blockIdx.x, t = threadIdx.x;
    v[t]        = scores[b*SEQ + t];        id[t]        = t;
    v[t + 1024] = scores[b*SEQ + t + 1024]; id[t + 1024] = t + 1024;
    __syncthreads();
    for (int k = 2; k <= 2048; k <<= 1) {
        for (int j = k >> 1; j > 0; j >>= 1) {
            #pragma unroll
            for (int s = 0; s < 2; s++) {
                int i = t + s*1024;
                int ixj = i ^ j;
                if (ixj > i) {
                    float vi = v[i], vj = v[ixj];
                    int   ii = id[i], ij = id[ixj];
                    bool before = (vi > vj) || (vi == vj && ii < ij);
                    bool up = ((i & k) == 0);
                    bool dosw = up ? (!before) : before;
                    if (dosw) { v[i] = vj; v[ixj] = vi; id[i] = ij; id[ixj] = ii; }
                }
            }
            __syncthreads();
        }
    }
    sel [b*KSEL + t] = id[t];
    wout[b*KSEL + t] = 1.f / (1.f + expf(-v[t]));
}

// ---------------- gather (fp32 + planes) / scatter ---------------------------
__global__ __launch_bounds__(256)
void gather_kernel(const float* __restrict__ x,
                   const __half* __restrict__ xh, const __half* __restrict__ xl,
                   const int* __restrict__ sel,
                   float* __restrict__ xs,
                   __half* __restrict__ xsh, __half* __restrict__ xsl) {
    const int row = blockIdx.x;
    const int b = row >> 10;
    const int src = b*SEQ + sel[row];
    const int t = threadIdx.x;
    float4 v = *(const float4*)(x + (size_t)src*D_MODEL + t*4);
    *(float4*)(xs + (size_t)row*D_MODEL + t*4) = v;
    uint2 hv = *(const uint2*)(xh + (size_t)src*D_MODEL + t*4);
    uint2 lv = *(const uint2*)(xl + (size_t)src*D_MODEL + t*4);
    *(uint2*)(xsh + (size_t)row*D_MODEL + t*4) = hv;
    *(uint2*)(xsl + (size_t)row*D_MODEL + t*4) = lv;
}

__global__ __launch_bounds__(256)
void scatter_kernel(float* __restrict__ x, const int* __restrict__ sel,
                    const float* __restrict__ w, const float* __restrict__ xs,
                    const float* __restrict__ proc) {
    const int row = blockIdx.x;
    const int b = row >> 10;
    const int dst = b*SEQ + sel[row];
    const float wv = w[row];
    const int t = threadIdx.x;
    float4 p  = *(const float4*)(proc + (size_t)row*D_MODEL + t*4);
    float4 s  = *(const float4*)(xs   + (size_t)row*D_MODEL + t*4);
    float4 xv = *(float4*)(x + (size_t)dst*D_MODEL + t*4);
    xv.x += (p.x - s.x)*wv;
    xv.y += (p.y - s.y)*wv;
    xv.z += (p.z - s.z)*wv;
    xv.w += (p.w - s.w)*wv;
    *(float4*)(x + (size_t)dst*D_MODEL + t*4) = xv;
}

// ---------------- host-side helpers ------------------------------------------
struct WP2 { __half *h, *l; };

static void run_encoder(const float* Xin, const __half* xinh, const __half* xinl,
                        float* Xout, __half* xouth, __half* xoutl,
                        int Ncur, int Tcur, int Bcur,
                        WP2 wq, const float* bq, WP2 wo, const float* bo,
                        WP2 w1, const float* b1, WP2 w2, const float* b2,
                        const float* g1, const float* be1, const float* g2, const float* be2,
                        float* t1, float* t2,
                        __half* qkvh, __half* qkvl, __half* vth, __half* vtl,
                        __half* pah, __half* pal, __half* pt1h, __half* pt1l,
                        __half* ffh, __half* ffl) {
    gemm_fp16x2<0,1><<<dim3(3*D_MODEL/128, Ncur/128), 256, GEMM_SMEM_BYTES>>>(
        xinh, xinl, wq.h, wq.l, bq, nullptr, qkvh, qkvl, Ncur, 3*D_MODEL, D_MODEL);
    vtrans_kernel<<<dim3(Tcur/64, NHEAD, Bcur), 256>>>(qkvh, qkvl, vth, vtl, Tcur);
    attn_mma<<<dim3(Tcur/128, NHEAD, Bcur), 256, ATTN_SMEM4>>>(qkvh, qkvl, vth, vtl, pah, pal, Tcur);
    gemm_fp16x2<0,0><<<dim3(D_MODEL/128, Ncur/128), 256, GEMM_SMEM_BYTES>>>(
        pah, pal, wo.h, wo.l, bo, t2, nullptr, nullptr, Ncur, D_MODEL, D_MODEL);
    addln_kernel<<<Ncur, 256>>>(Xin, t2, g1, be1, t1, pt1h, pt1l);
    gemm_fp16x2<1,1><<<dim3(DFF_/128, Ncur/128), 256, GEMM_SMEM_BYTES>>>(
        pt1h, pt1l, w1.h, w1.l, b1, nullptr, ffh, ffl, Ncur, DFF_, D_MODEL);
    gemm_fp16x2<0,0><<<dim3(D_MODEL/128, Ncur/128), 256, GEMM_SMEM_BYTES>>>(
        ffh, ffl, w2.h, w2.l, b2, t2, nullptr, nullptr, Ncur, D_MODEL, DFF_);
    addln_kernel<<<Ncur, 256>>>(t1, t2, g2, be2, Xout, xouth, xoutl);
}

extern "C" void kernel_launch(void* const* d_in, const int* in_sizes, int n_in,
                              void* d_out, int out_size) {
    (void)in_sizes; (void)n_in; (void)out_size;
    const float* x    = (const float*)d_in[0];
    const float* Wqkv = (const float*)d_in[1];
    const float* bqkv = (const float*)d_in[2];
    const float* Wo   = (const float*)d_in[3];
    const float* bo   = (const float*)d_in[4];
    const float* W1   = (const float*)d_in[5];
    const float* b1   = (const float*)d_in[6];
    const float* W2   = (const float*)d_in[7];
    const float* b2   = (const float*)d_in[8];
    const float* g1   = (const float*)d_in[9];
    const float* be1  = (const float*)d_in[10];
    const float* g2   = (const float*)d_in[11];
    const float* be2  = (const float*)d_in[12];
    const float* rw   = (const float*)d_in[13];

    float *gx, *gxsel, *gt1, *gt2, *gxo, *grs, *gw; int* gsel;
    cudaGetSymbolAddress((void**)&gx,    g_x);
    cudaGetSymbolAddress((void**)&gxsel, g_xsel);
    cudaGetSymbolAddress((void**)&gt1,   g_t1);
    cudaGetSymbolAddress((void**)&gt2,   g_t2);
    cudaGetSymbolAddress((void**)&gxo,   g_xo);
    cudaGetSymbolAddress((void**)&grs,   g_rs);
    cudaGetSymbolAddress((void**)&gsel,  g_sel);
    cudaGetSymbolAddress((void**)&gw,    g_w);

    __half *wqkv2, *wo2, *w12, *w22, *ffp, *qkv2, *vt2, *px, *pa, *pt1, *pxs;
    cudaGetSymbolAddress((void**)&wqkv2, g_wqkv2);
    cudaGetSymbolAddress((void**)&wo2,   g_wo2);
    cudaGetSymbolAddress((void**)&w12,   g_w12);
    cudaGetSymbolAddress((void**)&w22,   g_w22);
    cudaGetSymbolAddress((void**)&ffp,   g_ffp);
    cudaGetSymbolAddress((void**)&qkv2,  g_qkv2);
    cudaGetSymbolAddress((void**)&vt2,   g_vt2);
    cudaGetSymbolAddress((void**)&px,    g_px);
    cudaGetSymbolAddress((void**)&pa,    g_pa);
    cudaGetSymbolAddress((void**)&pt1,   g_pt1);
    cudaGetSymbolAddress((void**)&pxs,   g_pxs);

    cudaFuncSetAttribute(attn_mma, cudaFuncAttributeMaxDynamicSharedMemorySize, ATTN_SMEM4);
    cudaFuncSetAttribute(gemm_fp16x2<0,0>, cudaFuncAttributeMaxDynamicSharedMemorySize, GEMM_SMEM_BYTES);
    cudaFuncSetAttribute(gemm_fp16x2<0,1>, cudaFuncAttributeMaxDynamicSharedMemorySize, GEMM_SMEM_BYTES);
    cudaFuncSetAttribute(gemm_fp16x2<1,1>, cudaFuncAttributeMaxDynamicSharedMemorySize, GEMM_SMEM_BYTES);

    split2(Wqkv, wqkv2, wqkv2 + WQKV_SZ, WQKV_SZ);
    split2(Wo,   wo2,   wo2   + WO_SZ,   WO_SZ);
    split2(W1,   w12,   w12   + W1_SZ,   W1_SZ);
    split2(W2,   w22,   w22   + W2_SZ,   W2_SZ);

    __half* qkvh = qkv2;
    __half* qkvl = qkv2 + (size_t)QKV_SZ;
    __half* vth = vt2;
    __half* vtl = vt2 + (size_t)VT_SZ;
    __half* pxh = px;
    __half* pxl = px + (size_t)XP_SZ;
    __half* pah = pa;
    __half* pal = pa + (size_t)XP_SZ;
    __half* pt1h = pt1;
    __half* pt1l = pt1 + (size_t)XP_SZ;
    __half* ffh = ffp;
    __half* ffl = ffp + (size_t)ACT_SZ;
    __half* pxsh = pxs;
    __half* pxsl = pxs + (size_t)(NSEL*D_MODEL);

    const int n4 = NTOK*D_MODEL/4;
    copy_f4<<<(n4 + 255)/256, 256>>>((const float4*)x, (float4*)gx, n4);
    split2(gx, pxh, pxl, (size_t)NTOK * D_MODEL);

    for (int L = 0; L < NLAYER; L++) {
        WP2 wq_l = { wqkv2 + (size_t)L*3*D_MODEL*D_MODEL,
                     wqkv2 + WQKV_SZ + (size_t)L*3*D_MODEL*D_MODEL };
        WP2 wo_l = { wo2 + (size_t)L*D_MODEL*D_MODEL,
                     wo2 + WO_SZ + (size_t)L*D_MODEL*D_MODEL };
        WP2 w1_l = { w12 + (size_t)L*DFF_*D_MODEL,
                     w12 + W1_SZ + (size_t)L*DFF_*D_MODEL };
        WP2 w2_l = { w22 + (size_t)L*D_MODEL*DFF_,
                     w22 + W2_SZ + (size_t)L*D_MODEL*DFF_ };
        const float* bq_l  = bqkv + (size_t)L*3*D_MODEL;
        const float* bo_l  = bo   + (size_t)L*D_MODEL;
        const float* b1_l  = b1   + (size_t)L*DFF_;
        const float* b2_l  = b2   + (size_t)L*D_MODEL;
        const float* g1_l  = g1   + (size_t)L*D_MODEL;
        const float* be1_l = be1  + (size_t)L*D_MODEL;
        const float* g2_l  = g2   + (size_t)L*D_MODEL;
        const float* be2_l = be2  + (size_t)L*D_MODEL;

        if (L & 1) {
            router_kernel<<<NTOK, 256>>>(gx, rw + (size_t)L*D_MODEL, grs);
            topk_kernel<<<BATCH, 1024>>>(grs, gsel, gw);
            gather_kernel<<<NSEL, 256>>>(gx, pxh, pxl, gsel, gxsel, pxsh, pxsl);
            run_encoder(gxsel, pxsh, pxsl, gxo, pt1h, pt1l,
                        NSEL, KSEL, BATCH,
                        wq_l, bq_l, wo_l, bo_l, w1_l, b1_l, w2_l, b2_l,
                        g1_l, be1_l, g2_l, be2_l,
                        gt1, gt2, qkvh, qkvl, vth, vtl,
                        pah, pal, pt1h, pt1l, ffh, ffl);
            scatter_kernel<<<NSEL, 256>>>(gx, gsel, gw, gxsel, gxo);
            if (L + 1 < NLAYER)
                split2(gx, pxh, pxl, (size_t)NTOK * D_MODEL);
        } else {
            run_encoder(gx, pxh, pxl, gx, pxh, pxl, NTOK, SEQ, BATCH,
                        wq_l, bq_l, wo_l, bo_l, w1_l, b1_l, w2_l, b2_l,
                        g1_l, be1_l, g2_l, be2_l,
                        gt1, gt2, qkvh, qkvl, vth, vtl,
                        pah, pal, pt1h, pt1l, ffh, ffl);
        }
    }

    copy_f4<<<(n4 + 255)/256, 256>>>((const float4*)gx, (float4*)d_out, n4);
}

// round 17
// speedup vs baseline: 2.5999x; 1.0234x over previous
#include <cuda_runtime.h>
#include <cuda_fp16.h>
#include <math.h>
#include <stdint.h>

#define D_MODEL 1024
#define NHEAD   16
#define HDIM    64
#define DFF_    4096
#define NLAYER  6
#define BATCH   4
#define SEQ     2048
#define NTOK    (BATCH*SEQ)      /* 8192 */
#define KSEL    1024
#define NSEL    (BATCH*KSEL)     /* 4096 */

#define WQKV_SZ (NLAYER*3*D_MODEL*D_MODEL)
#define WO_SZ   (NLAYER*D_MODEL*D_MODEL)
#define W1_SZ   (NLAYER*DFF_*D_MODEL)
#define W2_SZ   (NLAYER*D_MODEL*DFF_)
#define ACT_SZ  (NTOK*DFF_)
#define QKV_SZ  (NTOK*3*D_MODEL)
#define VT_SZ   (NTOK*D_MODEL)
#define XP_SZ   (NTOK*D_MODEL)

#define LOW_SCALE   2048.0f
#define LOW_UNSCALE (1.0f/2048.0f)

// ---------------- scratch (device globals; no allocations allowed) ----------
__device__ __align__(256) float g_x   [NTOK*D_MODEL];
__device__ __align__(256) float g_xsel[NSEL*D_MODEL];
__device__ __align__(256) float g_t1  [NTOK*D_MODEL];
__device__ __align__(256) float g_t2  [NTOK*D_MODEL];
__device__ __align__(256) float g_xo  [NTOK*D_MODEL];
__device__ __align__(256) float g_rs  [BATCH*SEQ];
__device__ __align__(256) int   g_sel [BATCH*KSEL];
__device__ __align__(256) float g_w   [BATCH*KSEL];

// fp16 split-plane buffers (h, l*2048)
__device__ __align__(256) __half g_wqkv2[2][WQKV_SZ];
__device__ __align__(256) __half g_wo2  [2][WO_SZ];
__device__ __align__(256) __half g_w12  [2][W1_SZ];
__device__ __align__(256) __half g_w22  [2][W2_SZ];
__device__ __align__(256) __half g_ffp  [2][ACT_SZ];
__device__ __align__(256) __half g_qkv2 [2][QKV_SZ];
__device__ __align__(256) __half g_vt2  [2][VT_SZ];
__device__ __align__(256) __half g_px   [2][XP_SZ];
__device__ __align__(256) __half g_pa   [2][XP_SZ];
__device__ __align__(256) __half g_pt1  [2][XP_SZ];
__device__ __align__(256) __half g_pxs  [2][NSEL*D_MODEL];

// ---------------- simple float4 copy ---------------------------------------
__global__ void copy_f4(const float4* __restrict__ src, float4* __restrict__ dst, int n4) {
    int i = blockIdx.x * blockDim.x + threadIdx.x;
    if (i < n4) dst[i] = src[i];
}

// ---------------- 2-way fp16 split (low plane scaled by 2048) ----------------
__device__ __forceinline__ void split1(float v, __half& h, __half& l) {
    h = __float2half_rn(v);
    l = __float2half_rn((v - __half2float(h)) * LOW_SCALE);
}

__global__ __launch_bounds__(256)
void split2_kernel(const float* __restrict__ in,
                   __half* __restrict__ ph, __half* __restrict__ pl, int n8) {
    int i = blockIdx.x * blockDim.x + threadIdx.x;
    if (i >= n8) return;
    const float4* p = (const float4*)in + (size_t)i * 2;
    float4 x0 = p[0], x1 = p[1];
    float v[8] = {x0.x, x0.y, x0.z, x0.w, x1.x, x1.y, x1.z, x1.w};
    __align__(16) __half hh[8], ll[8];
    #pragma unroll
    for (int k = 0; k < 8; k++) split1(v[k], hh[k], ll[k]);
    *(uint4*)(ph + (size_t)i * 8) = *(uint4*)hh;
    *(uint4*)(pl + (size_t)i * 8) = *(uint4*)ll;
}

static inline void split2(const float* in, __half* h, __half* l, size_t n) {
    int n8 = (int)(n / 8);
    split2_kernel<<<(n8 + 255) / 256, 256>>>(in, h, l, n8);
}

// ---------------- V transpose: qkv fp16 planes -> VT [b*h][d][T] -------------
__global__ __launch_bounds__(256)
void vtrans_kernel(const __half* __restrict__ qh, const __half* __restrict__ ql,
                   __half* __restrict__ vth, __half* __restrict__ vtl, int T) {
    __shared__ __half sh[64][72], sl[64][72];
    const int t0 = blockIdx.x * 64, h = blockIdx.y, b = blockIdx.z;
    const int tid = threadIdx.x;
    const int row = tid >> 2;
    const int dg  = (tid & 3) * 16;

    const size_t src_off = (size_t)(b*T + t0 + row) * 3*D_MODEL + 2*D_MODEL + h*HDIM + dg;
    uint4 h0 = *(const uint4*)(qh + src_off);
    uint4 h1 = *(const uint4*)(qh + src_off + 8);
    uint4 l0 = *(const uint4*)(ql + src_off);
    uint4 l1 = *(const uint4*)(ql + src_off + 8);
    __align__(16) __half hb[16], lb[16];
    *(uint4*)&hb[0] = h0; *(uint4*)&hb[8] = h1;
    *(uint4*)&lb[0] = l0; *(uint4*)&lb[8] = l1;
    #pragma unroll
    for (int e = 0; e < 16; e++) {
        sh[dg + e][row] = hb[e];
        sl[dg + e][row] = lb[e];
    }
    __syncthreads();
    const size_t dst_off = ((size_t)((b*NHEAD + h)*HDIM + row)) * T + t0 + dg;
    *(uint4*)(vth + dst_off)     = *(uint4*)&sh[row][dg];
    *(uint4*)(vth + dst_off + 8) = *(uint4*)&sh[row][dg + 8];
    *(uint4*)(vtl + dst_off)     = *(uint4*)&sl[row][dg];
    *(uint4*)(vtl + dst_off + 8) = *(uint4*)&sl[row][dg + 8];
}

#define MMA_F16(d, a, b) \
    asm volatile("mma.sync.aligned.m16n8k16.row.col.f32.f16.f16.f32 " \
        "{%0,%1,%2,%3}, {%4,%5,%6,%7}, {%8,%9}, {%0,%1,%2,%3};" \
        : "+f"((d)[0]), "+f"((d)[1]), "+f"((d)[2]), "+f"((d)[3]) \
        : "r"((a)[0]), "r"((a)[1]), "r"((a)[2]), "r"((a)[3]), "r"((b)[0]), "r"((b)[1]))

#define LDSM4(r, addr) \
    asm volatile("ldmatrix.sync.aligned.m8n8.x4.shared.b16 {%0,%1,%2,%3}, [%4];" \
        : "=r"((r)[0]), "=r"((r)[1]), "=r"((r)[2]), "=r"((r)[3]) : "r"(addr))

__device__ __forceinline__ void cp_async16(uint32_t smem_addr, const void* gptr) {
    asm volatile("cp.async.ca.shared.global [%0], [%1], 16;" :: "r"(smem_addr), "l"(gptr));
}
#define CP_COMMIT() asm volatile("cp.async.commit_group;" ::: "memory")
#define CP_WAIT_1() asm volatile("cp.async.wait_group 1;" ::: "memory")
#define CP_WAIT_0() asm volatile("cp.async.wait_group 0;" ::: "memory")

// ---------------- fast exp on FMA pipe (no MUFU), rel err ~1.5e-6 ------------
__device__ __forceinline__ float fexp(float x) {
    x = fmaxf(x, -80.0f);
    float t  = x * 1.4426950408889634f;
    float fl = floorf(t);
    float f  = t - fl;
    float p  = 1.5252734e-5f;
    p = fmaf(p, f, 1.5403530e-4f);
    p = fmaf(p, f, 1.3333558e-3f);
    p = fmaf(p, f, 9.6181291e-3f);
    p = fmaf(p, f, 5.5504109e-2f);
    p = fmaf(p, f, 2.4022651e-1f);
    p = fmaf(p, f, 6.9314718e-1f);
    p = fmaf(p, f, 1.0f);
    int i = (int)fl;
    float sc = __int_as_float((i + 127) << 23);
    return p * sc;
}

// ---------------- fp16 2-plane split GEMM, 3-stage cp.async + ldmatrix -------
#define BK2 32
#define SROW2 40
#define PLANE_HALVES (128*SROW2)
#define GEMM_SMEM_BYTES (3*2*2*PLANE_HALVES*2)

template<int RELU, int EMIT>
__global__ __launch_bounds__(256)
void gemm_fp16x2(const __half* __restrict__ Ah, const __half* __restrict__ Al,
                 const __half* __restrict__ Wh, const __half* __restrict__ Wl,
                 const float* __restrict__ bias, float* __restrict__ C,
                 __half* __restrict__ Ch, __half* __restrict__ Cl,
                 int N, int M, int K) {
    extern __shared__ __half smh[];
    const int t    = threadIdx.x;
    const int lane = t & 31;
    const int warp = t >> 5;
    const int wm   = warp >> 2;
    const int wn   = warp & 3;
    const int rn   = blockIdx.y * 128;
    const int cm   = blockIdx.x * 128;
    const int g    = lane >> 2;
    const int tg   = lane & 3;

    const int la_row = (lane & 7) + ((lane >> 3) & 1) * 8;
    const int la_k   = (lane >> 4) * 8;
    const int lb_row = (lane & 7);
    const int lb_jn  = (lane >> 4);
    const int lb_k   = ((lane >> 3) & 1) * 8;

    const __half* Ap[2] = { Ah, Al };
    const __half* Wp[2] = { Wh, Wl };

    const uint32_t smem_u32 = (uint32_t)__cvta_generic_to_shared(smh);
    const int c0r = t >> 2,        c0k = (t & 3) * 8;
    const int c1r = (t + 256) >> 2, c1k = ((t + 256) & 3) * 8;

    float acc1[4][4][4], acc2[4][4][4];
    #pragma unroll
    for (int i = 0; i < 4; i++)
        #pragma unroll
        for (int j = 0; j < 4; j++)
            #pragma unroll
            for (int r = 0; r < 4; r++) { acc1[i][j][r] = 0.f; acc2[i][j][r] = 0.f; }

    const int KT = K / BK2;

    auto issue_stage = [&](int buf, int k0) {
        #pragma unroll
        for (int p = 0; p < 2; p++) {
            uint32_t baseA = smem_u32 + (uint32_t)(((buf*2 + 0)*2 + p) * PLANE_HALVES) * 2;
            uint32_t baseW = smem_u32 + (uint32_t)(((buf*2 + 1)*2 + p) * PLANE_HALVES) * 2;
            cp_async16(baseA + (uint32_t)(c0r*SROW2 + c0k)*2, Ap[p] + (size_t)(rn + c0r)*K + k0 + c0k);
            cp_async16(baseA + (uint32_t)(c1r*SROW2 + c1k)*2, Ap[p] + (size_t)(rn + c1r)*K + k0 + c1k);
            cp_async16(baseW + (uint32_t)(c0r*SROW2 + c0k)*2, Wp[p] + (size_t)(cm + c0r)*K + k0 + c0k);
            cp_async16(baseW + (uint32_t)(c1r*SROW2 + c1k)*2, Wp[p] + (size_t)(cm + c1r)*K + k0 + c1k);
        }
        CP_COMMIT();
    };

    issue_stage(0, 0);
    issue_stage(1, BK2);

    int cur = 0;
    for (int kt = 0; kt < KT; kt++) {
        if (kt + 1 < KT) CP_WAIT_1(); else CP_WAIT_0();
        __syncthreads();
        if (kt + 2 < KT) issue_stage((cur + 2 >= 3) ? cur - 1 : cur + 2, (kt + 2) * BK2);

        const uint32_t uA0 = smem_u32 + (uint32_t)(((cur*2 + 0)*2 + 0) * PLANE_HALVES) * 2;
        const uint32_t uA1 = smem_u32 + (uint32_t)(((cur*2 + 0)*2 + 1) * PLANE_HALVES) * 2;
        const uint32_t uW0 = smem_u32 + (uint32_t)(((cur*2 + 1)*2 + 0) * PLANE_HALVES) * 2;
        const uint32_t uW1 = smem_u32 + (uint32_t)(((cur*2 + 1)*2 + 1) * PLANE_HALVES) * 2;

        #pragma unroll
        for (int ks0 = 0; ks0 < BK2; ks0 += 16) {
            uint32_t fbv[2][8];
            #pragma unroll
            for (int jp = 0; jp < 2; jp++) {
                uint32_t boff = (uint32_t)((wn*32 + jp*16 + lb_jn*8 + lb_row)*SROW2 + ks0 + lb_k) * 2;
                LDSM4(&fbv[0][jp*4], uW0 + boff);
                LDSM4(&fbv[1][jp*4], uW1 + boff);
            }
            #pragma unroll
            for (int im = 0; im < 4; im++) {
                const int r0 = wm * 64 + im * 16;
                uint32_t aoff = (uint32_t)((r0 + la_row)*SROW2 + ks0 + la_k) * 2;
                uint32_t fa[2][4];
                LDSM4(fa[0], uA0 + aoff);
                LDSM4(fa[1], uA1 + aoff);
                #pragma unroll
                for (int jn = 0; jn < 4; jn++) {
                    MMA_F16(acc1[im][jn], fa[0], &fbv[0][jn*2]);
                    MMA_F16(acc2[im][jn], fa[0], &fbv[1][jn*2]);
                    MMA_F16(acc2[im][jn], fa[1], &fbv[0][jn*2]);
                }
            }
        }
        cur = (cur + 1 == 3) ? 0 : cur + 1;
    }
    __syncthreads();

    #pragma unroll
    for (int im = 0; im < 4; im++) {
        #pragma unroll
        for (int jn = 0; jn < 4; jn++) {
            const int row = rn + wm * 64 + im * 16 + g;
            const int col = cm + wn * 32 + jn * 8 + tg * 2;
            float b0 = bias[col], b1 = bias[col + 1];
            float v0 = acc1[im][jn][0] + acc2[im][jn][0] * LOW_UNSCALE + b0;
            float v1 = acc1[im][jn][1] + acc2[im][jn][1] * LOW_UNSCALE + b1;
            float v2 = acc1[im][jn][2] + acc2[im][jn][2] * LOW_UNSCALE + b0;
            float v3 = acc1[im][jn][3] + acc2[im][jn][3] * LOW_UNSCALE + b1;
            if (RELU) {
                v0 = fmaxf(v0, 0.f); v1 = fmaxf(v1, 0.f);
                v2 = fmaxf(v2, 0.f); v3 = fmaxf(v3, 0.f);
            }
            if (EMIT == 0) {
                *(float2*)&C[(size_t)row * M + col]       = make_float2(v0, v1);
                *(float2*)&C[(size_t)(row + 8) * M + col] = make_float2(v2, v3);
            } else {
                __half h0, l0, h1, l1, h2, l2, h3, l3;
                split1(v0, h0, l0); split1(v1, h1, l1);
                split1(v2, h2, l2); split1(v3, h3, l3);
                __half2 H01; H01.x = h0; H01.y = h1;
                __half2 L01; L01.x = l0; L01.y = l1;
                __half2 H23; H23.x = h2; H23.y = h3;
                __half2 L23; L23.x = l2; L23.y = l3;
                *(__half2*)&Ch[(size_t)row * M + col]       = H01;
                *(__half2*)&Cl[(size_t)row * M + col]       = L01;
                *(__half2*)&Ch[(size_t)(row + 8) * M + col] = H23;
                *(__half2*)&Cl[(size_t)(row + 8) * M + col] = L23;
            }
        }
    }
}

// ---------------- MMA flash attention: Q-tile 128, register softmax ----------
#define QS 72
#define QPL (128*QS)
#define KPL (64*QS)
#define OFF_K  (2*QPL)
#define OFF_V  (2*QPL + 4*KPL)
#define OFF_P  (2*QPL + 8*KPL)
#define OFF_F  (4*QPL + 8*KPL)
// floats after OFF_F: wmax[128*2] | wsum[128*2] | mrow[128] | lrow[128]
#define ATTN_SMEM4 (OFF_F*2 + (128*2 + 128*2 + 128 + 128)*4)

__global__ __launch_bounds__(256)
void attn_mma(const __half* __restrict__ qkvh, const __half* __restrict__ qkvl,
              const __half* __restrict__ vth,  const __half* __restrict__ vtl,
              __half* __restrict__ outh, __half* __restrict__ outl, int T) {
    extern __shared__ char sm_raw[];
    __half* smh = (__half*)sm_raw;
    __half* Ph = smh + OFF_P;
    __half* Pl = smh + OFF_P + QPL;
    float*  wmax = (float*)(smh + OFF_F);
    float*  wsum = wmax + 128*2;
    float*  mrow = wsum + 128*2;
    float*  lrow = mrow + 128;

    const int t    = threadIdx.x;
    const int lane = t & 31;
    const int warp = t >> 5;
    const int wm   = warp >> 1;
    const int wn   = warp & 1;
    const int g    = lane >> 2;
    const int tg   = lane & 3;
    const int qt = blockIdx.x, h = blockIdx.y, b = blockIdx.z;
    const int stride3 = 3 * D_MODEL;

    const int la_row = (lane & 7) + ((lane >> 3) & 1) * 8;
    const int la_k   = (lane >> 4) * 8;
    const int lb_row = (lane & 7);
    const int lb_jn  = (lane >> 4);
    const int lb_k   = ((lane >> 3) & 1) * 8;

    const uint32_t uS = (uint32_t)__cvta_generic_to_shared(smh);
    const uint32_t uQ = uS;
    const uint32_t uK = uS + OFF_K*2;
    const uint32_t uV = uS + OFF_V*2;
    const uint32_t uP = uS + OFF_P*2;

    const __half* qp[2] = { qkvh, qkvl };
    const __half* vp[2] = { vth,  vtl  };

    {
        #pragma unroll
        for (int i = 0; i < 8; i++) {
            int c = t + 256*i;
            int plane = c >> 10, rem = c & 1023, row = rem >> 3, ch = (rem & 7) * 8;
            const __half* qg = qp[plane] + (size_t)(b*T + qt*128 + row)*stride3 + h*HDIM + ch;
            cp_async16(uQ + (uint32_t)(plane*QPL + row*QS + ch)*2, qg);
        }
    }
    auto issue_kv = [&](int buf, int kt) {
        #pragma unroll
        for (int i = 0; i < 4; i++) {
            int c = t + 256*i;
            int plane = c >> 9, rem = c & 511, row = rem >> 3, ch = (rem & 7) * 8;
            const __half* kg = qp[plane] + (size_t)(b*T + kt*64 + row)*stride3 + D_MODEL + h*HDIM + ch;
            cp_async16(uK + (uint32_t)((buf*2 + plane)*KPL + row*QS + ch)*2, kg);
            const __half* vg = vp[plane] + ((size_t)((b*NHEAD + h)*HDIM + row))*T + kt*64 + ch;
            cp_async16(uV + (uint32_t)((buf*2 + plane)*KPL + row*QS + ch)*2, vg);
        }
        CP_COMMIT();
    };
    issue_kv(0, 0);

    if (t < 128) { mrow[t] = -1e30f; lrow[t] = 0.f; }

    float o1[2][4][4], o2[2][4][4];
    #pragma unroll
    for (int i = 0; i < 2; i++)
        #pragma unroll
        for (int j = 0; j < 4; j++)
            #pragma unroll
            for (int r = 0; r < 4; r++) { o1[i][j][r] = 0.f; o2[i][j][r] = 0.f; }

    const int nkt = T / 64;
    for (int kt2 = 0; kt2 < nkt; kt2++) {
        const int cur = kt2 & 1;
        const bool more = (kt2 + 1) < nkt;
        __syncthreads();
        if (more) issue_kv(cur ^ 1, kt2 + 1);
        if (more) CP_WAIT_1(); else CP_WAIT_0();
        __syncthreads();

        const uint32_t uK0 = uK + (uint32_t)(cur*2 + 0)*KPL*2;
        const uint32_t uK1 = uK + (uint32_t)(cur*2 + 1)*KPL*2;
        const uint32_t uV0 = uV + (uint32_t)(cur*2 + 0)*KPL*2;
        const uint32_t uV1 = uV + (uint32_t)(cur*2 + 1)*KPL*2;

        // ---- S = Q K^T (split, 3 terms), kept in registers ----
        float s1[2][4][4], s2[2][4][4];
        #pragma unroll
        for (int i = 0; i < 2; i++)
            #pragma unroll
            for (int j = 0; j < 4; j++)
                #pragma unroll
                for (int r = 0; r < 4; r++) { s1[i][j][r] = 0.f; s2[i][j][r] = 0.f; }

        #pragma unroll
        for (int ks0 = 0; ks0 < 64; ks0 += 16) {
            uint32_t fbv[2][8];
            #pragma unroll
            for (int jp = 0; jp < 2; jp++) {
                uint32_t boff = (uint32_t)((wn*32 + jp*16 + lb_jn*8 + lb_row)*QS + ks0 + lb_k) * 2;
                LDSM4(&fbv[0][jp*4], uK0 + boff);
                LDSM4(&fbv[1][jp*4], uK1 + boff);
            }
            #pragma unroll
            for (int im = 0; im < 2; im++) {
                const int r0 = wm * 32 + im * 16;
                uint32_t aoff = (uint32_t)((r0 + la_row)*QS + ks0 + la_k) * 2;
                uint32_t fa[2][4];
                LDSM4(fa[0], uQ + aoff);
                LDSM4(fa[1], uQ + (uint32_t)QPL*2 + aoff);
                #pragma unroll
                for (int jn = 0; jn < 4; jn++) {
                    MMA_F16(s1[im][jn], fa[0], &fbv[0][jn*2]);
                    MMA_F16(s2[im][jn], fa[0], &fbv[1][jn*2]);
                    MMA_F16(s2[im][jn], fa[1], &fbv[0][jn*2]);
                }
            }
        }

        // combine planes, scale (registers)
        float sv[2][4][4];
        #pragma unroll
        for (int im = 0; im < 2; im++)
            #pragma unroll
            for (int jn = 0; jn < 4; jn++)
                #pragma unroll
                for (int r = 0; r < 4; r++)
                    sv[im][jn][r] = (s1[im][jn][r] + s2[im][jn][r]*LOW_UNSCALE) * 0.125f;

        // ---- register softmax: per-row max via quad shfl + tiny smem ----
        float mx[2][2];
        #pragma unroll
        for (int im = 0; im < 2; im++) {
            mx[im][0] = -1e30f; mx[im][1] = -1e30f;
            #pragma unroll
            for (int jn = 0; jn < 4; jn++) {
                mx[im][0] = fmaxf(mx[im][0], fmaxf(sv[im][jn][0], sv[im][jn][1]));
                mx[im][1] = fmaxf(mx[im][1], fmaxf(sv[im][jn][2], sv[im][jn][3]));
            }
            #pragma unroll
            for (int hh = 0; hh < 2; hh++) {
                mx[im][hh] = fmaxf(mx[im][hh], __shfl_xor_sync(0xFFFFFFFF, mx[im][hh], 1));
                mx[im][hh] = fmaxf(mx[im][hh], __shfl_xor_sync(0xFFFFFFFF, mx[im][hh], 2));
            }
        }
        if (tg == 0) {
            #pragma unroll
            for (int im = 0; im < 2; im++) {
                wmax[(wm*32 + im*16 + g)*2 + wn]     = mx[im][0];
                wmax[(wm*32 + im*16 + g + 8)*2 + wn] = mx[im][1];
            }
        }
        __syncthreads();

        // per-row new max, alpha (from pre-update mrow), exps + P fragments
        float mnv[2][2], alv[2][2], ps[2][2];
        #pragma unroll
        for (int im = 0; im < 2; im++)
            #pragma unroll
            for (int hh = 0; hh < 2; hh++) {
                const int row = wm*32 + im*16 + g + hh*8;
                float mo = mrow[row];
                float mn = fmaxf(mo, fmaxf(wmax[row*2 + 0], wmax[row*2 + 1]));
                mnv[im][hh] = mn;
                alv[im][hh] = fexp(mo - mn);
                ps[im][hh] = 0.f;
            }
        #pragma unroll
        for (int im = 0; im < 2; im++) {
            const int r = wm*32 + im*16 + g;
            #pragma unroll
            for (int jn = 0; jn < 4; jn++) {
                const int c = wn*32 + jn*8 + tg*2;
                float p0 = fexp(sv[im][jn][0] - mnv[im][0]);
                float p1 = fexp(sv[im][jn][1] - mnv[im][0]);
                float p2 = fexp(sv[im][jn][2] - mnv[im][1]);
                float p3 = fexp(sv[im][jn][3] - mnv[im][1]);
                ps[im][0] += p0 + p1;
                ps[im][1] += p2 + p3;
                __half h0, l0, h1, l1, h2, l2, h3, l3;
                split1(p0, h0, l0); split1(p1, h1, l1);
                split1(p2, h2, l2); split1(p3, h3, l3);
                __half2 H01; H01.x = h0; H01.y = h1;
                __half2 L01; L01.x = l0; L01.y = l1;
                __half2 H23; H23.x = h2; H23.y = h3;
                __half2 L23; L23.x = l2; L23.y = l3;
                *(__half2*)&Ph[r*QS + c]       = H01;
                *(__half2*)&Pl[r*QS + c]       = L01;
                *(__half2*)&Ph[(r + 8)*QS + c] = H23;
                *(__half2*)&Pl[(r + 8)*QS + c] = L23;
            }
        }
        #pragma unroll
        for (int im = 0; im < 2; im++)
            #pragma unroll
            for (int hh = 0; hh < 2; hh++) {
                ps[im][hh] += __shfl_xor_sync(0xFFFFFFFF, ps[im][hh], 1);
                ps[im][hh] += __shfl_xor_sync(0xFFFFFFFF, ps[im][hh], 2);
            }
        if (tg == 0) {
            #pragma unroll
            for (int im = 0; im < 2; im++) {
                wsum[(wm*32 + im*16 + g)*2 + wn]     = ps[im][0];
                wsum[(wm*32 + im*16 + g + 8)*2 + wn] = ps[im][1];
            }
        }
        __syncthreads();

        // single writer updates running stats (read next iter / at end)
        if (wn == 0 && tg == 0) {
            #pragma unroll
            for (int im = 0; im < 2; im++)
                #pragma unroll
                for (int hh = 0; hh < 2; hh++) {
                    const int row = wm*32 + im*16 + g + hh*8;
                    float s = wsum[row*2 + 0] + wsum[row*2 + 1];
                    lrow[row] = lrow[row]*alv[im][hh] + s;
                    mrow[row] = mnv[im][hh];
                }
        }

        // ---- rescale O accumulators (local alpha), then O += P V ----
        #pragma unroll
        for (int im = 0; im < 2; im++) {
            float a0 = alv[im][0], a1 = alv[im][1];
            #pragma unroll
            for (int jn = 0; jn < 4; jn++) {
                o1[im][jn][0] *= a0; o1[im][jn][1] *= a0;
                o1[im][jn][2] *= a1; o1[im][jn][3] *= a1;
                o2[im][jn][0] *= a0; o2[im][jn][1] *= a0;
                o2[im][jn][2] *= a1; o2[im][jn][3] *= a1;
            }
        }
        #pragma unroll
        for (int ks0 = 0; ks0 < 64; ks0 += 16) {
            uint32_t fbv[2][8];
            #pragma unroll
            for (int jp = 0; jp < 2; jp++) {
                uint32_t boff = (uint32_t)((wn*32 + jp*16 + lb_jn*8 + lb_row)*QS + ks0 + lb_k) * 2;
                LDSM4(&fbv[0][jp*4], uV0 + boff);
                LDSM4(&fbv[1][jp*4], uV1 + boff);
            }
            #pragma unroll
            for (int im = 0; im < 2; im++) {
                const int r0 = wm * 32 + im * 16;
                uint32_t aoff = (uint32_t)((r0 + la_row)*QS + ks0 + la_k) * 2;
                uint32_t fa[2][4];
                LDSM4(fa[0], uP + aoff);
                LDSM4(fa[1], uP + (uint32_t)QPL*2 + aoff);
                #pragma unroll
                for (int jn = 0; jn < 4; jn++) {
                    MMA_F16(o1[im][jn], fa[0], &fbv[0][jn*2]);
                    MMA_F16(o2[im][jn], fa[0], &fbv[1][jn*2]);
                    MMA_F16(o2[im][jn], fa[1], &fbv[0][jn*2]);
                }
            }
        }
    }
    __syncthreads();

    const int n0 = b*T + qt*128;
    #pragma unroll
    for (int im = 0; im < 2; im++) {
        #pragma unroll
        for (int jn = 0; jn < 4; jn++) {
            const int r = wm * 32 + im * 16 + g;
            const int c = wn * 32 + jn * 8 + tg * 2;
            float inv0 = 1.f / lrow[r];
            float inv1 = 1.f / lrow[r + 8];
            float v0 = (o1[im][jn][0] + o2[im][jn][0]*LOW_UNSCALE) * inv0;
            float v1 = (o1[im][jn][1] + o2[im][jn][1]*LOW_UNSCALE) * inv0;
            float v2 = (o1[im][jn][2] + o2[im][jn][2]*LOW_UNSCALE) * inv1;
            float v3 = (o1[im][jn][3] + o2[im][jn][3]*LOW_UNSCALE) * inv1;
            __half h0, l0, h1, l1, h2, l2, h3, l3;
            split1(v0, h0, l0); split1(v1, h1, l1);
            split1(v2, h2, l2); split1(v3, h3, l3);
            __half2 H01; H01.x = h0; H01.y = h1;
            __half2 L01; L01.x = l0; L01.y = l1;
            __half2 H23; H23.x = h2; H23.y = h3;
            __half2 L23; L23.x = l2; L23.y = l3;
            *(__half2*)&outh[(size_t)(n0 + r)*D_MODEL + h*HDIM + c]     = H01;
            *(__half2*)&outl[(size_t)(n0 + r)*D_MODEL + h*HDIM + c]     = L01;
            *(__half2*)&outh[(size_t)(n0 + r + 8)*D_MODEL + h*HDIM + c] = H23;
            *(__half2*)&outl[(size_t)(n0 + r + 8)*D_MODEL + h*HDIM + c] = L23;
        }
    }
}

// ---------------- residual add + LayerNorm (emits fp32 + planes) -------------
__global__ __launch_bounds__(256)
void addln_kernel(const float* __restrict__ a, const float* __restrict__ r,
                  const float* __restrict__ g, const float* __restrict__ be,
                  float* __restrict__ out, __half* __restrict__ outh,
                  __half* __restrict__ outl) {
    __shared__ float rsum[256], rsq[256];
    const int n = blockIdx.x, t = threadIdx.x;
    float4 av = *(const float4*)(a + (size_t)n*D_MODEL + t*4);
    float4 rv = *(const float4*)(r + (size_t)n*D_MODEL + t*4);
    float x0 = av.x + rv.x, x1 = av.y + rv.y, x2 = av.z + rv.z, x3 = av.w + rv.w;
    rsum[t] = x0 + x1 + x2 + x3;
    rsq [t] = x0*x0 + x1*x1 + x2*x2 + x3*x3;
    __syncthreads();
    for (int off = 128; off > 0; off >>= 1) {
        if (t < off) { rsum[t] += rsum[t+off]; rsq[t] += rsq[t+off]; }
        __syncthreads();
    }
    float mu  = rsum[0] * (1.f/1024.f);
    float var = rsq[0]  * (1.f/1024.f) - mu*mu;
    float rstd = rsqrtf(var + 1e-5f);
    float4 gv = *(const float4*)(g  + t*4);
    float4 bv = *(const float4*)(be + t*4);
    float4 o;
    o.x = (x0 - mu)*rstd*gv.x + bv.x;
    o.y = (x1 - mu)*rstd*gv.y + bv.y;
    o.z = (x2 - mu)*rstd*gv.z + bv.z;
    o.w = (x3 - mu)*rstd*gv.w + bv.w;
    *(float4*)(out + (size_t)n*D_MODEL + t*4) = o;
    __align__(8) __half hh[4], ll[4];
    split1(o.x, hh[0], ll[0]); split1(o.y, hh[1], ll[1]);
    split1(o.z, hh[2], ll[2]); split1(o.w, hh[3], ll[3]);
    *(uint2*)(outh + (size_t)n*D_MODEL + t*4) = *(uint2*)hh;
    *(uint2*)(outl + (size_t)n*D_MODEL + t*4) = *(uint2*)ll;
}

// ---------------- router score ----------------------------------------------
__global__ __launch_bounds__(256)
void router_kernel(const float* __restrict__ x, const float* __restrict__ rw,
                   float* __restrict__ out) {
    __shared__ float red[256];
    const int n = blockIdx.x, t = threadIdx.x;
    float4 xv = *(const float4*)(x + (size_t)n*D_MODEL + t*4);
    float4 wv = *(const float4*)(rw + t*4);
    red[t] = xv.x*wv.x + xv.y*wv.y + xv.z*wv.z + xv.w*wv.w;
    __syncthreads();
    for (int off = 128; off > 0; off >>= 1) {
        if (t < off) red[t] += red[t+off];
        __syncthreads();
    }
    if (t == 0) out[n] = red[0];
}

// ---------------- top-k via bitonic sort (desc value, asc index) ------------
__global__ __launch_bounds__(1024)
void topk_kernel(const float* __restrict__ scores, int* __restrict__ sel,
                 float* __restrict__ wout) {
    __shared__ float v[2048];
    __shared__ int  id[2048];
    const int b = blockIdx.x, t = threadIdx.x;
    v[t]        = scores[b*SEQ + t];        id[t]        = t;
    v[t + 1024] = scores[b*SEQ + t + 1024]; id[t + 1024] = t + 1024;
    __syncthreads();
    for (int k = 2; k <= 2048; k <<= 1) {
        for (int j = k >> 1; j > 0; j >>= 1) {
            #pragma unroll
            for (int s = 0; s < 2; s++) {
                int i = t + s*1024;
                int ixj = i ^ j;
                if (ixj > i) {
                    float vi = v[i], vj = v[ixj];
                    int   ii = id[i], ij = id[ixj];
                    bool before = (vi > vj) || (vi == vj && ii < ij);
                    bool up = ((i & k) == 0);
                    bool dosw = up ? (!before) : before;
                    if (dosw) { v[i] = vj; v[ixj] = vi; id[i] = ij; id[ixj] = ii; }
                }
            }
            __syncthreads();
        }
    }
    sel [b*KSEL + t] = id[t];
    wout[b*KSEL + t] = 1.f / (1.f + expf(-v[t]));
}

// ---------------- gather (fp32 + planes) / scatter ---------------------------
__global__ __launch_bounds__(256)
void gather_kernel(const float* __restrict__ x,
                   const __half* __restrict__ xh, const __half* __restrict__ xl,
                   const int* __restrict__ sel,
                   float* __restrict__ xs,
                   __half* __restrict__ xsh, __half* __restrict__ xsl) {
    const int row = blockIdx.x;
    const int b = row >> 10;
    const int src = b*SEQ + sel[row];
    const int t = threadIdx.x;
    float4 v = *(const float4*)(x + (size_t)src*D_MODEL + t*4);
    *(float4*)(xs + (size_t)row*D_MODEL + t*4) = v;
    uint2 hv = *(const uint2*)(xh + (size_t)src*D_MODEL + t*4);
    uint2 lv = *(const uint2*)(xl + (size_t)src*D_MODEL + t*4);
    *(uint2*)(xsh + (size_t)row*D_MODEL + t*4) = hv;
    *(uint2*)(xsl + (size_t)row*D_MODEL + t*4) = lv;
}

__global__ __launch_bounds__(256)
void scatter_kernel(float* __restrict__ x, const int* __restrict__ sel,
                    const float* __restrict__ w, const float* __restrict__ xs,
                    const float* __restrict__ proc) {
    const int row = blockIdx.x;
    const int b = row >> 10;
    const int dst = b*SEQ + sel[row];
    const float wv = w[row];
    const int t = threadIdx.x;
    float4 p  = *(const float4*)(proc + (size_t)row*D_MODEL + t*4);
    float4 s  = *(const float4*)(xs   + (size_t)row*D_MODEL + t*4);
    float4 xv = *(float4*)(x + (size_t)dst*D_MODEL + t*4);
    xv.x += (p.x - s.x)*wv;
    xv.y += (p.y - s.y)*wv;
    xv.z += (p.z - s.z)*wv;
    xv.w += (p.w - s.w)*wv;
    *(float4*)(x + (size_t)dst*D_MODEL + t*4) = xv;
}

// ---------------- host-side helpers ------------------------------------------
struct WP2 { __half *h, *l; };

static void run_encoder(const float* Xin, const __half* xinh, const __half* xinl,
                        float* Xout, __half* xouth, __half* xoutl,
                        int Ncur, int Tcur, int Bcur,
                        WP2 wq, const float* bq, WP2 wo, const float* bo,
                        WP2 w1, const float* b1, WP2 w2, const float* b2,
                        const float* g1, const float* be1, const float* g2, const float* be2,
                        float* t1, float* t2,
                        __half* qkvh, __half* qkvl, __half* vth, __half* vtl,
                        __half* pah, __half* pal, __half* pt1h, __half* pt1l,
                        __half* ffh, __half* ffl) {
    gemm_fp16x2<0,1><<<dim3(3*D_MODEL/128, Ncur/128), 256, GEMM_SMEM_BYTES>>>(
        xinh, xinl, wq.h, wq.l, bq, nullptr, qkvh, qkvl, Ncur, 3*D_MODEL, D_MODEL);
    vtrans_kernel<<<dim3(Tcur/64, NHEAD, Bcur), 256>>>(qkvh, qkvl, vth, vtl, Tcur);
    attn_mma<<<dim3(Tcur/128, NHEAD, Bcur), 256, ATTN_SMEM4>>>(qkvh, qkvl, vth, vtl, pah, pal, Tcur);
    gemm_fp16x2<0,0><<<dim3(D_MODEL/128, Ncur/128), 256, GEMM_SMEM_BYTES>>>(
        pah, pal, wo.h, wo.l, bo, t2, nullptr, nullptr, Ncur, D_MODEL, D_MODEL);
    addln_kernel<<<Ncur, 256>>>(Xin, t2, g1, be1, t1, pt1h, pt1l);
    gemm_fp16x2<1,1><<<dim3(DFF_/128, Ncur/128), 256, GEMM_SMEM_BYTES>>>(
        pt1h, pt1l, w1.h, w1.l, b1, nullptr, ffh, ffl, Ncur, DFF_, D_MODEL);
    gemm_fp16x2<0,0><<<dim3(D_MODEL/128, Ncur/128), 256, GEMM_SMEM_BYTES>>>(
        ffh, ffl, w2.h, w2.l, b2, t2, nullptr, nullptr, Ncur, D_MODEL, DFF_);
    addln_kernel<<<Ncur, 256>>>(t1, t2, g2, be2, Xout, xouth, xoutl);
}

extern "C" void kernel_launch(void* const* d_in, const int* in_sizes, int n_in,
                              void* d_out, int out_size) {
    (void)in_sizes; (void)n_in; (void)out_size;
    const float* x    = (const float*)d_in[0];
    const float* Wqkv = (const float*)d_in[1];
    const float* bqkv = (const float*)d_in[2];
    const float* Wo   = (const float*)d_in[3];
    const float* bo   = (const float*)d_in[4];
    const float* W1   = (const float*)d_in[5];
    const float* b1   = (const float*)d_in[6];
    const float* W2   = (const float*)d_in[7];
    const float* b2   = (const float*)d_in[8];
    const float* g1   = (const float*)d_in[9];
    const float* be1  = (const float*)d_in[10];
    const float* g2   = (const float*)d_in[11];
    const float* be2  = (const float*)d_in[12];
    const float* rw   = (const float*)d_in[13];

    float *gx, *gxsel, *gt1, *gt2, *gxo, *grs, *gw; int* gsel;
    cudaGetSymbolAddress((void**)&gx,    g_x);
    cudaGetSymbolAddress((void**)&gxsel, g_xsel);
    cudaGetSymbolAddress((void**)&gt1,   g_t1);
    cudaGetSymbolAddress((void**)&gt2,   g_t2);
    cudaGetSymbolAddress((void**)&gxo,   g_xo);
    cudaGetSymbolAddress((void**)&grs,   g_rs);
    cudaGetSymbolAddress((void**)&gsel,  g_sel);
    cudaGetSymbolAddress((void**)&gw,    g_w);

    __half *wqkv2, *wo2, *w12, *w22, *ffp, *qkv2, *vt2, *px, *pa, *pt1, *pxs;
    cudaGetSymbolAddress((void**)&wqkv2, g_wqkv2);
    cudaGetSymbolAddress((void**)&wo2,   g_wo2);
    cudaGetSymbolAddress((void**)&w12,   g_w12);
    cudaGetSymbolAddress((void**)&w22,   g_w22);
    cudaGetSymbolAddress((void**)&ffp,   g_ffp);
    cudaGetSymbolAddress((void**)&qkv2,  g_qkv2);
    cudaGetSymbolAddress((void**)&vt2,   g_vt2);
    cudaGetSymbolAddress((void**)&px,    g_px);
    cudaGetSymbolAddress((void**)&pa,    g_pa);
    cudaGetSymbolAddress((void**)&pt1,   g_pt1);
    cudaGetSymbolAddress((void**)&pxs,   g_pxs);

    cudaFuncSetAttribute(attn_mma, cudaFuncAttributeMaxDynamicSharedMemorySize, ATTN_SMEM4);
    cudaFuncSetAttribute(gemm_fp16x2<0,0>, cudaFuncAttributeMaxDynamicSharedMemorySize, GEMM_SMEM_BYTES);
    cudaFuncSetAttribute(gemm_fp16x2<0,1>, cudaFuncAttributeMaxDynamicSharedMemorySize, GEMM_SMEM_BYTES);
    cudaFuncSetAttribute(gemm_fp16x2<1,1>, cudaFuncAttributeMaxDynamicSharedMemorySize, GEMM_SMEM_BYTES);

    split2(Wqkv, wqkv2, wqkv2 + WQKV_SZ, WQKV_SZ);
    split2(Wo,   wo2,   wo2   + WO_SZ,   WO_SZ);
    split2(W1,   w12,   w12   + W1_SZ,   W1_SZ);
    split2(W2,   w22,   w22   + W2_SZ,   W2_SZ);

    __half* qkvh = qkv2;
    __half* qkvl = qkv2 + (size_t)QKV_SZ;
    __half* vth = vt2;
    __half* vtl = vt2 + (size_t)VT_SZ;
    __half* pxh = px;
    __half* pxl = px + (size_t)XP_SZ;
    __half* pah = pa;
    __half* pal = pa + (size_t)XP_SZ;
    __half* pt1h = pt1;
    __half* pt1l = pt1 + (size_t)XP_SZ;
    __half* ffh = ffp;
    __half* ffl = ffp + (size_t)ACT_SZ;
    __half* pxsh = pxs;
    __half* pxsl = pxs + (size_t)(NSEL*D_MODEL);

    const int n4 = NTOK*D_MODEL/4;
    copy_f4<<<(n4 + 255)/256, 256>>>((const float4*)x, (float4*)gx, n4);
    split2(gx, pxh, pxl, (size_t)NTOK * D_MODEL);

    for (int L = 0; L < NLAYER; L++) {
        WP2 wq_l = { wqkv2 + (size_t)L*3*D_MODEL*D_MODEL,
                     wqkv2 + WQKV_SZ + (size_t)L*3*D_MODEL*D_MODEL };
        WP2 wo_l = { wo2 + (size_t)L*D_MODEL*D_MODEL,
                     wo2 + WO_SZ + (size_t)L*D_MODEL*D_MODEL };
        WP2 w1_l = { w12 + (size_t)L*DFF_*D_MODEL,
                     w12 + W1_SZ + (size_t)L*DFF_*D_MODEL };
        WP2 w2_l = { w22 + (size_t)L*D_MODEL*DFF_,
                     w22 + W2_SZ + (size_t)L*D_MODEL*DFF_ };
        const float* bq_l  = bqkv + (size_t)L*3*D_MODEL;
        const float* bo_l  = bo   + (size_t)L*D_MODEL;
        const float* b1_l  = b1   + (size_t)L*DFF_;
        const float* b2_l  = b2   + (size_t)L*D_MODEL;
        const float* g1_l  = g1   + (size_t)L*D_MODEL;
        const float* be1_l = be1  + (size_t)L*D_MODEL;
        const float* g2_l  = g2   + (size_t)L*D_MODEL;
        const float* be2_l = be2  + (size_t)L*D_MODEL;

        if (L & 1) {
            router_kernel<<<NTOK, 256>>>(gx, rw + (size_t)L*D_MODEL, grs);
            topk_kernel<<<BATCH, 1024>>>(grs, gsel, gw);
            gather_kernel<<<NSEL, 256>>>(gx, pxh, pxl, gsel, gxsel, pxsh, pxsl);
            run_encoder(gxsel, pxsh, pxsl, gxo, pt1h, pt1l,
                        NSEL, KSEL, BATCH,
                        wq_l, bq_l, wo_l, bo_l, w1_l, b1_l, w2_l, b2_l,
                        g1_l, be1_l, g2_l, be2_l,
                        gt1, gt2, qkvh, qkvl, vth, vtl,
                        pah, pal, pt1h, pt1l, ffh, ffl);
            scatter_kernel<<<NSEL, 256>>>(gx, gsel, gw, gxsel, gxo);
            if (L + 1 < NLAYER)
                split2(gx, pxh, pxl, (size_t)NTOK * D_MODEL);
        } else {
            run_encoder(gx, pxh, pxl, gx, pxh, pxl, NTOK, SEQ, BATCH,
                        wq_l, bq_l, wo_l, bo_l, w1_l, b1_l, w2_l, b2_l,
                        g1_l, be1_l, g2_l, be2_l,
                        gt1, gt2, qkvh, qkvl, vth, vtl,
                        pah, pal, pt1h, pt1l, ffh, ffl);
        }
    }

    copy_f4<<<(n4 + 255)/256, 256>>>((const float4*)gx, (float4*)d_out, n4);
}